// round 5
// baseline (speedup 1.0000x reference)
#include <cuda_runtime.h>
#include <cuda_bf16.h>
#include <math.h>
#include <stdint.h>

// Problem constants
#define BB   2
#define SS   2048
#define HID  2048
#define NH   16
#define NKV  4
#define HD   128
#define MTOK (BB*SS)          // 4096
#define QDIM (NH*HD)          // 2048
#define KVDIM (NKV*HD)        // 512
#define QKVD (QDIM + 2*KVDIM) // 3072

// ---------------------------------------------------------------------------
// Scratch (device globals; no allocation allowed)
// ---------------------------------------------------------------------------
__device__ float g_C[(size_t)MTOK * QKVD];                       // fused QKV fp32
__device__ __nv_bfloat16 g_Hh[(size_t)MTOK * HID],  g_Hl[(size_t)MTOK * HID];
__device__ __nv_bfloat16 g_Wh[(size_t)QKVD * HID],  g_Wl[(size_t)QKVD * HID];
__device__ __nv_bfloat16 g_Woh[(size_t)HID * QDIM], g_Wol[(size_t)HID * QDIM];
__device__ __nv_bfloat16 g_Qh[(size_t)MTOK * QDIM],  g_Ql[(size_t)MTOK * QDIM];
__device__ __nv_bfloat16 g_Kh[(size_t)MTOK * KVDIM], g_Kl[(size_t)MTOK * KVDIM];
__device__ __nv_bfloat16 g_Vh[(size_t)MTOK * KVDIM], g_Vl[(size_t)MTOK * KVDIM];
__device__ __nv_bfloat16 g_Oh[(size_t)MTOK * QDIM],  g_Ol[(size_t)MTOK * QDIM];

// ---------------------------------------------------------------------------
// helpers
// ---------------------------------------------------------------------------
__device__ __forceinline__ uint32_t smem_to_u32(const void* p) {
    uint32_t a;
    asm("{ .reg .u64 t; cvta.to.shared.u64 t, %1; cvt.u32.u64 %0, t; }"
        : "=r"(a) : "l"(p));
    return a;
}
__device__ __forceinline__ uint32_t pack_bf16(__nv_bfloat16 a, __nv_bfloat16 b) {
    return (uint32_t)__bfloat16_as_ushort(a) |
           ((uint32_t)__bfloat16_as_ushort(b) << 16);
}
__device__ __forceinline__ void split2(float a, float b, uint32_t& h, uint32_t& l) {
    __nv_bfloat16 ha = __float2bfloat16_rn(a);
    __nv_bfloat16 hb = __float2bfloat16_rn(b);
    __nv_bfloat16 la = __float2bfloat16_rn(a - __bfloat162float(ha));
    __nv_bfloat16 lb = __float2bfloat16_rn(b - __bfloat162float(hb));
    h = pack_bf16(ha, hb);
    l = pack_bf16(la, lb);
}

#define LDMX4(r, addr) \
    asm volatile("ldmatrix.sync.aligned.m8n8.x4.shared.b16 {%0,%1,%2,%3}, [%4];" \
        : "=r"((r)[0]), "=r"((r)[1]), "=r"((r)[2]), "=r"((r)[3]) : "r"(addr))
#define LDMX4T(r, addr) \
    asm volatile("ldmatrix.sync.aligned.m8n8.x4.trans.shared.b16 {%0,%1,%2,%3}, [%4];" \
        : "=r"((r)[0]), "=r"((r)[1]), "=r"((r)[2]), "=r"((r)[3]) : "r"(addr))
#define MMA_BF16(c, a, b0, b1) \
    asm volatile("mma.sync.aligned.m16n8k16.row.col.f32.bf16.bf16.f32 " \
        "{%0,%1,%2,%3},{%4,%5,%6,%7},{%8,%9},{%0,%1,%2,%3};" \
        : "+f"((c)[0]), "+f"((c)[1]), "+f"((c)[2]), "+f"((c)[3]) \
        : "r"((a)[0]), "r"((a)[1]), "r"((a)[2]), "r"((a)[3]), "r"(b0), "r"(b1))

__device__ __forceinline__ void cp16(uint32_t dst, const void* src) {
    asm volatile("cp.async.cg.shared.global [%0], [%1], 16;" :: "r"(dst), "l"(src));
}
#define CP_COMMIT() asm volatile("cp.async.commit_group;" ::: "memory")
#define CP_WAIT(n)  asm volatile("cp.async.wait_group %0;" :: "n"(n) : "memory")

// ---------------------------------------------------------------------------
// split kernels
// ---------------------------------------------------------------------------
__global__ void split_kernel(const float* __restrict__ src,
                             __nv_bfloat16* __restrict__ h,
                             __nv_bfloat16* __restrict__ l, int n4)
{
    int i = blockIdx.x * blockDim.x + threadIdx.x;
    if (i >= n4) return;
    float4 v = ((const float4*)src)[i];
    uint32_t h0, l0, h1, l1;
    split2(v.x, v.y, h0, l0);
    split2(v.z, v.w, h1, l1);
    ((uint2*)h)[i] = make_uint2(h0, h1);
    ((uint2*)l)[i] = make_uint2(l0, l1);
}

// strided split: src rows have stride 'stride'; ncols contiguous; out contiguous
__global__ void split_strided(const float* __restrict__ src, int stride, int ncols,
                              __nv_bfloat16* __restrict__ h,
                              __nv_bfloat16* __restrict__ l, int nrows)
{
    int i = blockIdx.x * blockDim.x + threadIdx.x;
    int per_row = ncols / 4;
    if (i >= nrows * per_row) return;
    int r = i / per_row, c = (i - r * per_row) * 4;
    float4 v = *(const float4*)(src + (size_t)r * stride + c);
    uint32_t h0, l0, h1, l1;
    split2(v.x, v.y, h0, l0);
    split2(v.z, v.w, h1, l1);
    size_t o = ((size_t)r * ncols + c) >> 1;
    ((uint2*)h)[o >> 1] = make_uint2(h0, h1);
    ((uint2*)l)[o >> 1] = make_uint2(l0, l1);
}

// ---------------------------------------------------------------------------
// RoPE + split, strided source
// ---------------------------------------------------------------------------
__global__ void rope_split_kernel(const float* __restrict__ X, int stride,
                                  const int* __restrict__ pos_ids, int nheads,
                                  __nv_bfloat16* __restrict__ Xh,
                                  __nv_bfloat16* __restrict__ Xl)
{
    int idx = blockIdx.x * blockDim.x + threadIdx.x;
    if (idx >= MTOK * 64) return;
    int i = idx & 63;
    int m = idx >> 6;
    int p = pos_ids[m];

    double inv = exp(-(double)i * 0.14391156831212787);  // ln(10000)/64
    double ang = (double)p * inv;
    double k = rint(ang * 0.15915494309189535);
    float r = (float)(ang - k * 6.283185307179586477);
    float sv, cv;
    sincosf(r, &sv, &cv);

    size_t sbase = (size_t)m * stride + i;
    size_t obase = (size_t)m * (nheads * 128) + i;
#pragma unroll 4
    for (int h = 0; h < nheads; h++) {
        float x1 = X[sbase], x2 = X[sbase + 64];
        float y1 = x1 * cv - x2 * sv;
        float y2 = x2 * cv + x1 * sv;
        __nv_bfloat16 h1 = __float2bfloat16_rn(y1);
        __nv_bfloat16 h2 = __float2bfloat16_rn(y2);
        Xh[obase]      = h1;
        Xh[obase + 64] = h2;
        Xl[obase]      = __float2bfloat16_rn(y1 - __bfloat162float(h1));
        Xl[obase + 64] = __float2bfloat16_rn(y2 - __bfloat162float(h2));
        sbase += 128;
        obase += 128;
    }
}

// ---------------------------------------------------------------------------
// bf16x3 GEMM, pre-split inputs, cp.async 3-stage pipeline.
// C[M,N] = (Ah+Al) @ (Bh+Bl)^T via Ah*Bh + Ah*Bl + Al*Bh, fp32 out.
// CTA 128x128, BK=32, 256 thr, 8 warps (warp 64x32).
// ---------------------------------------------------------------------------
#define SROW   40
#define TPART  (128 * SROW * 2)        // 10240 B
#define TSTAGE (4 * TPART)             // 40960 B
#define GEMM_SMEM (3 * TSTAGE)         // 122880 B

__global__ __launch_bounds__(256) void gemm_bf16x3_pre(
    const __nv_bfloat16* __restrict__ Ah, const __nv_bfloat16* __restrict__ Al,
    const __nv_bfloat16* __restrict__ Bh, const __nv_bfloat16* __restrict__ Bl,
    float* __restrict__ C, int M, int N, int K)
{
    extern __shared__ char smem[];
    const uint32_t sbase = smem_to_u32(smem);

    const int tid  = threadIdx.x;
    const int wid  = tid >> 5;
    const int lane = tid & 31;
    const int wm   = wid >> 2;
    const int wn   = wid & 3;
    const int bm   = blockIdx.y * 128;
    const int bn   = blockIdx.x * 128;
    const int NKT  = K / 32;

    // cp.async mapping: per part 512 chunks (128 rows x 4x16B), 2 per thread
    const int cr0 = tid >> 2, cc0 = (tid & 3) * 16;
    const int cr1 = (tid + 256) >> 2;

    const __nv_bfloat16* parts[4] = {Ah, Al, Bh, Bl};

#define G_ISSUE(kt, buf) do { \
    uint32_t db = sbase + (uint32_t)(buf) * TSTAGE; \
    _Pragma("unroll") \
    for (int p = 0; p < 4; p++) { \
        int rb = (p < 2) ? bm : bn; \
        const __nv_bfloat16* sp = parts[p]; \
        cp16(db + p * TPART + cr0 * 80 + cc0, \
             sp + (size_t)(rb + cr0) * K + (kt) * 32 + (cc0 >> 1)); \
        cp16(db + p * TPART + cr1 * 80 + cc0, \
             sp + (size_t)(rb + cr1) * K + (kt) * 32 + (cc0 >> 1)); \
    } \
} while (0)

    float acc[4][4][4];
#pragma unroll
    for (int mf = 0; mf < 4; mf++)
#pragma unroll
        for (int nf = 0; nf < 4; nf++)
#pragma unroll
            for (int r = 0; r < 4; r++) acc[mf][nf][r] = 0.f;

    G_ISSUE(0, 0); CP_COMMIT();
    G_ISSUE(1, 1); CP_COMMIT();
    G_ISSUE(2, 2); CP_COMMIT();

    const int lr16 = lane & 15;
    const int lh   = lane >> 4;
    const uint32_t a_lane = (uint32_t)((wm * 64 + lr16) * (SROW * 2) + lh * 16);
    const uint32_t b_lane = (uint32_t)((wn * 32 + lr16) * (SROW * 2) + lh * 16);

    for (int kt = 0; kt < NKT; kt++) {
        if (kt + 3 <= NKT)       CP_WAIT(2);
        else if (kt + 2 == NKT)  CP_WAIT(1);
        else                     CP_WAIT(0);
        __syncthreads();

        {
            const uint32_t base = sbase + (uint32_t)(kt % 3) * TSTAGE;
#pragma unroll
            for (int ks = 0; ks < 2; ks++) {
                const uint32_t kb = ks * 32;
                uint32_t ah[4][4], al[4][4], bh[2][4], bl[2][4];
#pragma unroll
                for (int mf = 0; mf < 4; mf++)
                    LDMX4(ah[mf], base + a_lane + mf * 16 * (SROW * 2) + kb);
#pragma unroll
                for (int nf2 = 0; nf2 < 2; nf2++)
                    LDMX4(bh[nf2], base + 2 * TPART + b_lane + nf2 * 16 * (SROW * 2) + kb);
#pragma unroll
                for (int mf = 0; mf < 4; mf++)
#pragma unroll
                    for (int nf = 0; nf < 4; nf++)
                        MMA_BF16(acc[mf][nf], ah[mf],
                                 bh[nf >> 1][nf & 1], bh[nf >> 1][(nf & 1) + 2]);
#pragma unroll
                for (int nf2 = 0; nf2 < 2; nf2++)
                    LDMX4(bl[nf2], base + 3 * TPART + b_lane + nf2 * 16 * (SROW * 2) + kb);
#pragma unroll
                for (int mf = 0; mf < 4; mf++)
#pragma unroll
                    for (int nf = 0; nf < 4; nf++)
                        MMA_BF16(acc[mf][nf], ah[mf],
                                 bl[nf >> 1][nf & 1], bl[nf >> 1][(nf & 1) + 2]);
#pragma unroll
                for (int mf = 0; mf < 4; mf++)
                    LDMX4(al[mf], base + TPART + a_lane + mf * 16 * (SROW * 2) + kb);
#pragma unroll
                for (int mf = 0; mf < 4; mf++)
#pragma unroll
                    for (int nf = 0; nf < 4; nf++)
                        MMA_BF16(acc[mf][nf], al[mf],
                                 bh[nf >> 1][nf & 1], bh[nf >> 1][(nf & 1) + 2]);
            }
        }
        __syncthreads();
        if (kt + 3 < NKT) { G_ISSUE(kt + 3, kt % 3); CP_COMMIT(); }
    }

    const int erow = bm + wm * 64 + (lane >> 2);
    const int ecol = bn + wn * 32 + (lane & 3) * 2;
#pragma unroll
    for (int mf = 0; mf < 4; mf++)
#pragma unroll
        for (int nf = 0; nf < 4; nf++) {
            float* c = acc[mf][nf];
            size_t ro0 = (size_t)(erow + mf * 16) * N + ecol + nf * 8;
            size_t ro1 = ro0 + 8 * (size_t)N;
            *(float2*)(C + ro0) = make_float2(c[0], c[1]);
            *(float2*)(C + ro1) = make_float2(c[2], c[3]);
        }
#undef G_ISSUE
}

// ---------------------------------------------------------------------------
// Tensor-core flash attention, causal, GQA.
// 128 q-rows x 64 kv tiles, 8 warps (16 q-rows each), KV double-buffered cp.async.
// QK: 3-pass bf16 split; PV: 3-pass; split bf16 output.
// smem: Qh,Ql (128x136) + 2 KV stages of (Kh,Kl,Vh,Vl 64x136) = 208896 B
// ---------------------------------------------------------------------------
#define FROWB 272                      // 136 bf16 per row, bytes
#define FQT   (128 * FROWB)            // 34816
#define FKT   (64 * FROWB)             // 17408
#define FKVST (4 * FKT)                // 69632 per stage
#define FLASH_SMEM (2 * FQT + 2 * FKVST)   // 208896
#define SC_LOG2E 0.12751631762078975f  // (1/sqrt(128)) * log2(e)

__global__ __launch_bounds__(256) void flash_tc(
    const __nv_bfloat16* __restrict__ Qh, const __nv_bfloat16* __restrict__ Ql,
    const __nv_bfloat16* __restrict__ Kh, const __nv_bfloat16* __restrict__ Kl,
    const __nv_bfloat16* __restrict__ Vh, const __nv_bfloat16* __restrict__ Vl,
    __nv_bfloat16* __restrict__ Oh, __nv_bfloat16* __restrict__ Ol)
{
    extern __shared__ char sm[];
    const uint32_t sb  = smem_to_u32(sm);
    const uint32_t sQh = sb, sQl = sb + FQT;
    const uint32_t sKV = sb + 2 * FQT;          // stage base

    const int q0  = blockIdx.x * 128;
    const int h   = blockIdx.y;
    const int b   = blockIdx.z;
    const int kvh = h >> 2;
    const int tid  = threadIdx.x;
    const int wid  = tid >> 5;
    const int lane = tid & 31;

    const __nv_bfloat16* kvp[4] = {Kh, Kl, Vh, Vl};

    // KV cp.async issue: per part 1024 chunks (64 rows x 16x16B), 4/thread
#define KV_ISSUE(kt, buf) do { \
    uint32_t db = sKV + (uint32_t)(buf) * FKVST; \
    size_t gb = (size_t)(b * SS + (kt)) * KVDIM + kvh * HD; \
    _Pragma("unroll") \
    for (int p = 0; p < 4; p++) { \
        const __nv_bfloat16* sp = kvp[p]; \
        _Pragma("unroll") \
        for (int j = 0; j < 4; j++) { \
            int i = tid + j * 256; \
            int r = i >> 4, c16 = (i & 15) * 16; \
            cp16(db + p * FKT + r * FROWB + c16, \
                 sp + gb + (size_t)r * KVDIM + (c16 >> 1)); \
        } \
    } \
} while (0)

    // load Q tile (hi & lo)
    for (int i = tid; i < 128 * 16; i += 256) {
        int r = i >> 4, c = i & 15;
        size_t g = (size_t)(b * SS + q0 + r) * QDIM + h * HD + c * 8;
        int off = r * FROWB + c * 16;
        *(uint4*)(sm + off)       = *(const uint4*)(Qh + g);
        *(uint4*)(sm + FQT + off) = *(const uint4*)(Ql + g);
    }

    const int ntiles = q0 / 64 + 2;
    KV_ISSUE(0, 0); CP_COMMIT();
    KV_ISSUE(64, 1); CP_COMMIT();

    const uint32_t a_off  = (uint32_t)((16 * wid + (lane & 7) + 8 * ((lane >> 3) & 1)) * FROWB
                                       + (lane >> 4) * 16);
    const uint32_t vt_off = (uint32_t)(((lane & 7) + 8 * ((lane >> 3) & 1)) * FROWB
                                       + (lane >> 4) * 16);
    const uint32_t b_off  = (uint32_t)(((lane & 7) + 8 * (lane >> 4)) * FROWB
                                       + ((lane >> 3) & 1) * 16);

    float o[16][4];
#pragma unroll
    for (int nf = 0; nf < 16; nf++)
#pragma unroll
        for (int r = 0; r < 4; r++) o[nf][r] = 0.f;
    float mo[2] = {-1e30f, -1e30f};
    float ls[2] = {0.f, 0.f};

    for (int t = 0; t < ntiles; t++) {
        const int kt = t * 64;
        if (t + 1 < ntiles) CP_WAIT(1); else CP_WAIT(0);
        __syncthreads();

        const uint32_t kvb = sKV + (uint32_t)(t & 1) * FKVST;
        const uint32_t cKh = kvb, cKl = kvb + FKT, cVh = kvb + 2 * FKT, cVl = kvb + 3 * FKT;

        // ---- S = Q K^T (3 passes)
        float s[8][4];
#pragma unroll
        for (int f = 0; f < 8; f++)
#pragma unroll
            for (int r = 0; r < 4; r++) s[f][r] = 0.f;

#pragma unroll
        for (int ks = 0; ks < 8; ks++) {
            uint32_t ah[4], al[4];
            LDMX4(ah, sQh + a_off + ks * 32);
            LDMX4(al, sQl + a_off + ks * 32);
#pragma unroll
            for (int nb = 0; nb < 4; nb++) {
                uint32_t kh[4], kl[4];
                LDMX4(kh, cKh + b_off + nb * 16 * FROWB + ks * 32);
                LDMX4(kl, cKl + b_off + nb * 16 * FROWB + ks * 32);
                MMA_BF16(s[2 * nb],     ah, kh[0], kh[1]);
                MMA_BF16(s[2 * nb + 1], ah, kh[2], kh[3]);
                MMA_BF16(s[2 * nb],     al, kh[0], kh[1]);
                MMA_BF16(s[2 * nb + 1], al, kh[2], kh[3]);
                MMA_BF16(s[2 * nb],     ah, kl[0], kl[1]);
                MMA_BF16(s[2 * nb + 1], ah, kl[2], kl[3]);
            }
        }

#pragma unroll
        for (int f = 0; f < 8; f++)
#pragma unroll
            for (int r = 0; r < 4; r++) s[f][r] *= SC_LOG2E;

        if (t >= ntiles - 2) {
            const int row0 = q0 + 16 * wid + (lane >> 2);
            const int colb = kt + 2 * (lane & 3);
#pragma unroll
            for (int f = 0; f < 8; f++)
#pragma unroll
                for (int r = 0; r < 4; r++) {
                    int col = colb + 8 * f + (r & 1);
                    int row = row0 + 8 * (r >> 1);
                    if (col > row) s[f][r] = -1e30f;
                }
        }

        // ---- online softmax
#pragma unroll
        for (int hh = 0; hh < 2; hh++) {
            float mt = -1e30f;
#pragma unroll
            for (int f = 0; f < 8; f++)
                mt = fmaxf(mt, fmaxf(s[f][2 * hh], s[f][2 * hh + 1]));
            mt = fmaxf(mt, __shfl_xor_sync(0xffffffffu, mt, 1));
            mt = fmaxf(mt, __shfl_xor_sync(0xffffffffu, mt, 2));
            float mn = fmaxf(mo[hh], mt);
            float alpha = exp2f(mo[hh] - mn);
            float rs = 0.f;
#pragma unroll
            for (int f = 0; f < 8; f++) {
                float p0 = exp2f(s[f][2 * hh] - mn);
                float p1 = exp2f(s[f][2 * hh + 1] - mn);
                s[f][2 * hh] = p0;
                s[f][2 * hh + 1] = p1;
                rs += p0 + p1;
            }
            rs += __shfl_xor_sync(0xffffffffu, rs, 1);
            rs += __shfl_xor_sync(0xffffffffu, rs, 2);
            ls[hh] = ls[hh] * alpha + rs;
            mo[hh] = mn;
#pragma unroll
            for (int nf = 0; nf < 16; nf++) {
                o[nf][2 * hh]     *= alpha;
                o[nf][2 * hh + 1] *= alpha;
            }
        }

        // ---- O += P V (3 passes)
#pragma unroll
        for (int ks = 0; ks < 4; ks++) {
            uint32_t ph[4], pl[4];
            split2(s[2 * ks][0],     s[2 * ks][1],     ph[0], pl[0]);
            split2(s[2 * ks][2],     s[2 * ks][3],     ph[1], pl[1]);
            split2(s[2 * ks + 1][0], s[2 * ks + 1][1], ph[2], pl[2]);
            split2(s[2 * ks + 1][2], s[2 * ks + 1][3], ph[3], pl[3]);
#pragma unroll
            for (int nb = 0; nb < 8; nb++) {
                uint32_t vh[4], vl[4];
                LDMX4T(vh, cVh + vt_off + ks * 16 * FROWB + nb * 32);
                LDMX4T(vl, cVl + vt_off + ks * 16 * FROWB + nb * 32);
                MMA_BF16(o[2 * nb],     ph, vh[0], vh[1]);
                MMA_BF16(o[2 * nb + 1], ph, vh[2], vh[3]);
                MMA_BF16(o[2 * nb],     pl, vh[0], vh[1]);
                MMA_BF16(o[2 * nb + 1], pl, vh[2], vh[3]);
                MMA_BF16(o[2 * nb],     ph, vl[0], vl[1]);
                MMA_BF16(o[2 * nb + 1], ph, vl[2], vl[3]);
            }
        }

        __syncthreads();
        if (t + 2 < ntiles) { KV_ISSUE(kt + 128, t & 1); CP_COMMIT(); }
    }

    // epilogue
    float inv0 = 1.f / ls[0];
    float inv1 = 1.f / ls[1];
#pragma unroll
    for (int nf = 0; nf < 16; nf++) {
#pragma unroll
        for (int rp = 0; rp < 2; rp++) {
            float invv = rp ? inv1 : inv0;
            float v0 = o[nf][2 * rp] * invv;
            float v1 = o[nf][2 * rp + 1] * invv;
            uint32_t hi, lo;
            split2(v0, v1, hi, lo);
            int row = q0 + 16 * wid + (lane >> 2) + 8 * rp;
            int col = h * HD + 8 * nf + 2 * (lane & 3);
            size_t g = (size_t)(b * SS + row) * QDIM + col;
            *(uint32_t*)(Oh + g) = hi;
            *(uint32_t*)(Ol + g) = lo;
        }
    }
#undef KV_ISSUE
}

// ---------------------------------------------------------------------------
// launcher
// ---------------------------------------------------------------------------
extern "C" void kernel_launch(void* const* d_in, const int* in_sizes, int n_in,
                              void* d_out, int out_size)
{
    const float* hidden = (const float*)d_in[0];
    const float* Wq     = (const float*)d_in[1];
    const float* Wk     = (const float*)d_in[2];
    const float* Wv     = (const float*)d_in[3];
    const float* Wo     = (const float*)d_in[4];
    const int*   pos    = (const int*)d_in[5];
    float* out = (float*)d_out;

    float* Cb;
    cudaGetSymbolAddress((void**)&Cb, g_C);
    __nv_bfloat16 *Hh, *Hl, *Wh, *Wl, *Woh, *Wol;
    __nv_bfloat16 *Qh, *Ql, *Kh, *Kl, *Vh, *Vl, *Ohb, *Olb;
    cudaGetSymbolAddress((void**)&Hh, g_Hh);   cudaGetSymbolAddress((void**)&Hl, g_Hl);
    cudaGetSymbolAddress((void**)&Wh, g_Wh);   cudaGetSymbolAddress((void**)&Wl, g_Wl);
    cudaGetSymbolAddress((void**)&Woh, g_Woh); cudaGetSymbolAddress((void**)&Wol, g_Wol);
    cudaGetSymbolAddress((void**)&Qh, g_Qh);   cudaGetSymbolAddress((void**)&Ql, g_Ql);
    cudaGetSymbolAddress((void**)&Kh, g_Kh);   cudaGetSymbolAddress((void**)&Kl, g_Kl);
    cudaGetSymbolAddress((void**)&Vh, g_Vh);   cudaGetSymbolAddress((void**)&Vl, g_Vl);
    cudaGetSymbolAddress((void**)&Ohb, g_Oh);  cudaGetSymbolAddress((void**)&Olb, g_Ol);

    cudaFuncSetAttribute(gemm_bf16x3_pre,
                         cudaFuncAttributeMaxDynamicSharedMemorySize, GEMM_SMEM);
    cudaFuncSetAttribute(flash_tc,
                         cudaFuncAttributeMaxDynamicSharedMemorySize, FLASH_SMEM);

    // 1. split inputs; pack Wq|Wk|Wv row-wise into one [3072, 2048] buffer
    split_kernel<<<(MTOK * HID / 4 + 255) / 256, 256>>>(hidden, Hh, Hl, MTOK * HID / 4);
    split_kernel<<<(QDIM * HID / 4 + 255) / 256, 256>>>(Wq, Wh, Wl, QDIM * HID / 4);
    split_kernel<<<(KVDIM * HID / 4 + 255) / 256, 256>>>(
        Wk, Wh + (size_t)QDIM * HID, Wl + (size_t)QDIM * HID, KVDIM * HID / 4);
    split_kernel<<<(KVDIM * HID / 4 + 255) / 256, 256>>>(
        Wv, Wh + (size_t)(QDIM + KVDIM) * HID, Wl + (size_t)(QDIM + KVDIM) * HID,
        KVDIM * HID / 4);
    split_kernel<<<(HID * QDIM / 4 + 255) / 256, 256>>>(Wo, Woh, Wol, HID * QDIM / 4);

    // 2. fused QKV projection -> fp32 C [MTOK, 3072]
    gemm_bf16x3_pre<<<dim3(QKVD / 128, MTOK / 128), 256, GEMM_SMEM>>>(
        Hh, Hl, Wh, Wl, Cb, MTOK, QKVD, HID);

    // 3. RoPE + split (strided views into C)
    rope_split_kernel<<<(MTOK * 64) / 256, 256>>>(Cb, QKVD, pos, NH, Qh, Ql);
    rope_split_kernel<<<(MTOK * 64) / 256, 256>>>(Cb + QDIM, QKVD, pos, NKV, Kh, Kl);
    split_strided<<<(MTOK * KVDIM / 4 + 255) / 256, 256>>>(
        Cb + QDIM + KVDIM, QKVD, KVDIM, Vh, Vl, MTOK);

    // 4. flash attention
    flash_tc<<<dim3(SS / 128, NH, BB), 256, FLASH_SMEM>>>(
        Qh, Ql, Kh, Kl, Vh, Vl, Ohb, Olb);

    // 5. output projection
    gemm_bf16x3_pre<<<dim3(HID / 128, MTOK / 128), 256, GEMM_SMEM>>>(
        Ohb, Olb, Woh, Wol, out, MTOK, HID, QDIM);
}

// round 6
// speedup vs baseline: 1.4386x; 1.4386x over previous
#include <cuda_runtime.h>
#include <cuda_fp16.h>
#include <math.h>
#include <stdint.h>

// Problem constants
#define BB   2
#define SS   2048
#define HID  2048
#define NH   16
#define NKV  4
#define HD   128
#define MTOK (BB*SS)          // 4096
#define QDIM (NH*HD)          // 2048
#define KVDIM (NKV*HD)        // 512
#define QKVD (QDIM + 2*KVDIM) // 3072

#define WSCALE    64.0f
#define INV_WSCALE 0.015625f

// ---------------------------------------------------------------------------
// Scratch (device globals; no allocation allowed)
// ---------------------------------------------------------------------------
__device__ float g_C[(size_t)MTOK * QKVD];                 // fused QKV fp32
__device__ __half g_H16[(size_t)MTOK * HID];               // hidden fp16 single
__device__ __half g_Wh[(size_t)QKVD * HID],  g_Wl[(size_t)QKVD * HID];   // x64
__device__ __half g_Woh[(size_t)HID * QDIM], g_Wol[(size_t)HID * QDIM];  // x64
__device__ __half g_Qh[(size_t)MTOK * QDIM],  g_Ql[(size_t)MTOK * QDIM];
__device__ __half g_Kh[(size_t)MTOK * KVDIM], g_Kl[(size_t)MTOK * KVDIM];
__device__ __half g_Vh[(size_t)MTOK * KVDIM], g_Vl[(size_t)MTOK * KVDIM];
__device__ __half g_O16[(size_t)MTOK * QDIM];              // attn out fp16 single

// ---------------------------------------------------------------------------
// helpers
// ---------------------------------------------------------------------------
__device__ __forceinline__ uint32_t smem_to_u32(const void* p) {
    uint32_t a;
    asm("{ .reg .u64 t; cvta.to.shared.u64 t, %1; cvt.u32.u64 %0, t; }"
        : "=r"(a) : "l"(p));
    return a;
}
__device__ __forceinline__ uint32_t pack_h2(__half a, __half b) {
    return (uint32_t)__half_as_ushort(a) | ((uint32_t)__half_as_ushort(b) << 16);
}
// split pair of floats into packed fp16 hi and fp16 lo
__device__ __forceinline__ void split2h(float a, float b, uint32_t& h, uint32_t& l) {
    __half ha = __float2half_rn(a);
    __half hb = __float2half_rn(b);
    __half la = __float2half_rn(a - __half2float(ha));
    __half lb = __float2half_rn(b - __half2float(hb));
    h = pack_h2(ha, hb);
    l = pack_h2(la, lb);
}

#define LDMX4(r, addr) \
    asm volatile("ldmatrix.sync.aligned.m8n8.x4.shared.b16 {%0,%1,%2,%3}, [%4];" \
        : "=r"((r)[0]), "=r"((r)[1]), "=r"((r)[2]), "=r"((r)[3]) : "r"(addr))
#define LDMX4T(r, addr) \
    asm volatile("ldmatrix.sync.aligned.m8n8.x4.trans.shared.b16 {%0,%1,%2,%3}, [%4];" \
        : "=r"((r)[0]), "=r"((r)[1]), "=r"((r)[2]), "=r"((r)[3]) : "r"(addr))
#define MMA_F16(c, a, b0, b1) \
    asm volatile("mma.sync.aligned.m16n8k16.row.col.f32.f16.f16.f32 " \
        "{%0,%1,%2,%3},{%4,%5,%6,%7},{%8,%9},{%0,%1,%2,%3};" \
        : "+f"((c)[0]), "+f"((c)[1]), "+f"((c)[2]), "+f"((c)[3]) \
        : "r"((a)[0]), "r"((a)[1]), "r"((a)[2]), "r"((a)[3]), "r"(b0), "r"(b1))

__device__ __forceinline__ void cp16(uint32_t dst, const void* src) {
    asm volatile("cp.async.cg.shared.global [%0], [%1], 16;" :: "r"(dst), "l"(src));
}
#define CP_COMMIT() asm volatile("cp.async.commit_group;" ::: "memory")
#define CP_WAIT(n)  asm volatile("cp.async.wait_group %0;" :: "n"(n) : "memory")

// ---------------------------------------------------------------------------
// split kernels
// ---------------------------------------------------------------------------
// fp32 -> single fp16
__global__ void split_single(const float* __restrict__ src,
                             __half* __restrict__ o, int n4)
{
    int i = blockIdx.x * blockDim.x + threadIdx.x;
    if (i >= n4) return;
    float4 v = ((const float4*)src)[i];
    ((uint2*)o)[i] = make_uint2(
        pack_h2(__float2half_rn(v.x), __float2half_rn(v.y)),
        pack_h2(__float2half_rn(v.z), __float2half_rn(v.w)));
}

// fp32 weights -> scaled (x64) fp16 hi + lo
__global__ void split_w(const float* __restrict__ src,
                        __half* __restrict__ h, __half* __restrict__ l, int n4)
{
    int i = blockIdx.x * blockDim.x + threadIdx.x;
    if (i >= n4) return;
    float4 v = ((const float4*)src)[i];
    uint32_t h0, l0, h1, l1;
    split2h(v.x * WSCALE, v.y * WSCALE, h0, l0);
    split2h(v.z * WSCALE, v.w * WSCALE, h1, l1);
    ((uint2*)h)[i] = make_uint2(h0, h1);
    ((uint2*)l)[i] = make_uint2(l0, l1);
}

// strided fp32 -> fp16 hi/lo (for V slice of fused C)
__global__ void split_strided(const float* __restrict__ src, int stride, int ncols,
                              __half* __restrict__ h, __half* __restrict__ l,
                              int nrows)
{
    int i = blockIdx.x * blockDim.x + threadIdx.x;
    int per_row = ncols / 4;
    if (i >= nrows * per_row) return;
    int r = i / per_row, c = (i - r * per_row) * 4;
    float4 v = *(const float4*)(src + (size_t)r * stride + c);
    uint32_t h0, l0, h1, l1;
    split2h(v.x, v.y, h0, l0);
    split2h(v.z, v.w, h1, l1);
    size_t o4 = ((size_t)r * ncols + c) >> 2;
    ((uint2*)h)[o4] = make_uint2(h0, h1);
    ((uint2*)l)[o4] = make_uint2(l0, l1);
}

// ---------------------------------------------------------------------------
// RoPE + split to fp16 hi/lo, strided source
// ---------------------------------------------------------------------------
__global__ void rope_split_kernel(const float* __restrict__ X, int stride,
                                  const int* __restrict__ pos_ids, int nheads,
                                  __half* __restrict__ Xh,
                                  __half* __restrict__ Xl)
{
    int idx = blockIdx.x * blockDim.x + threadIdx.x;
    if (idx >= MTOK * 64) return;
    int i = idx & 63;
    int m = idx >> 6;
    int p = pos_ids[m];

    double inv = exp(-(double)i * 0.14391156831212787);  // ln(10000)/64
    double ang = (double)p * inv;
    double k = rint(ang * 0.15915494309189535);
    float r = (float)(ang - k * 6.283185307179586477);
    float sv, cv;
    sincosf(r, &sv, &cv);

    size_t sbase = (size_t)m * stride + i;
    size_t obase = (size_t)m * (nheads * 128) + i;
#pragma unroll 4
    for (int h = 0; h < nheads; h++) {
        float x1 = X[sbase], x2 = X[sbase + 64];
        float y1 = x1 * cv - x2 * sv;
        float y2 = x2 * cv + x1 * sv;
        __half h1 = __float2half_rn(y1);
        __half h2 = __float2half_rn(y2);
        Xh[obase]      = h1;
        Xh[obase + 64] = h2;
        Xl[obase]      = __float2half_rn(y1 - __half2float(h1));
        Xl[obase + 64] = __float2half_rn(y2 - __half2float(h2));
        sbase += 128;
        obase += 128;
    }
}

// ---------------------------------------------------------------------------
// fp16 2-pass GEMM: C[M,N] = outscale * A16[M,K] @ (Bh+Bl)[N,K]^T
// (A single fp16; B pre-split hi/lo). CTA 128x128, BK=32, 256 thr, 8 warps.
// smem parts A|Bh|Bl, rows padded to 40 halves, 3-stage cp.async pipeline.
// ---------------------------------------------------------------------------
#define SROW   40
#define TPART  (128 * SROW * 2)        // 10240 B
#define TSTAGE (3 * TPART)             // 30720 B
#define GEMM_SMEM (3 * TSTAGE)         // 92160 B

__global__ __launch_bounds__(256) void gemm_f16_2p(
    const __half* __restrict__ A,
    const __half* __restrict__ Bh, const __half* __restrict__ Bl,
    float* __restrict__ C, int M, int N, int K, float outscale)
{
    extern __shared__ char smem[];
    const uint32_t sbase = smem_to_u32(smem);

    const int tid  = threadIdx.x;
    const int wid  = tid >> 5;
    const int lane = tid & 31;
    const int wm   = wid >> 2;
    const int wn   = wid & 3;
    const int bm   = blockIdx.y * 128;
    const int bn   = blockIdx.x * 128;
    const int NKT  = K / 32;

    const int cr0 = tid >> 2, cc0 = (tid & 3) * 16;
    const int cr1 = (tid + 256) >> 2;

    const __half* parts[3] = {A, Bh, Bl};

#define G_ISSUE(kt, buf) do { \
    uint32_t db = sbase + (uint32_t)(buf) * TSTAGE; \
    _Pragma("unroll") \
    for (int p = 0; p < 3; p++) { \
        int rb = (p == 0) ? bm : bn; \
        const __half* sp = parts[p]; \
        cp16(db + p * TPART + cr0 * 80 + cc0, \
             sp + (size_t)(rb + cr0) * K + (kt) * 32 + (cc0 >> 1)); \
        cp16(db + p * TPART + cr1 * 80 + cc0, \
             sp + (size_t)(rb + cr1) * K + (kt) * 32 + (cc0 >> 1)); \
    } \
} while (0)

    float acc[4][4][4];
#pragma unroll
    for (int mf = 0; mf < 4; mf++)
#pragma unroll
        for (int nf = 0; nf < 4; nf++)
#pragma unroll
            for (int r = 0; r < 4; r++) acc[mf][nf][r] = 0.f;

    G_ISSUE(0, 0); CP_COMMIT();
    G_ISSUE(1, 1); CP_COMMIT();
    G_ISSUE(2, 2); CP_COMMIT();

    const int lr16 = lane & 15;
    const int lh   = lane >> 4;
    const uint32_t a_lane = (uint32_t)((wm * 64 + lr16) * (SROW * 2) + lh * 16);
    const uint32_t b_lane = (uint32_t)((wn * 32 + lr16) * (SROW * 2) + lh * 16);

    for (int kt = 0; kt < NKT; kt++) {
        if (kt + 3 <= NKT)       CP_WAIT(2);
        else if (kt + 2 == NKT)  CP_WAIT(1);
        else                     CP_WAIT(0);
        __syncthreads();

        {
            const uint32_t base = sbase + (uint32_t)(kt % 3) * TSTAGE;
#pragma unroll
            for (int ks = 0; ks < 2; ks++) {
                const uint32_t kb = ks * 32;
                uint32_t ah[4][4], bh[2][4], bl[2][4];
#pragma unroll
                for (int mf = 0; mf < 4; mf++)
                    LDMX4(ah[mf], base + a_lane + mf * 16 * (SROW * 2) + kb);
#pragma unroll
                for (int nf2 = 0; nf2 < 2; nf2++)
                    LDMX4(bh[nf2], base + TPART + b_lane + nf2 * 16 * (SROW * 2) + kb);
#pragma unroll
                for (int mf = 0; mf < 4; mf++)
#pragma unroll
                    for (int nf = 0; nf < 4; nf++)
                        MMA_F16(acc[mf][nf], ah[mf],
                                bh[nf >> 1][nf & 1], bh[nf >> 1][(nf & 1) + 2]);
#pragma unroll
                for (int nf2 = 0; nf2 < 2; nf2++)
                    LDMX4(bl[nf2], base + 2 * TPART + b_lane + nf2 * 16 * (SROW * 2) + kb);
#pragma unroll
                for (int mf = 0; mf < 4; mf++)
#pragma unroll
                    for (int nf = 0; nf < 4; nf++)
                        MMA_F16(acc[mf][nf], ah[mf],
                                bl[nf >> 1][nf & 1], bl[nf >> 1][(nf & 1) + 2]);
            }
        }
        __syncthreads();
        if (kt + 3 < NKT) { G_ISSUE(kt + 3, kt % 3); CP_COMMIT(); }
    }

    const int erow = bm + wm * 64 + (lane >> 2);
    const int ecol = bn + wn * 32 + (lane & 3) * 2;
#pragma unroll
    for (int mf = 0; mf < 4; mf++)
#pragma unroll
        for (int nf = 0; nf < 4; nf++) {
            float* c = acc[mf][nf];
            size_t ro0 = (size_t)(erow + mf * 16) * N + ecol + nf * 8;
            size_t ro1 = ro0 + 8 * (size_t)N;
            *(float2*)(C + ro0) = make_float2(c[0] * outscale, c[1] * outscale);
            *(float2*)(C + ro1) = make_float2(c[2] * outscale, c[3] * outscale);
        }
#undef G_ISSUE
}

// ---------------------------------------------------------------------------
// Tensor-core flash attention (fp16 3-pass splits), causal, GQA.
// 128 q-rows x 64 kv tiles, 8 warps, KV double-buffered cp.async.
// Output: single fp16 (the rounding IS the Wo-stage A error budget).
// ---------------------------------------------------------------------------
#define FROWB 272
#define FQT   (128 * FROWB)
#define FKT   (64 * FROWB)
#define FKVST (4 * FKT)
#define FLASH_SMEM (2 * FQT + 2 * FKVST)   // 208896
#define SC_LOG2E 0.12751631762078975f      // (1/sqrt(128)) * log2(e)

__global__ __launch_bounds__(256) void flash_tc(
    const __half* __restrict__ Qh, const __half* __restrict__ Ql,
    const __half* __restrict__ Kh, const __half* __restrict__ Kl,
    const __half* __restrict__ Vh, const __half* __restrict__ Vl,
    __half* __restrict__ O)
{
    extern __shared__ char sm[];
    const uint32_t sb  = smem_to_u32(sm);
    const uint32_t sQh = sb, sQl = sb + FQT;
    const uint32_t sKV = sb + 2 * FQT;

    const int q0  = blockIdx.x * 128;
    const int h   = blockIdx.y;
    const int b   = blockIdx.z;
    const int kvh = h >> 2;
    const int tid  = threadIdx.x;
    const int wid  = tid >> 5;
    const int lane = tid & 31;

    const __half* kvp[4] = {Kh, Kl, Vh, Vl};

#define KV_ISSUE(kt, buf) do { \
    uint32_t db = sKV + (uint32_t)(buf) * FKVST; \
    size_t gb = (size_t)(b * SS + (kt)) * KVDIM + kvh * HD; \
    _Pragma("unroll") \
    for (int p = 0; p < 4; p++) { \
        const __half* sp = kvp[p]; \
        _Pragma("unroll") \
        for (int j = 0; j < 4; j++) { \
            int i = tid + j * 256; \
            int r = i >> 4, c16 = (i & 15) * 16; \
            cp16(db + p * FKT + r * FROWB + c16, \
                 sp + gb + (size_t)r * KVDIM + (c16 >> 1)); \
        } \
    } \
} while (0)

    for (int i = tid; i < 128 * 16; i += 256) {
        int r = i >> 4, c = i & 15;
        size_t g = (size_t)(b * SS + q0 + r) * QDIM + h * HD + c * 8;
        int off = r * FROWB + c * 16;
        *(uint4*)(sm + off)       = *(const uint4*)(Qh + g);
        *(uint4*)(sm + FQT + off) = *(const uint4*)(Ql + g);
    }

    const int ntiles = q0 / 64 + 2;
    KV_ISSUE(0, 0); CP_COMMIT();
    KV_ISSUE(64, 1); CP_COMMIT();

    const uint32_t a_off  = (uint32_t)((16 * wid + (lane & 7) + 8 * ((lane >> 3) & 1)) * FROWB
                                       + (lane >> 4) * 16);
    const uint32_t vt_off = (uint32_t)(((lane & 7) + 8 * ((lane >> 3) & 1)) * FROWB
                                       + (lane >> 4) * 16);
    const uint32_t b_off  = (uint32_t)(((lane & 7) + 8 * (lane >> 4)) * FROWB
                                       + ((lane >> 3) & 1) * 16);

    float o[16][4];
#pragma unroll
    for (int nf = 0; nf < 16; nf++)
#pragma unroll
        for (int r = 0; r < 4; r++) o[nf][r] = 0.f;
    float mo[2] = {-1e30f, -1e30f};
    float ls[2] = {0.f, 0.f};

    for (int t = 0; t < ntiles; t++) {
        const int kt = t * 64;
        if (t + 1 < ntiles) CP_WAIT(1); else CP_WAIT(0);
        __syncthreads();

        const uint32_t kvb = sKV + (uint32_t)(t & 1) * FKVST;
        const uint32_t cKh = kvb, cKl = kvb + FKT, cVh = kvb + 2 * FKT, cVl = kvb + 3 * FKT;

        float s[8][4];
#pragma unroll
        for (int f = 0; f < 8; f++)
#pragma unroll
            for (int r = 0; r < 4; r++) s[f][r] = 0.f;

#pragma unroll
        for (int ks = 0; ks < 8; ks++) {
            uint32_t ah[4], al[4];
            LDMX4(ah, sQh + a_off + ks * 32);
            LDMX4(al, sQl + a_off + ks * 32);
#pragma unroll
            for (int nb = 0; nb < 4; nb++) {
                uint32_t kh[4], kl[4];
                LDMX4(kh, cKh + b_off + nb * 16 * FROWB + ks * 32);
                LDMX4(kl, cKl + b_off + nb * 16 * FROWB + ks * 32);
                MMA_F16(s[2 * nb],     ah, kh[0], kh[1]);
                MMA_F16(s[2 * nb + 1], ah, kh[2], kh[3]);
                MMA_F16(s[2 * nb],     al, kh[0], kh[1]);
                MMA_F16(s[2 * nb + 1], al, kh[2], kh[3]);
                MMA_F16(s[2 * nb],     ah, kl[0], kl[1]);
                MMA_F16(s[2 * nb + 1], ah, kl[2], kl[3]);
            }
        }

#pragma unroll
        for (int f = 0; f < 8; f++)
#pragma unroll
            for (int r = 0; r < 4; r++) s[f][r] *= SC_LOG2E;

        if (t >= ntiles - 2) {
            const int row0 = q0 + 16 * wid + (lane >> 2);
            const int colb = kt + 2 * (lane & 3);
#pragma unroll
            for (int f = 0; f < 8; f++)
#pragma unroll
                for (int r = 0; r < 4; r++) {
                    int col = colb + 8 * f + (r & 1);
                    int row = row0 + 8 * (r >> 1);
                    if (col > row) s[f][r] = -1e30f;
                }
        }

#pragma unroll
        for (int hh = 0; hh < 2; hh++) {
            float mt = -1e30f;
#pragma unroll
            for (int f = 0; f < 8; f++)
                mt = fmaxf(mt, fmaxf(s[f][2 * hh], s[f][2 * hh + 1]));
            mt = fmaxf(mt, __shfl_xor_sync(0xffffffffu, mt, 1));
            mt = fmaxf(mt, __shfl_xor_sync(0xffffffffu, mt, 2));
            float mn = fmaxf(mo[hh], mt);
            float alpha = exp2f(mo[hh] - mn);
            float rs = 0.f;
#pragma unroll
            for (int f = 0; f < 8; f++) {
                float p0 = exp2f(s[f][2 * hh] - mn);
                float p1 = exp2f(s[f][2 * hh + 1] - mn);
                s[f][2 * hh] = p0;
                s[f][2 * hh + 1] = p1;
                rs += p0 + p1;
            }
            rs += __shfl_xor_sync(0xffffffffu, rs, 1);
            rs += __shfl_xor_sync(0xffffffffu, rs, 2);
            ls[hh] = ls[hh] * alpha + rs;
            mo[hh] = mn;
#pragma unroll
            for (int nf = 0; nf < 16; nf++) {
                o[nf][2 * hh]     *= alpha;
                o[nf][2 * hh + 1] *= alpha;
            }
        }

#pragma unroll
        for (int ks = 0; ks < 4; ks++) {
            uint32_t ph[4], pl[4];
            split2h(s[2 * ks][0],     s[2 * ks][1],     ph[0], pl[0]);
            split2h(s[2 * ks][2],     s[2 * ks][3],     ph[1], pl[1]);
            split2h(s[2 * ks + 1][0], s[2 * ks + 1][1], ph[2], pl[2]);
            split2h(s[2 * ks + 1][2], s[2 * ks + 1][3], ph[3], pl[3]);
#pragma unroll
            for (int nb = 0; nb < 8; nb++) {
                uint32_t vh[4], vl[4];
                LDMX4T(vh, cVh + vt_off + ks * 16 * FROWB + nb * 32);
                LDMX4T(vl, cVl + vt_off + ks * 16 * FROWB + nb * 32);
                MMA_F16(o[2 * nb],     ph, vh[0], vh[1]);
                MMA_F16(o[2 * nb + 1], ph, vh[2], vh[3]);
                MMA_F16(o[2 * nb],     pl, vh[0], vh[1]);
                MMA_F16(o[2 * nb + 1], pl, vh[2], vh[3]);
                MMA_F16(o[2 * nb],     ph, vl[0], vl[1]);
                MMA_F16(o[2 * nb + 1], ph, vl[2], vl[3]);
            }
        }

        __syncthreads();
        if (t + 2 < ntiles) { KV_ISSUE(kt + 128, t & 1); CP_COMMIT(); }
    }

    // epilogue: normalize, store single fp16
    float inv0 = 1.f / ls[0];
    float inv1 = 1.f / ls[1];
#pragma unroll
    for (int nf = 0; nf < 16; nf++) {
#pragma unroll
        for (int rp = 0; rp < 2; rp++) {
            float invv = rp ? inv1 : inv0;
            float v0 = o[nf][2 * rp] * invv;
            float v1 = o[nf][2 * rp + 1] * invv;
            uint32_t hv = pack_h2(__float2half_rn(v0), __float2half_rn(v1));
            int row = q0 + 16 * wid + (lane >> 2) + 8 * rp;
            int col = h * HD + 8 * nf + 2 * (lane & 3);
            size_t g = (size_t)(b * SS + row) * QDIM + col;
            *(uint32_t*)(O + g) = hv;
        }
    }
#undef KV_ISSUE
}

// ---------------------------------------------------------------------------
// launcher
// ---------------------------------------------------------------------------
extern "C" void kernel_launch(void* const* d_in, const int* in_sizes, int n_in,
                              void* d_out, int out_size)
{
    const float* hidden = (const float*)d_in[0];
    const float* Wq     = (const float*)d_in[1];
    const float* Wk     = (const float*)d_in[2];
    const float* Wv     = (const float*)d_in[3];
    const float* Wo     = (const float*)d_in[4];
    const int*   pos    = (const int*)d_in[5];
    float* out = (float*)d_out;

    float* Cb;
    cudaGetSymbolAddress((void**)&Cb, g_C);
    __half *H16, *Wh, *Wl, *Woh, *Wol;
    __half *Qh, *Ql, *Kh, *Kl, *Vh, *Vl, *O16;
    cudaGetSymbolAddress((void**)&H16, g_H16);
    cudaGetSymbolAddress((void**)&Wh, g_Wh);   cudaGetSymbolAddress((void**)&Wl, g_Wl);
    cudaGetSymbolAddress((void**)&Woh, g_Woh); cudaGetSymbolAddress((void**)&Wol, g_Wol);
    cudaGetSymbolAddress((void**)&Qh, g_Qh);   cudaGetSymbolAddress((void**)&Ql, g_Ql);
    cudaGetSymbolAddress((void**)&Kh, g_Kh);   cudaGetSymbolAddress((void**)&Kl, g_Kl);
    cudaGetSymbolAddress((void**)&Vh, g_Vh);   cudaGetSymbolAddress((void**)&Vl, g_Vl);
    cudaGetSymbolAddress((void**)&O16, g_O16);

    cudaFuncSetAttribute(gemm_f16_2p,
                         cudaFuncAttributeMaxDynamicSharedMemorySize, GEMM_SMEM);
    cudaFuncSetAttribute(flash_tc,
                         cudaFuncAttributeMaxDynamicSharedMemorySize, FLASH_SMEM);

    // 1. convert hidden to fp16 single; weights to scaled fp16 hi/lo (packed QKV)
    split_single<<<(MTOK * HID / 4 + 255) / 256, 256>>>(hidden, H16, MTOK * HID / 4);
    split_w<<<(QDIM * HID / 4 + 255) / 256, 256>>>(Wq, Wh, Wl, QDIM * HID / 4);
    split_w<<<(KVDIM * HID / 4 + 255) / 256, 256>>>(
        Wk, Wh + (size_t)QDIM * HID, Wl + (size_t)QDIM * HID, KVDIM * HID / 4);
    split_w<<<(KVDIM * HID / 4 + 255) / 256, 256>>>(
        Wv, Wh + (size_t)(QDIM + KVDIM) * HID, Wl + (size_t)(QDIM + KVDIM) * HID,
        KVDIM * HID / 4);
    split_w<<<(HID * QDIM / 4 + 255) / 256, 256>>>(Wo, Woh, Wol, HID * QDIM / 4);

    // 2. fused QKV projection -> fp32 C [MTOK, 3072] (unscale by 1/64)
    gemm_f16_2p<<<dim3(QKVD / 128, MTOK / 128), 256, GEMM_SMEM>>>(
        H16, Wh, Wl, Cb, MTOK, QKVD, HID, INV_WSCALE);

    // 3. RoPE + split to fp16 hi/lo (strided views into C)
    rope_split_kernel<<<(MTOK * 64) / 256, 256>>>(Cb, QKVD, pos, NH, Qh, Ql);
    rope_split_kernel<<<(MTOK * 64) / 256, 256>>>(Cb + QDIM, QKVD, pos, NKV, Kh, Kl);
    split_strided<<<(MTOK * KVDIM / 4 + 255) / 256, 256>>>(
        Cb + QDIM + KVDIM, QKVD, KVDIM, Vh, Vl, MTOK);

    // 4. flash attention -> single fp16 O
    flash_tc<<<dim3(SS / 128, NH, BB), 256, FLASH_SMEM>>>(
        Qh, Ql, Kh, Kl, Vh, Vl, O16);

    // 5. output projection (unscale by 1/64)
    gemm_f16_2p<<<dim3(HID / 128, MTOK / 128), 256, GEMM_SMEM>>>(
        O16, Woh, Wol, out, MTOK, HID, QDIM, INV_WSCALE);
}

// round 7
// speedup vs baseline: 1.6742x; 1.1638x over previous
#include <cuda_runtime.h>
#include <cuda_fp16.h>
#include <math.h>
#include <stdint.h>

// Problem constants
#define BB   2
#define SS   2048
#define HID  2048
#define NH   16
#define NKV  4
#define HD   128
#define MTOK (BB*SS)          // 4096
#define QDIM (NH*HD)          // 2048
#define KVDIM (NKV*HD)        // 512
#define QKVD (QDIM + 2*KVDIM) // 3072

#define WSCALE    64.0f
#define INV_WSCALE 0.015625f

// ---------------------------------------------------------------------------
// Scratch (device globals; no allocation allowed)
// ---------------------------------------------------------------------------
__device__ float g_C[(size_t)MTOK * QKVD];                 // fused QKV fp32
__device__ __half g_H16[(size_t)MTOK * HID];               // hidden fp16 single
__device__ __half g_Wh[(size_t)QKVD * HID],  g_Wl[(size_t)QKVD * HID];   // x64
__device__ __half g_Woh[(size_t)HID * QDIM], g_Wol[(size_t)HID * QDIM];  // x64
__device__ __half g_Qh[(size_t)MTOK * QDIM],  g_Ql[(size_t)MTOK * QDIM];
__device__ __half g_K16[(size_t)MTOK * KVDIM];             // K single fp16 (roped)
__device__ __half g_V16[(size_t)MTOK * KVDIM];             // V single fp16
__device__ __half g_O16[(size_t)MTOK * QDIM];              // attn out fp16 single

// ---------------------------------------------------------------------------
// helpers
// ---------------------------------------------------------------------------
__device__ __forceinline__ uint32_t smem_to_u32(const void* p) {
    uint32_t a;
    asm("{ .reg .u64 t; cvta.to.shared.u64 t, %1; cvt.u32.u64 %0, t; }"
        : "=r"(a) : "l"(p));
    return a;
}
__device__ __forceinline__ uint32_t pack_h2(__half a, __half b) {
    return (uint32_t)__half_as_ushort(a) | ((uint32_t)__half_as_ushort(b) << 16);
}
__device__ __forceinline__ void split2h(float a, float b, uint32_t& h, uint32_t& l) {
    __half ha = __float2half_rn(a);
    __half hb = __float2half_rn(b);
    __half la = __float2half_rn(a - __half2float(ha));
    __half lb = __float2half_rn(b - __half2float(hb));
    h = pack_h2(ha, hb);
    l = pack_h2(la, lb);
}

#define LDMX4(r, addr) \
    asm volatile("ldmatrix.sync.aligned.m8n8.x4.shared.b16 {%0,%1,%2,%3}, [%4];" \
        : "=r"((r)[0]), "=r"((r)[1]), "=r"((r)[2]), "=r"((r)[3]) : "r"(addr))
#define LDMX4T(r, addr) \
    asm volatile("ldmatrix.sync.aligned.m8n8.x4.trans.shared.b16 {%0,%1,%2,%3}, [%4];" \
        : "=r"((r)[0]), "=r"((r)[1]), "=r"((r)[2]), "=r"((r)[3]) : "r"(addr))
#define MMA_F16(c, a, b0, b1) \
    asm volatile("mma.sync.aligned.m16n8k16.row.col.f32.f16.f16.f32 " \
        "{%0,%1,%2,%3},{%4,%5,%6,%7},{%8,%9},{%0,%1,%2,%3};" \
        : "+f"((c)[0]), "+f"((c)[1]), "+f"((c)[2]), "+f"((c)[3]) \
        : "r"((a)[0]), "r"((a)[1]), "r"((a)[2]), "r"((a)[3]), "r"(b0), "r"(b1))

__device__ __forceinline__ void cp16(uint32_t dst, const void* src) {
    asm volatile("cp.async.cg.shared.global [%0], [%1], 16;" :: "r"(dst), "l"(src));
}
#define CP_COMMIT() asm volatile("cp.async.commit_group;" ::: "memory")
#define CP_WAIT(n)  asm volatile("cp.async.wait_group %0;" :: "n"(n) : "memory")

// ---------------------------------------------------------------------------
// split kernels
// ---------------------------------------------------------------------------
__global__ void split_single(const float* __restrict__ src,
                             __half* __restrict__ o, int n4)
{
    int i = blockIdx.x * blockDim.x + threadIdx.x;
    if (i >= n4) return;
    float4 v = ((const float4*)src)[i];
    ((uint2*)o)[i] = make_uint2(
        pack_h2(__float2half_rn(v.x), __float2half_rn(v.y)),
        pack_h2(__float2half_rn(v.z), __float2half_rn(v.w)));
}

__global__ void split_w(const float* __restrict__ src,
                        __half* __restrict__ h, __half* __restrict__ l, int n4)
{
    int i = blockIdx.x * blockDim.x + threadIdx.x;
    if (i >= n4) return;
    float4 v = ((const float4*)src)[i];
    uint32_t h0, l0, h1, l1;
    split2h(v.x * WSCALE, v.y * WSCALE, h0, l0);
    split2h(v.z * WSCALE, v.w * WSCALE, h1, l1);
    ((uint2*)h)[i] = make_uint2(h0, h1);
    ((uint2*)l)[i] = make_uint2(l0, l1);
}

// strided fp32 -> single fp16 (for V slice of fused C)
__global__ void single_strided(const float* __restrict__ src, int stride, int ncols,
                               __half* __restrict__ o, int nrows)
{
    int i = blockIdx.x * blockDim.x + threadIdx.x;
    int per_row = ncols / 4;
    if (i >= nrows * per_row) return;
    int r = i / per_row, c = (i - r * per_row) * 4;
    float4 v = *(const float4*)(src + (size_t)r * stride + c);
    size_t o4 = ((size_t)r * ncols + c) >> 2;
    ((uint2*)o)[o4] = make_uint2(
        pack_h2(__float2half_rn(v.x), __float2half_rn(v.y)),
        pack_h2(__float2half_rn(v.z), __float2half_rn(v.w)));
}

// ---------------------------------------------------------------------------
// RoPE kernels (strided source from fused C)
// ---------------------------------------------------------------------------
__global__ void rope_split_kernel(const float* __restrict__ X, int stride,
                                  const int* __restrict__ pos_ids, int nheads,
                                  __half* __restrict__ Xh,
                                  __half* __restrict__ Xl)
{
    int idx = blockIdx.x * blockDim.x + threadIdx.x;
    if (idx >= MTOK * 64) return;
    int i = idx & 63;
    int m = idx >> 6;
    int p = pos_ids[m];

    double inv = exp(-(double)i * 0.14391156831212787);  // ln(10000)/64
    double ang = (double)p * inv;
    double k = rint(ang * 0.15915494309189535);
    float r = (float)(ang - k * 6.283185307179586477);
    float sv, cv;
    sincosf(r, &sv, &cv);

    size_t sbase = (size_t)m * stride + i;
    size_t obase = (size_t)m * (nheads * 128) + i;
#pragma unroll 4
    for (int h = 0; h < nheads; h++) {
        float x1 = X[sbase], x2 = X[sbase + 64];
        float y1 = x1 * cv - x2 * sv;
        float y2 = x2 * cv + x1 * sv;
        __half h1 = __float2half_rn(y1);
        __half h2 = __float2half_rn(y2);
        Xh[obase]      = h1;
        Xh[obase + 64] = h2;
        Xl[obase]      = __float2half_rn(y1 - __half2float(h1));
        Xl[obase + 64] = __float2half_rn(y2 - __half2float(h2));
        sbase += 128;
        obase += 128;
    }
}

__global__ void rope_single_kernel(const float* __restrict__ X, int stride,
                                   const int* __restrict__ pos_ids, int nheads,
                                   __half* __restrict__ Xo)
{
    int idx = blockIdx.x * blockDim.x + threadIdx.x;
    if (idx >= MTOK * 64) return;
    int i = idx & 63;
    int m = idx >> 6;
    int p = pos_ids[m];

    double inv = exp(-(double)i * 0.14391156831212787);
    double ang = (double)p * inv;
    double k = rint(ang * 0.15915494309189535);
    float r = (float)(ang - k * 6.283185307179586477);
    float sv, cv;
    sincosf(r, &sv, &cv);

    size_t sbase = (size_t)m * stride + i;
    size_t obase = (size_t)m * (nheads * 128) + i;
#pragma unroll 4
    for (int h = 0; h < nheads; h++) {
        float x1 = X[sbase], x2 = X[sbase + 64];
        Xo[obase]      = __float2half_rn(x1 * cv - x2 * sv);
        Xo[obase + 64] = __float2half_rn(x2 * cv + x1 * sv);
        sbase += 128;
        obase += 128;
    }
}

// ---------------------------------------------------------------------------
// fp16 2-pass GEMM: C[M,N] = outscale * A16[M,K] @ (Bh+Bl)[N,K]^T
// CTA 128x128, BK=32, 256 thr, 8 warps. 3-stage cp.async pipeline.
// ---------------------------------------------------------------------------
#define SROW   40
#define TPART  (128 * SROW * 2)        // 10240 B
#define TSTAGE (3 * TPART)             // 30720 B
#define GEMM_SMEM (3 * TSTAGE)         // 92160 B

__global__ __launch_bounds__(256) void gemm_f16_2p(
    const __half* __restrict__ A,
    const __half* __restrict__ Bh, const __half* __restrict__ Bl,
    float* __restrict__ C, int M, int N, int K, float outscale)
{
    extern __shared__ char smem[];
    const uint32_t sbase = smem_to_u32(smem);

    const int tid  = threadIdx.x;
    const int wid  = tid >> 5;
    const int lane = tid & 31;
    const int wm   = wid >> 2;
    const int wn   = wid & 3;
    const int bm   = blockIdx.y * 128;
    const int bn   = blockIdx.x * 128;
    const int NKT  = K / 32;

    const int cr0 = tid >> 2, cc0 = (tid & 3) * 16;
    const int cr1 = (tid + 256) >> 2;

    const __half* parts[3] = {A, Bh, Bl};

#define G_ISSUE(kt, buf) do { \
    uint32_t db = sbase + (uint32_t)(buf) * TSTAGE; \
    _Pragma("unroll") \
    for (int p = 0; p < 3; p++) { \
        int rb = (p == 0) ? bm : bn; \
        const __half* sp = parts[p]; \
        cp16(db + p * TPART + cr0 * 80 + cc0, \
             sp + (size_t)(rb + cr0) * K + (kt) * 32 + (cc0 >> 1)); \
        cp16(db + p * TPART + cr1 * 80 + cc0, \
             sp + (size_t)(rb + cr1) * K + (kt) * 32 + (cc0 >> 1)); \
    } \
} while (0)

    float acc[4][4][4];
#pragma unroll
    for (int mf = 0; mf < 4; mf++)
#pragma unroll
        for (int nf = 0; nf < 4; nf++)
#pragma unroll
            for (int r = 0; r < 4; r++) acc[mf][nf][r] = 0.f;

    G_ISSUE(0, 0); CP_COMMIT();
    G_ISSUE(1, 1); CP_COMMIT();
    G_ISSUE(2, 2); CP_COMMIT();

    const int lr16 = lane & 15;
    const int lh   = lane >> 4;
    const uint32_t a_lane = (uint32_t)((wm * 64 + lr16) * (SROW * 2) + lh * 16);
    const uint32_t b_lane = (uint32_t)((wn * 32 + lr16) * (SROW * 2) + lh * 16);

    for (int kt = 0; kt < NKT; kt++) {
        if (kt + 3 <= NKT)       CP_WAIT(2);
        else if (kt + 2 == NKT)  CP_WAIT(1);
        else                     CP_WAIT(0);
        __syncthreads();

        {
            const uint32_t base = sbase + (uint32_t)(kt % 3) * TSTAGE;
#pragma unroll
            for (int ks = 0; ks < 2; ks++) {
                const uint32_t kb = ks * 32;
                uint32_t ah[4][4], bh[2][4], bl[2][4];
#pragma unroll
                for (int mf = 0; mf < 4; mf++)
                    LDMX4(ah[mf], base + a_lane + mf * 16 * (SROW * 2) + kb);
#pragma unroll
                for (int nf2 = 0; nf2 < 2; nf2++)
                    LDMX4(bh[nf2], base + TPART + b_lane + nf2 * 16 * (SROW * 2) + kb);
#pragma unroll
                for (int mf = 0; mf < 4; mf++)
#pragma unroll
                    for (int nf = 0; nf < 4; nf++)
                        MMA_F16(acc[mf][nf], ah[mf],
                                bh[nf >> 1][nf & 1], bh[nf >> 1][(nf & 1) + 2]);
#pragma unroll
                for (int nf2 = 0; nf2 < 2; nf2++)
                    LDMX4(bl[nf2], base + 2 * TPART + b_lane + nf2 * 16 * (SROW * 2) + kb);
#pragma unroll
                for (int mf = 0; mf < 4; mf++)
#pragma unroll
                    for (int nf = 0; nf < 4; nf++)
                        MMA_F16(acc[mf][nf], ah[mf],
                                bl[nf >> 1][nf & 1], bl[nf >> 1][(nf & 1) + 2]);
            }
        }
        __syncthreads();
        if (kt + 3 < NKT) { G_ISSUE(kt + 3, kt % 3); CP_COMMIT(); }
    }

    const int erow = bm + wm * 64 + (lane >> 2);
    const int ecol = bn + wn * 32 + (lane & 3) * 2;
#pragma unroll
    for (int mf = 0; mf < 4; mf++)
#pragma unroll
        for (int nf = 0; nf < 4; nf++) {
            float* c = acc[mf][nf];
            size_t ro0 = (size_t)(erow + mf * 16) * N + ecol + nf * 8;
            size_t ro1 = ro0 + 8 * (size_t)N;
            *(float2*)(C + ro0) = make_float2(c[0] * outscale, c[1] * outscale);
            *(float2*)(C + ro1) = make_float2(c[2] * outscale, c[3] * outscale);
        }
#undef G_ISSUE
}

// ---------------------------------------------------------------------------
// Tensor-core flash attention, causal, GQA. 3 MMA passes total:
// QK = Qh*K + Ql*K (Q split, K single); PV = P*V (both single fp16).
// 128 q-rows x 64 kv tiles, 8 warps, K/V double-buffered cp.async.
// smem: Qh,Ql (128x136) + 2 stages of (K,V 64x136) = 139264 B
// ---------------------------------------------------------------------------
#define FROWB 272
#define FQT   (128 * FROWB)            // 34816
#define FKT   (64 * FROWB)             // 17408
#define FKVST (2 * FKT)                // 34816 per stage
#define FLASH_SMEM (2 * FQT + 2 * FKVST)   // 139264
#define SC_LOG2E 0.12751631762078975f      // (1/sqrt(128)) * log2(e)

__global__ __launch_bounds__(256) void flash_tc(
    const __half* __restrict__ Qh, const __half* __restrict__ Ql,
    const __half* __restrict__ K16, const __half* __restrict__ V16,
    __half* __restrict__ O)
{
    extern __shared__ char sm[];
    const uint32_t sb  = smem_to_u32(sm);
    const uint32_t sQh = sb, sQl = sb + FQT;
    const uint32_t sKV = sb + 2 * FQT;

    const int q0  = blockIdx.x * 128;
    const int h   = blockIdx.y;
    const int b   = blockIdx.z;
    const int kvh = h >> 2;
    const int tid  = threadIdx.x;
    const int wid  = tid >> 5;
    const int lane = tid & 31;

    const __half* kvp[2] = {K16, V16};

    // per part: 64 rows x 16 chunks of 16B = 1024; 2 parts -> 8 per thread
#define KV_ISSUE(kt, buf) do { \
    uint32_t db = sKV + (uint32_t)(buf) * FKVST; \
    size_t gb = (size_t)(b * SS + (kt)) * KVDIM + kvh * HD; \
    _Pragma("unroll") \
    for (int p = 0; p < 2; p++) { \
        const __half* sp = kvp[p]; \
        _Pragma("unroll") \
        for (int j = 0; j < 4; j++) { \
            int i = tid + j * 256; \
            int r = i >> 4, c16 = (i & 15) * 16; \
            cp16(db + p * FKT + r * FROWB + c16, \
                 sp + gb + (size_t)r * KVDIM + (c16 >> 1)); \
        } \
    } \
} while (0)

    for (int i = tid; i < 128 * 16; i += 256) {
        int r = i >> 4, c = i & 15;
        size_t g = (size_t)(b * SS + q0 + r) * QDIM + h * HD + c * 8;
        int off = r * FROWB + c * 16;
        *(uint4*)(sm + off)       = *(const uint4*)(Qh + g);
        *(uint4*)(sm + FQT + off) = *(const uint4*)(Ql + g);
    }

    const int ntiles = q0 / 64 + 2;
    KV_ISSUE(0, 0); CP_COMMIT();
    KV_ISSUE(64, 1); CP_COMMIT();

    const uint32_t a_off  = (uint32_t)((16 * wid + (lane & 7) + 8 * ((lane >> 3) & 1)) * FROWB
                                       + (lane >> 4) * 16);
    const uint32_t vt_off = (uint32_t)(((lane & 7) + 8 * ((lane >> 3) & 1)) * FROWB
                                       + (lane >> 4) * 16);
    const uint32_t b_off  = (uint32_t)(((lane & 7) + 8 * (lane >> 4)) * FROWB
                                       + ((lane >> 3) & 1) * 16);

    float o[16][4];
#pragma unroll
    for (int nf = 0; nf < 16; nf++)
#pragma unroll
        for (int r = 0; r < 4; r++) o[nf][r] = 0.f;
    float mo[2] = {-1e30f, -1e30f};
    float ls[2] = {0.f, 0.f};

    for (int t = 0; t < ntiles; t++) {
        const int kt = t * 64;
        if (t + 1 < ntiles) CP_WAIT(1); else CP_WAIT(0);
        __syncthreads();

        const uint32_t kvb = sKV + (uint32_t)(t & 1) * FKVST;
        const uint32_t cK = kvb, cV = kvb + FKT;

        // ---- S = Q K^T (2 passes: Qh*K + Ql*K)
        float s[8][4];
#pragma unroll
        for (int f = 0; f < 8; f++)
#pragma unroll
            for (int r = 0; r < 4; r++) s[f][r] = 0.f;

#pragma unroll
        for (int ks = 0; ks < 8; ks++) {
            uint32_t qh[4], ql[4];
            LDMX4(qh, sQh + a_off + ks * 32);
            LDMX4(ql, sQl + a_off + ks * 32);
#pragma unroll
            for (int nb = 0; nb < 4; nb++) {
                uint32_t kk[4];
                LDMX4(kk, cK + b_off + nb * 16 * FROWB + ks * 32);
                MMA_F16(s[2 * nb],     qh, kk[0], kk[1]);
                MMA_F16(s[2 * nb + 1], qh, kk[2], kk[3]);
                MMA_F16(s[2 * nb],     ql, kk[0], kk[1]);
                MMA_F16(s[2 * nb + 1], ql, kk[2], kk[3]);
            }
        }

#pragma unroll
        for (int f = 0; f < 8; f++)
#pragma unroll
            for (int r = 0; r < 4; r++) s[f][r] *= SC_LOG2E;

        if (t >= ntiles - 2) {
            const int row0 = q0 + 16 * wid + (lane >> 2);
            const int colb = kt + 2 * (lane & 3);
#pragma unroll
            for (int f = 0; f < 8; f++)
#pragma unroll
                for (int r = 0; r < 4; r++) {
                    int col = colb + 8 * f + (r & 1);
                    int row = row0 + 8 * (r >> 1);
                    if (col > row) s[f][r] = -1e30f;
                }
        }

        // ---- online softmax
#pragma unroll
        for (int hh = 0; hh < 2; hh++) {
            float mt = -1e30f;
#pragma unroll
            for (int f = 0; f < 8; f++)
                mt = fmaxf(mt, fmaxf(s[f][2 * hh], s[f][2 * hh + 1]));
            mt = fmaxf(mt, __shfl_xor_sync(0xffffffffu, mt, 1));
            mt = fmaxf(mt, __shfl_xor_sync(0xffffffffu, mt, 2));
            float mn = fmaxf(mo[hh], mt);
            float alpha = exp2f(mo[hh] - mn);
            float rs = 0.f;
#pragma unroll
            for (int f = 0; f < 8; f++) {
                float p0 = exp2f(s[f][2 * hh] - mn);
                float p1 = exp2f(s[f][2 * hh + 1] - mn);
                s[f][2 * hh] = p0;
                s[f][2 * hh + 1] = p1;
                rs += p0 + p1;
            }
            rs += __shfl_xor_sync(0xffffffffu, rs, 1);
            rs += __shfl_xor_sync(0xffffffffu, rs, 2);
            ls[hh] = ls[hh] * alpha + rs;
            mo[hh] = mn;
#pragma unroll
            for (int nf = 0; nf < 16; nf++) {
                o[nf][2 * hh]     *= alpha;
                o[nf][2 * hh + 1] *= alpha;
            }
        }

        // ---- O += P V (single pass, P single fp16)
#pragma unroll
        for (int ks = 0; ks < 4; ks++) {
            uint32_t ph[4];
            ph[0] = pack_h2(__float2half_rn(s[2 * ks][0]),     __float2half_rn(s[2 * ks][1]));
            ph[1] = pack_h2(__float2half_rn(s[2 * ks][2]),     __float2half_rn(s[2 * ks][3]));
            ph[2] = pack_h2(__float2half_rn(s[2 * ks + 1][0]), __float2half_rn(s[2 * ks + 1][1]));
            ph[3] = pack_h2(__float2half_rn(s[2 * ks + 1][2]), __float2half_rn(s[2 * ks + 1][3]));
#pragma unroll
            for (int nb = 0; nb < 8; nb++) {
                uint32_t vv[4];
                LDMX4T(vv, cV + vt_off + ks * 16 * FROWB + nb * 32);
                MMA_F16(o[2 * nb],     ph, vv[0], vv[1]);
                MMA_F16(o[2 * nb + 1], ph, vv[2], vv[3]);
            }
        }

        __syncthreads();
        if (t + 2 < ntiles) { KV_ISSUE(kt + 128, t & 1); CP_COMMIT(); }
    }

    // epilogue: normalize, store single fp16
    float inv0 = 1.f / ls[0];
    float inv1 = 1.f / ls[1];
#pragma unroll
    for (int nf = 0; nf < 16; nf++) {
#pragma unroll
        for (int rp = 0; rp < 2; rp++) {
            float invv = rp ? inv1 : inv0;
            float v0 = o[nf][2 * rp] * invv;
            float v1 = o[nf][2 * rp + 1] * invv;
            uint32_t hv = pack_h2(__float2half_rn(v0), __float2half_rn(v1));
            int row = q0 + 16 * wid + (lane >> 2) + 8 * rp;
            int col = h * HD + 8 * nf + 2 * (lane & 3);
            size_t g = (size_t)(b * SS + row) * QDIM + col;
            *(uint32_t*)(O + g) = hv;
        }
    }
#undef KV_ISSUE
}

// ---------------------------------------------------------------------------
// launcher
// ---------------------------------------------------------------------------
extern "C" void kernel_launch(void* const* d_in, const int* in_sizes, int n_in,
                              void* d_out, int out_size)
{
    const float* hidden = (const float*)d_in[0];
    const float* Wq     = (const float*)d_in[1];
    const float* Wk     = (const float*)d_in[2];
    const float* Wv     = (const float*)d_in[3];
    const float* Wo     = (const float*)d_in[4];
    const int*   pos    = (const int*)d_in[5];
    float* out = (float*)d_out;

    float* Cb;
    cudaGetSymbolAddress((void**)&Cb, g_C);
    __half *H16, *Wh, *Wl, *Woh, *Wol;
    __half *Qh, *Ql, *K16, *V16, *O16;
    cudaGetSymbolAddress((void**)&H16, g_H16);
    cudaGetSymbolAddress((void**)&Wh, g_Wh);   cudaGetSymbolAddress((void**)&Wl, g_Wl);
    cudaGetSymbolAddress((void**)&Woh, g_Woh); cudaGetSymbolAddress((void**)&Wol, g_Wol);
    cudaGetSymbolAddress((void**)&Qh, g_Qh);   cudaGetSymbolAddress((void**)&Ql, g_Ql);
    cudaGetSymbolAddress((void**)&K16, g_K16); cudaGetSymbolAddress((void**)&V16, g_V16);
    cudaGetSymbolAddress((void**)&O16, g_O16);

    cudaFuncSetAttribute(gemm_f16_2p,
                         cudaFuncAttributeMaxDynamicSharedMemorySize, GEMM_SMEM);
    cudaFuncSetAttribute(flash_tc,
                         cudaFuncAttributeMaxDynamicSharedMemorySize, FLASH_SMEM);

    // 1. convert hidden to fp16 single; weights to scaled fp16 hi/lo (packed QKV)
    split_single<<<(MTOK * HID / 4 + 255) / 256, 256>>>(hidden, H16, MTOK * HID / 4);
    split_w<<<(QDIM * HID / 4 + 255) / 256, 256>>>(Wq, Wh, Wl, QDIM * HID / 4);
    split_w<<<(KVDIM * HID / 4 + 255) / 256, 256>>>(
        Wk, Wh + (size_t)QDIM * HID, Wl + (size_t)QDIM * HID, KVDIM * HID / 4);
    split_w<<<(KVDIM * HID / 4 + 255) / 256, 256>>>(
        Wv, Wh + (size_t)(QDIM + KVDIM) * HID, Wl + (size_t)(QDIM + KVDIM) * HID,
        KVDIM * HID / 4);
    split_w<<<(HID * QDIM / 4 + 255) / 256, 256>>>(Wo, Woh, Wol, HID * QDIM / 4);

    // 2. fused QKV projection -> fp32 C [MTOK, 3072] (unscale by 1/64)
    gemm_f16_2p<<<dim3(QKVD / 128, MTOK / 128), 256, GEMM_SMEM>>>(
        H16, Wh, Wl, Cb, MTOK, QKVD, HID, INV_WSCALE);

    // 3. RoPE: Q -> split hi/lo; K -> single; V -> single
    rope_split_kernel<<<(MTOK * 64) / 256, 256>>>(Cb, QKVD, pos, NH, Qh, Ql);
    rope_single_kernel<<<(MTOK * 64) / 256, 256>>>(Cb + QDIM, QKVD, pos, NKV, K16);
    single_strided<<<(MTOK * KVDIM / 4 + 255) / 256, 256>>>(
        Cb + QDIM + KVDIM, QKVD, KVDIM, V16, MTOK);

    // 4. flash attention -> single fp16 O
    flash_tc<<<dim3(SS / 128, NH, BB), 256, FLASH_SMEM>>>(Qh, Ql, K16, V16, O16);

    // 5. output projection (unscale by 1/64)
    gemm_f16_2p<<<dim3(HID / 128, MTOK / 128), 256, GEMM_SMEM>>>(
        O16, Woh, Wol, out, MTOK, HID, QDIM, INV_WSCALE);
}

// round 8
// speedup vs baseline: 2.1701x; 1.2962x over previous
#include <cuda_runtime.h>
#include <cuda_fp16.h>
#include <math.h>
#include <stdint.h>

// Problem constants
#define BB   2
#define SS   2048
#define HID  2048
#define NH   16
#define NKV  4
#define HD   128
#define MTOK (BB*SS)          // 4096
#define QDIM (NH*HD)          // 2048
#define KVDIM (NKV*HD)        // 512
#define QKVD (QDIM + 2*KVDIM) // 3072

#define WSCALE    64.0f
#define INV_WSCALE 0.015625f

// ---------------------------------------------------------------------------
// Scratch (device globals; no allocation allowed)
// ---------------------------------------------------------------------------
__device__ float g_C[(size_t)MTOK * QKVD];                 // fused QKV fp32
__device__ __half g_H16[(size_t)MTOK * HID];               // hidden fp16 single
__device__ __half g_W16[(size_t)QKVD * HID];               // packed QKV weights x64
__device__ __half g_Wo16[(size_t)HID * QDIM];              // Wo x64
__device__ __half g_Qh[(size_t)MTOK * QDIM],  g_Ql[(size_t)MTOK * QDIM];
__device__ __half g_K16[(size_t)MTOK * KVDIM];             // K single fp16 (roped)
__device__ __half g_V16[(size_t)MTOK * KVDIM];             // V single fp16
__device__ __half g_O16[(size_t)MTOK * QDIM];              // attn out fp16 single

// ---------------------------------------------------------------------------
// helpers
// ---------------------------------------------------------------------------
__device__ __forceinline__ uint32_t smem_to_u32(const void* p) {
    uint32_t a;
    asm("{ .reg .u64 t; cvta.to.shared.u64 t, %1; cvt.u32.u64 %0, t; }"
        : "=r"(a) : "l"(p));
    return a;
}
__device__ __forceinline__ uint32_t pack_h2(__half a, __half b) {
    return (uint32_t)__half_as_ushort(a) | ((uint32_t)__half_as_ushort(b) << 16);
}
__device__ __forceinline__ void split2h(float a, float b, uint32_t& h, uint32_t& l) {
    __half ha = __float2half_rn(a);
    __half hb = __float2half_rn(b);
    __half la = __float2half_rn(a - __half2float(ha));
    __half lb = __float2half_rn(b - __half2float(hb));
    h = pack_h2(ha, hb);
    l = pack_h2(la, lb);
}

#define LDMX4(r, addr) \
    asm volatile("ldmatrix.sync.aligned.m8n8.x4.shared.b16 {%0,%1,%2,%3}, [%4];" \
        : "=r"((r)[0]), "=r"((r)[1]), "=r"((r)[2]), "=r"((r)[3]) : "r"(addr))
#define LDMX4T(r, addr) \
    asm volatile("ldmatrix.sync.aligned.m8n8.x4.trans.shared.b16 {%0,%1,%2,%3}, [%4];" \
        : "=r"((r)[0]), "=r"((r)[1]), "=r"((r)[2]), "=r"((r)[3]) : "r"(addr))
#define MMA_F16(c, a, b0, b1) \
    asm volatile("mma.sync.aligned.m16n8k16.row.col.f32.f16.f16.f32 " \
        "{%0,%1,%2,%3},{%4,%5,%6,%7},{%8,%9},{%0,%1,%2,%3};" \
        : "+f"((c)[0]), "+f"((c)[1]), "+f"((c)[2]), "+f"((c)[3]) \
        : "r"((a)[0]), "r"((a)[1]), "r"((a)[2]), "r"((a)[3]), "r"(b0), "r"(b1))

__device__ __forceinline__ void cp16(uint32_t dst, const void* src) {
    asm volatile("cp.async.cg.shared.global [%0], [%1], 16;" :: "r"(dst), "l"(src));
}
#define CP_COMMIT() asm volatile("cp.async.commit_group;" ::: "memory")
#define CP_WAIT(n)  asm volatile("cp.async.wait_group %0;" :: "n"(n) : "memory")

// ---------------------------------------------------------------------------
// convert kernels
// ---------------------------------------------------------------------------
__global__ void split_single(const float* __restrict__ src,
                             __half* __restrict__ o, int n4)
{
    int i = blockIdx.x * blockDim.x + threadIdx.x;
    if (i >= n4) return;
    float4 v = ((const float4*)src)[i];
    ((uint2*)o)[i] = make_uint2(
        pack_h2(__float2half_rn(v.x), __float2half_rn(v.y)),
        pack_h2(__float2half_rn(v.z), __float2half_rn(v.w)));
}

// fp32 weights -> scaled (x64) single fp16
__global__ void conv_w(const float* __restrict__ src,
                       __half* __restrict__ o, int n4)
{
    int i = blockIdx.x * blockDim.x + threadIdx.x;
    if (i >= n4) return;
    float4 v = ((const float4*)src)[i];
    ((uint2*)o)[i] = make_uint2(
        pack_h2(__float2half_rn(v.x * WSCALE), __float2half_rn(v.y * WSCALE)),
        pack_h2(__float2half_rn(v.z * WSCALE), __float2half_rn(v.w * WSCALE)));
}

// strided fp32 -> single fp16 (for V slice of fused C)
__global__ void single_strided(const float* __restrict__ src, int stride, int ncols,
                               __half* __restrict__ o, int nrows)
{
    int i = blockIdx.x * blockDim.x + threadIdx.x;
    int per_row = ncols / 4;
    if (i >= nrows * per_row) return;
    int r = i / per_row, c = (i - r * per_row) * 4;
    float4 v = *(const float4*)(src + (size_t)r * stride + c);
    size_t o4 = ((size_t)r * ncols + c) >> 2;
    ((uint2*)o)[o4] = make_uint2(
        pack_h2(__float2half_rn(v.x), __float2half_rn(v.y)),
        pack_h2(__float2half_rn(v.z), __float2half_rn(v.w)));
}

// ---------------------------------------------------------------------------
// RoPE kernels (strided source from fused C)
// ---------------------------------------------------------------------------
__global__ void rope_split_kernel(const float* __restrict__ X, int stride,
                                  const int* __restrict__ pos_ids, int nheads,
                                  __half* __restrict__ Xh,
                                  __half* __restrict__ Xl)
{
    int idx = blockIdx.x * blockDim.x + threadIdx.x;
    if (idx >= MTOK * 64) return;
    int i = idx & 63;
    int m = idx >> 6;
    int p = pos_ids[m];

    double inv = exp(-(double)i * 0.14391156831212787);  // ln(10000)/64
    double ang = (double)p * inv;
    double k = rint(ang * 0.15915494309189535);
    float r = (float)(ang - k * 6.283185307179586477);
    float sv, cv;
    sincosf(r, &sv, &cv);

    size_t sbase = (size_t)m * stride + i;
    size_t obase = (size_t)m * (nheads * 128) + i;
#pragma unroll 4
    for (int h = 0; h < nheads; h++) {
        float x1 = X[sbase], x2 = X[sbase + 64];
        float y1 = x1 * cv - x2 * sv;
        float y2 = x2 * cv + x1 * sv;
        __half h1 = __float2half_rn(y1);
        __half h2 = __float2half_rn(y2);
        Xh[obase]      = h1;
        Xh[obase + 64] = h2;
        Xl[obase]      = __float2half_rn(y1 - __half2float(h1));
        Xl[obase + 64] = __float2half_rn(y2 - __half2float(h2));
        sbase += 128;
        obase += 128;
    }
}

__global__ void rope_single_kernel(const float* __restrict__ X, int stride,
                                   const int* __restrict__ pos_ids, int nheads,
                                   __half* __restrict__ Xo)
{
    int idx = blockIdx.x * blockDim.x + threadIdx.x;
    if (idx >= MTOK * 64) return;
    int i = idx & 63;
    int m = idx >> 6;
    int p = pos_ids[m];

    double inv = exp(-(double)i * 0.14391156831212787);
    double ang = (double)p * inv;
    double k = rint(ang * 0.15915494309189535);
    float r = (float)(ang - k * 6.283185307179586477);
    float sv, cv;
    sincosf(r, &sv, &cv);

    size_t sbase = (size_t)m * stride + i;
    size_t obase = (size_t)m * (nheads * 128) + i;
#pragma unroll 4
    for (int h = 0; h < nheads; h++) {
        float x1 = X[sbase], x2 = X[sbase + 64];
        Xo[obase]      = __float2half_rn(x1 * cv - x2 * sv);
        Xo[obase + 64] = __float2half_rn(x2 * cv + x1 * sv);
        sbase += 128;
        obase += 128;
    }
}

// ---------------------------------------------------------------------------
// Single-pass fp16 GEMM: C[M,N] = outscale * A16[M,K] @ B16[N,K]^T
// CTA 128x128, BK=32, 256 thr, 8 warps (warp 64x32). 3-stage cp.async.
// smem: parts A|B (rows padded to 40 halves), 20480 B/stage, 61440 total.
// ---------------------------------------------------------------------------
#define SROW   40
#define TPART  (128 * SROW * 2)        // 10240 B
#define TSTAGE (2 * TPART)             // 20480 B
#define GEMM_SMEM (3 * TSTAGE)         // 61440 B

__global__ __launch_bounds__(256) void gemm_f16(
    const __half* __restrict__ A, const __half* __restrict__ B,
    float* __restrict__ C, int M, int N, int K, float outscale)
{
    extern __shared__ char smem[];
    const uint32_t sbase = smem_to_u32(smem);

    const int tid  = threadIdx.x;
    const int wid  = tid >> 5;
    const int lane = tid & 31;
    const int wm   = wid >> 2;
    const int wn   = wid & 3;
    const int bm   = blockIdx.y * 128;
    const int bn   = blockIdx.x * 128;
    const int NKT  = K / 32;

    const int cr0 = tid >> 2, cc0 = (tid & 3) * 16;
    const int cr1 = (tid + 256) >> 2;

#define G_ISSUE(kt, buf) do { \
    uint32_t db = sbase + (uint32_t)(buf) * TSTAGE; \
    cp16(db + cr0 * 80 + cc0, \
         A + (size_t)(bm + cr0) * K + (kt) * 32 + (cc0 >> 1)); \
    cp16(db + cr1 * 80 + cc0, \
         A + (size_t)(bm + cr1) * K + (kt) * 32 + (cc0 >> 1)); \
    cp16(db + TPART + cr0 * 80 + cc0, \
         B + (size_t)(bn + cr0) * K + (kt) * 32 + (cc0 >> 1)); \
    cp16(db + TPART + cr1 * 80 + cc0, \
         B + (size_t)(bn + cr1) * K + (kt) * 32 + (cc0 >> 1)); \
} while (0)

    float acc[4][4][4];
#pragma unroll
    for (int mf = 0; mf < 4; mf++)
#pragma unroll
        for (int nf = 0; nf < 4; nf++)
#pragma unroll
            for (int r = 0; r < 4; r++) acc[mf][nf][r] = 0.f;

    G_ISSUE(0, 0); CP_COMMIT();
    G_ISSUE(1, 1); CP_COMMIT();
    G_ISSUE(2, 2); CP_COMMIT();

    const int lr16 = lane & 15;
    const int lh   = lane >> 4;
    const uint32_t a_lane = (uint32_t)((wm * 64 + lr16) * (SROW * 2) + lh * 16);
    const uint32_t b_lane = (uint32_t)((wn * 32 + lr16) * (SROW * 2) + lh * 16);

    for (int kt = 0; kt < NKT; kt++) {
        if (kt + 3 <= NKT)       CP_WAIT(2);
        else if (kt + 2 == NKT)  CP_WAIT(1);
        else                     CP_WAIT(0);
        __syncthreads();

        {
            const uint32_t base = sbase + (uint32_t)(kt % 3) * TSTAGE;
#pragma unroll
            for (int ks = 0; ks < 2; ks++) {
                const uint32_t kb = ks * 32;
                uint32_t ah[4][4], bh[2][4];
#pragma unroll
                for (int mf = 0; mf < 4; mf++)
                    LDMX4(ah[mf], base + a_lane + mf * 16 * (SROW * 2) + kb);
#pragma unroll
                for (int nf2 = 0; nf2 < 2; nf2++)
                    LDMX4(bh[nf2], base + TPART + b_lane + nf2 * 16 * (SROW * 2) + kb);
#pragma unroll
                for (int mf = 0; mf < 4; mf++)
#pragma unroll
                    for (int nf = 0; nf < 4; nf++)
                        MMA_F16(acc[mf][nf], ah[mf],
                                bh[nf >> 1][nf & 1], bh[nf >> 1][(nf & 1) + 2]);
            }
        }
        __syncthreads();
        if (kt + 3 < NKT) { G_ISSUE(kt + 3, kt % 3); CP_COMMIT(); }
    }

    const int erow = bm + wm * 64 + (lane >> 2);
    const int ecol = bn + wn * 32 + (lane & 3) * 2;
#pragma unroll
    for (int mf = 0; mf < 4; mf++)
#pragma unroll
        for (int nf = 0; nf < 4; nf++) {
            float* c = acc[mf][nf];
            size_t ro0 = (size_t)(erow + mf * 16) * N + ecol + nf * 8;
            size_t ro1 = ro0 + 8 * (size_t)N;
            *(float2*)(C + ro0) = make_float2(c[0] * outscale, c[1] * outscale);
            *(float2*)(C + ro1) = make_float2(c[2] * outscale, c[3] * outscale);
        }
#undef G_ISSUE
}

// ---------------------------------------------------------------------------
// Tensor-core flash attention, causal, GQA. 3 MMA passes total:
// QK = Qh*K + Ql*K (Q split, K single); PV = P*V (both single fp16).
// 128 q-rows x 64 kv tiles, 8 warps, K/V double-buffered cp.async.
// ---------------------------------------------------------------------------
#define FROWB 272
#define FQT   (128 * FROWB)            // 34816
#define FKT   (64 * FROWB)             // 17408
#define FKVST (2 * FKT)                // 34816 per stage
#define FLASH_SMEM (2 * FQT + 2 * FKVST)   // 139264
#define SC_LOG2E 0.12751631762078975f      // (1/sqrt(128)) * log2(e)

__global__ __launch_bounds__(256) void flash_tc(
    const __half* __restrict__ Qh, const __half* __restrict__ Ql,
    const __half* __restrict__ K16, const __half* __restrict__ V16,
    __half* __restrict__ O)
{
    extern __shared__ char sm[];
    const uint32_t sb  = smem_to_u32(sm);
    const uint32_t sQh = sb, sQl = sb + FQT;
    const uint32_t sKV = sb + 2 * FQT;

    const int q0  = blockIdx.x * 128;
    const int h   = blockIdx.y;
    const int b   = blockIdx.z;
    const int kvh = h >> 2;
    const int tid  = threadIdx.x;
    const int wid  = tid >> 5;
    const int lane = tid & 31;

    const __half* kvp[2] = {K16, V16};

#define KV_ISSUE(kt, buf) do { \
    uint32_t db = sKV + (uint32_t)(buf) * FKVST; \
    size_t gb = (size_t)(b * SS + (kt)) * KVDIM + kvh * HD; \
    _Pragma("unroll") \
    for (int p = 0; p < 2; p++) { \
        const __half* sp = kvp[p]; \
        _Pragma("unroll") \
        for (int j = 0; j < 4; j++) { \
            int i = tid + j * 256; \
            int r = i >> 4, c16 = (i & 15) * 16; \
            cp16(db + p * FKT + r * FROWB + c16, \
                 sp + gb + (size_t)r * KVDIM + (c16 >> 1)); \
        } \
    } \
} while (0)

    for (int i = tid; i < 128 * 16; i += 256) {
        int r = i >> 4, c = i & 15;
        size_t g = (size_t)(b * SS + q0 + r) * QDIM + h * HD + c * 8;
        int off = r * FROWB + c * 16;
        *(uint4*)(sm + off)       = *(const uint4*)(Qh + g);
        *(uint4*)(sm + FQT + off) = *(const uint4*)(Ql + g);
    }

    const int ntiles = q0 / 64 + 2;
    KV_ISSUE(0, 0); CP_COMMIT();
    KV_ISSUE(64, 1); CP_COMMIT();

    const uint32_t a_off  = (uint32_t)((16 * wid + (lane & 7) + 8 * ((lane >> 3) & 1)) * FROWB
                                       + (lane >> 4) * 16);
    const uint32_t vt_off = (uint32_t)(((lane & 7) + 8 * ((lane >> 3) & 1)) * FROWB
                                       + (lane >> 4) * 16);
    const uint32_t b_off  = (uint32_t)(((lane & 7) + 8 * (lane >> 4)) * FROWB
                                       + ((lane >> 3) & 1) * 16);

    float o[16][4];
#pragma unroll
    for (int nf = 0; nf < 16; nf++)
#pragma unroll
        for (int r = 0; r < 4; r++) o[nf][r] = 0.f;
    float mo[2] = {-1e30f, -1e30f};
    float ls[2] = {0.f, 0.f};

    for (int t = 0; t < ntiles; t++) {
        const int kt = t * 64;
        if (t + 1 < ntiles) CP_WAIT(1); else CP_WAIT(0);
        __syncthreads();

        const uint32_t kvb = sKV + (uint32_t)(t & 1) * FKVST;
        const uint32_t cK = kvb, cV = kvb + FKT;

        // ---- S = Q K^T (2 passes: Qh*K + Ql*K)
        float s[8][4];
#pragma unroll
        for (int f = 0; f < 8; f++)
#pragma unroll
            for (int r = 0; r < 4; r++) s[f][r] = 0.f;

#pragma unroll
        for (int ks = 0; ks < 8; ks++) {
            uint32_t qh[4], ql[4];
            LDMX4(qh, sQh + a_off + ks * 32);
            LDMX4(ql, sQl + a_off + ks * 32);
#pragma unroll
            for (int nb = 0; nb < 4; nb++) {
                uint32_t kk[4];
                LDMX4(kk, cK + b_off + nb * 16 * FROWB + ks * 32);
                MMA_F16(s[2 * nb],     qh, kk[0], kk[1]);
                MMA_F16(s[2 * nb + 1], qh, kk[2], kk[3]);
                MMA_F16(s[2 * nb],     ql, kk[0], kk[1]);
                MMA_F16(s[2 * nb + 1], ql, kk[2], kk[3]);
            }
        }

#pragma unroll
        for (int f = 0; f < 8; f++)
#pragma unroll
            for (int r = 0; r < 4; r++) s[f][r] *= SC_LOG2E;

        if (t >= ntiles - 2) {
            const int row0 = q0 + 16 * wid + (lane >> 2);
            const int colb = kt + 2 * (lane & 3);
#pragma unroll
            for (int f = 0; f < 8; f++)
#pragma unroll
                for (int r = 0; r < 4; r++) {
                    int col = colb + 8 * f + (r & 1);
                    int row = row0 + 8 * (r >> 1);
                    if (col > row) s[f][r] = -1e30f;
                }
        }

        // ---- online softmax
#pragma unroll
        for (int hh = 0; hh < 2; hh++) {
            float mt = -1e30f;
#pragma unroll
            for (int f = 0; f < 8; f++)
                mt = fmaxf(mt, fmaxf(s[f][2 * hh], s[f][2 * hh + 1]));
            mt = fmaxf(mt, __shfl_xor_sync(0xffffffffu, mt, 1));
            mt = fmaxf(mt, __shfl_xor_sync(0xffffffffu, mt, 2));
            float mn = fmaxf(mo[hh], mt);
            float alpha = exp2f(mo[hh] - mn);
            float rs = 0.f;
#pragma unroll
            for (int f = 0; f < 8; f++) {
                float p0 = exp2f(s[f][2 * hh] - mn);
                float p1 = exp2f(s[f][2 * hh + 1] - mn);
                s[f][2 * hh] = p0;
                s[f][2 * hh + 1] = p1;
                rs += p0 + p1;
            }
            rs += __shfl_xor_sync(0xffffffffu, rs, 1);
            rs += __shfl_xor_sync(0xffffffffu, rs, 2);
            ls[hh] = ls[hh] * alpha + rs;
            mo[hh] = mn;
#pragma unroll
            for (int nf = 0; nf < 16; nf++) {
                o[nf][2 * hh]     *= alpha;
                o[nf][2 * hh + 1] *= alpha;
            }
        }

        // ---- O += P V (single pass)
#pragma unroll
        for (int ks = 0; ks < 4; ks++) {
            uint32_t ph[4];
            ph[0] = pack_h2(__float2half_rn(s[2 * ks][0]),     __float2half_rn(s[2 * ks][1]));
            ph[1] = pack_h2(__float2half_rn(s[2 * ks][2]),     __float2half_rn(s[2 * ks][3]));
            ph[2] = pack_h2(__float2half_rn(s[2 * ks + 1][0]), __float2half_rn(s[2 * ks + 1][1]));
            ph[3] = pack_h2(__float2half_rn(s[2 * ks + 1][2]), __float2half_rn(s[2 * ks + 1][3]));
#pragma unroll
            for (int nb = 0; nb < 8; nb++) {
                uint32_t vv[4];
                LDMX4T(vv, cV + vt_off + ks * 16 * FROWB + nb * 32);
                MMA_F16(o[2 * nb],     ph, vv[0], vv[1]);
                MMA_F16(o[2 * nb + 1], ph, vv[2], vv[3]);
            }
        }

        __syncthreads();
        if (t + 2 < ntiles) { KV_ISSUE(kt + 128, t & 1); CP_COMMIT(); }
    }

    // epilogue: normalize, store single fp16
    float inv0 = 1.f / ls[0];
    float inv1 = 1.f / ls[1];
#pragma unroll
    for (int nf = 0; nf < 16; nf++) {
#pragma unroll
        for (int rp = 0; rp < 2; rp++) {
            float invv = rp ? inv1 : inv0;
            float v0 = o[nf][2 * rp] * invv;
            float v1 = o[nf][2 * rp + 1] * invv;
            uint32_t hv = pack_h2(__float2half_rn(v0), __float2half_rn(v1));
            int row = q0 + 16 * wid + (lane >> 2) + 8 * rp;
            int col = h * HD + 8 * nf + 2 * (lane & 3);
            size_t g = (size_t)(b * SS + row) * QDIM + col;
            *(uint32_t*)(O + g) = hv;
        }
    }
#undef KV_ISSUE
}

// ---------------------------------------------------------------------------
// launcher
// ---------------------------------------------------------------------------
extern "C" void kernel_launch(void* const* d_in, const int* in_sizes, int n_in,
                              void* d_out, int out_size)
{
    const float* hidden = (const float*)d_in[0];
    const float* Wq     = (const float*)d_in[1];
    const float* Wk     = (const float*)d_in[2];
    const float* Wv     = (const float*)d_in[3];
    const float* Wo     = (const float*)d_in[4];
    const int*   pos    = (const int*)d_in[5];
    float* out = (float*)d_out;

    float* Cb;
    cudaGetSymbolAddress((void**)&Cb, g_C);
    __half *H16, *W16, *Wo16;
    __half *Qh, *Ql, *K16, *V16, *O16;
    cudaGetSymbolAddress((void**)&H16, g_H16);
    cudaGetSymbolAddress((void**)&W16, g_W16);
    cudaGetSymbolAddress((void**)&Wo16, g_Wo16);
    cudaGetSymbolAddress((void**)&Qh, g_Qh);   cudaGetSymbolAddress((void**)&Ql, g_Ql);
    cudaGetSymbolAddress((void**)&K16, g_K16); cudaGetSymbolAddress((void**)&V16, g_V16);
    cudaGetSymbolAddress((void**)&O16, g_O16);

    cudaFuncSetAttribute(gemm_f16,
                         cudaFuncAttributeMaxDynamicSharedMemorySize, GEMM_SMEM);
    cudaFuncSetAttribute(flash_tc,
                         cudaFuncAttributeMaxDynamicSharedMemorySize, FLASH_SMEM);

    // 1. convert: hidden -> fp16; weights -> scaled single fp16 (packed QKV)
    split_single<<<(MTOK * HID / 4 + 255) / 256, 256>>>(hidden, H16, MTOK * HID / 4);
    conv_w<<<(QDIM * HID / 4 + 255) / 256, 256>>>(Wq, W16, QDIM * HID / 4);
    conv_w<<<(KVDIM * HID / 4 + 255) / 256, 256>>>(
        Wk, W16 + (size_t)QDIM * HID, KVDIM * HID / 4);
    conv_w<<<(KVDIM * HID / 4 + 255) / 256, 256>>>(
        Wv, W16 + (size_t)(QDIM + KVDIM) * HID, KVDIM * HID / 4);
    conv_w<<<(HID * QDIM / 4 + 255) / 256, 256>>>(Wo, Wo16, HID * QDIM / 4);

    // 2. fused QKV projection -> fp32 C [MTOK, 3072] (unscale by 1/64)
    gemm_f16<<<dim3(QKVD / 128, MTOK / 128), 256, GEMM_SMEM>>>(
        H16, W16, Cb, MTOK, QKVD, HID, INV_WSCALE);

    // 3. RoPE: Q -> split hi/lo; K -> single; V -> single
    rope_split_kernel<<<(MTOK * 64) / 256, 256>>>(Cb, QKVD, pos, NH, Qh, Ql);
    rope_single_kernel<<<(MTOK * 64) / 256, 256>>>(Cb + QDIM, QKVD, pos, NKV, K16);
    single_strided<<<(MTOK * KVDIM / 4 + 255) / 256, 256>>>(
        Cb + QDIM + KVDIM, QKVD, KVDIM, V16, MTOK);

    // 4. flash attention -> single fp16 O
    flash_tc<<<dim3(SS / 128, NH, BB), 256, FLASH_SMEM>>>(Qh, Ql, K16, V16, O16);

    // 5. output projection (unscale by 1/64)
    gemm_f16<<<dim3(HID / 128, MTOK / 128), 256, GEMM_SMEM>>>(
        O16, Wo16, out, MTOK, HID, QDIM, INV_WSCALE);
}

// round 9
// speedup vs baseline: 2.3534x; 1.0845x over previous
#include <cuda_runtime.h>
#include <cuda_fp16.h>
#include <math.h>
#include <stdint.h>

// Problem constants
#define BB   2
#define SS   2048
#define HID  2048
#define NH   16
#define NKV  4
#define HD   128
#define MTOK (BB*SS)          // 4096
#define QDIM (NH*HD)          // 2048
#define KVDIM (NKV*HD)        // 512
#define QKVD (QDIM + 2*KVDIM) // 3072

#define WSCALE    64.0f
#define INV_WSCALE 0.015625f

// ---------------------------------------------------------------------------
// Scratch (device globals; no allocation allowed)
// ---------------------------------------------------------------------------
__device__ float g_C[(size_t)MTOK * QKVD];                 // fused QKV fp32
__device__ __half g_H16[(size_t)MTOK * HID];               // hidden fp16
__device__ __half g_W16[(size_t)QKVD * HID];               // packed QKV weights x64
__device__ __half g_Wo16[(size_t)HID * QDIM];              // Wo x64
__device__ __half g_Q16[(size_t)MTOK * QDIM];              // Q fp16 (roped)
__device__ __half g_K16[(size_t)MTOK * KVDIM];             // K fp16 (roped)
__device__ __half g_V16[(size_t)MTOK * KVDIM];             // V fp16
__device__ __half g_O16[(size_t)MTOK * QDIM];              // attn out fp16

// ---------------------------------------------------------------------------
// helpers
// ---------------------------------------------------------------------------
__device__ __forceinline__ uint32_t smem_to_u32(const void* p) {
    uint32_t a;
    asm("{ .reg .u64 t; cvta.to.shared.u64 t, %1; cvt.u32.u64 %0, t; }"
        : "=r"(a) : "l"(p));
    return a;
}
__device__ __forceinline__ uint32_t pack_h2(__half a, __half b) {
    return (uint32_t)__half_as_ushort(a) | ((uint32_t)__half_as_ushort(b) << 16);
}

#define LDMX4(r, addr) \
    asm volatile("ldmatrix.sync.aligned.m8n8.x4.shared.b16 {%0,%1,%2,%3}, [%4];" \
        : "=r"((r)[0]), "=r"((r)[1]), "=r"((r)[2]), "=r"((r)[3]) : "r"(addr))
#define LDMX4T(r, addr) \
    asm volatile("ldmatrix.sync.aligned.m8n8.x4.trans.shared.b16 {%0,%1,%2,%3}, [%4];" \
        : "=r"((r)[0]), "=r"((r)[1]), "=r"((r)[2]), "=r"((r)[3]) : "r"(addr))
#define MMA_F16(c, a, b0, b1) \
    asm volatile("mma.sync.aligned.m16n8k16.row.col.f32.f16.f16.f32 " \
        "{%0,%1,%2,%3},{%4,%5,%6,%7},{%8,%9},{%0,%1,%2,%3};" \
        : "+f"((c)[0]), "+f"((c)[1]), "+f"((c)[2]), "+f"((c)[3]) \
        : "r"((a)[0]), "r"((a)[1]), "r"((a)[2]), "r"((a)[3]), "r"(b0), "r"(b1))

__device__ __forceinline__ void cp16(uint32_t dst, const void* src) {
    asm volatile("cp.async.cg.shared.global [%0], [%1], 16;" :: "r"(dst), "l"(src));
}
#define CP_COMMIT() asm volatile("cp.async.commit_group;" ::: "memory")
#define CP_WAIT(n)  asm volatile("cp.async.wait_group %0;" :: "n"(n) : "memory")

// ---------------------------------------------------------------------------
// convert kernels
// ---------------------------------------------------------------------------
__global__ void split_single(const float* __restrict__ src,
                             __half* __restrict__ o, int n4)
{
    int i = blockIdx.x * blockDim.x + threadIdx.x;
    if (i >= n4) return;
    float4 v = ((const float4*)src)[i];
    ((uint2*)o)[i] = make_uint2(
        pack_h2(__float2half_rn(v.x), __float2half_rn(v.y)),
        pack_h2(__float2half_rn(v.z), __float2half_rn(v.w)));
}

__global__ void conv_w(const float* __restrict__ src,
                       __half* __restrict__ o, int n4)
{
    int i = blockIdx.x * blockDim.x + threadIdx.x;
    if (i >= n4) return;
    float4 v = ((const float4*)src)[i];
    ((uint2*)o)[i] = make_uint2(
        pack_h2(__float2half_rn(v.x * WSCALE), __float2half_rn(v.y * WSCALE)),
        pack_h2(__float2half_rn(v.z * WSCALE), __float2half_rn(v.w * WSCALE)));
}

__global__ void single_strided(const float* __restrict__ src, int stride, int ncols,
                               __half* __restrict__ o, int nrows)
{
    int i = blockIdx.x * blockDim.x + threadIdx.x;
    int per_row = ncols / 4;
    if (i >= nrows * per_row) return;
    int r = i / per_row, c = (i - r * per_row) * 4;
    float4 v = *(const float4*)(src + (size_t)r * stride + c);
    size_t o4 = ((size_t)r * ncols + c) >> 2;
    ((uint2*)o)[o4] = make_uint2(
        pack_h2(__float2half_rn(v.x), __float2half_rn(v.y)),
        pack_h2(__float2half_rn(v.z), __float2half_rn(v.w)));
}

// ---------------------------------------------------------------------------
// RoPE -> single fp16, strided source
// ---------------------------------------------------------------------------
__global__ void rope_single_kernel(const float* __restrict__ X, int stride,
                                   const int* __restrict__ pos_ids, int nheads,
                                   __half* __restrict__ Xo)
{
    int idx = blockIdx.x * blockDim.x + threadIdx.x;
    if (idx >= MTOK * 64) return;
    int i = idx & 63;
    int m = idx >> 6;
    int p = pos_ids[m];

    double inv = exp(-(double)i * 0.14391156831212787);  // ln(10000)/64
    double ang = (double)p * inv;
    double k = rint(ang * 0.15915494309189535);
    float r = (float)(ang - k * 6.283185307179586477);
    float sv, cv;
    sincosf(r, &sv, &cv);

    size_t sbase = (size_t)m * stride + i;
    size_t obase = (size_t)m * (nheads * 128) + i;
#pragma unroll 4
    for (int h = 0; h < nheads; h++) {
        float x1 = X[sbase], x2 = X[sbase + 64];
        Xo[obase]      = __float2half_rn(x1 * cv - x2 * sv);
        Xo[obase + 64] = __float2half_rn(x2 * cv + x1 * sv);
        sbase += 128;
        obase += 128;
    }
}

// ---------------------------------------------------------------------------
// Single-pass fp16 GEMM: C[M,N] = outscale * A16[M,K] @ B16[N,K]^T
// CTA 128x128, BK=32, 256 thr, 8 warps (warp 64x32). 3-stage cp.async.
// ---------------------------------------------------------------------------
#define SROW   40
#define TPART  (128 * SROW * 2)        // 10240 B
#define TSTAGE (2 * TPART)             // 20480 B
#define GEMM_SMEM (3 * TSTAGE)         // 61440 B

__global__ __launch_bounds__(256) void gemm_f16(
    const __half* __restrict__ A, const __half* __restrict__ B,
    float* __restrict__ C, int M, int N, int K, float outscale)
{
    extern __shared__ char smem[];
    const uint32_t sbase = smem_to_u32(smem);

    const int tid  = threadIdx.x;
    const int wid  = tid >> 5;
    const int lane = tid & 31;
    const int wm   = wid >> 2;
    const int wn   = wid & 3;
    const int bm   = blockIdx.y * 128;
    const int bn   = blockIdx.x * 128;
    const int NKT  = K / 32;

    const int cr0 = tid >> 2, cc0 = (tid & 3) * 16;
    const int cr1 = (tid + 256) >> 2;

#define G_ISSUE(kt, buf) do { \
    uint32_t db = sbase + (uint32_t)(buf) * TSTAGE; \
    cp16(db + cr0 * 80 + cc0, \
         A + (size_t)(bm + cr0) * K + (kt) * 32 + (cc0 >> 1)); \
    cp16(db + cr1 * 80 + cc0, \
         A + (size_t)(bm + cr1) * K + (kt) * 32 + (cc0 >> 1)); \
    cp16(db + TPART + cr0 * 80 + cc0, \
         B + (size_t)(bn + cr0) * K + (kt) * 32 + (cc0 >> 1)); \
    cp16(db + TPART + cr1 * 80 + cc0, \
         B + (size_t)(bn + cr1) * K + (kt) * 32 + (cc0 >> 1)); \
} while (0)

    float acc[4][4][4];
#pragma unroll
    for (int mf = 0; mf < 4; mf++)
#pragma unroll
        for (int nf = 0; nf < 4; nf++)
#pragma unroll
            for (int r = 0; r < 4; r++) acc[mf][nf][r] = 0.f;

    G_ISSUE(0, 0); CP_COMMIT();
    G_ISSUE(1, 1); CP_COMMIT();
    G_ISSUE(2, 2); CP_COMMIT();

    const int lr16 = lane & 15;
    const int lh   = lane >> 4;
    const uint32_t a_lane = (uint32_t)((wm * 64 + lr16) * (SROW * 2) + lh * 16);
    const uint32_t b_lane = (uint32_t)((wn * 32 + lr16) * (SROW * 2) + lh * 16);

    for (int kt = 0; kt < NKT; kt++) {
        if (kt + 3 <= NKT)       CP_WAIT(2);
        else if (kt + 2 == NKT)  CP_WAIT(1);
        else                     CP_WAIT(0);
        __syncthreads();

        {
            const uint32_t base = sbase + (uint32_t)(kt % 3) * TSTAGE;
#pragma unroll
            for (int ks = 0; ks < 2; ks++) {
                const uint32_t kb = ks * 32;
                uint32_t ah[4][4], bh[2][4];
#pragma unroll
                for (int mf = 0; mf < 4; mf++)
                    LDMX4(ah[mf], base + a_lane + mf * 16 * (SROW * 2) + kb);
#pragma unroll
                for (int nf2 = 0; nf2 < 2; nf2++)
                    LDMX4(bh[nf2], base + TPART + b_lane + nf2 * 16 * (SROW * 2) + kb);
#pragma unroll
                for (int mf = 0; mf < 4; mf++)
#pragma unroll
                    for (int nf = 0; nf < 4; nf++)
                        MMA_F16(acc[mf][nf], ah[mf],
                                bh[nf >> 1][nf & 1], bh[nf >> 1][(nf & 1) + 2]);
            }
        }
        __syncthreads();
        if (kt + 3 < NKT) { G_ISSUE(kt + 3, kt % 3); CP_COMMIT(); }
    }

    const int erow = bm + wm * 64 + (lane >> 2);
    const int ecol = bn + wn * 32 + (lane & 3) * 2;
#pragma unroll
    for (int mf = 0; mf < 4; mf++)
#pragma unroll
        for (int nf = 0; nf < 4; nf++) {
            float* c = acc[mf][nf];
            size_t ro0 = (size_t)(erow + mf * 16) * N + ecol + nf * 8;
            size_t ro1 = ro0 + 8 * (size_t)N;
            *(float2*)(C + ro0) = make_float2(c[0] * outscale, c[1] * outscale);
            *(float2*)(C + ro1) = make_float2(c[2] * outscale, c[3] * outscale);
        }
#undef G_ISSUE
}

// ---------------------------------------------------------------------------
// Tensor-core flash attention, causal, GQA. 2 MMA passes per tile:
// QK = Q*K (both single fp16); PV = P*V (both single fp16).
// 128 q-rows x 64 kv tiles, 8 warps, K/V double-buffered cp.async.
// q-tile order REVERSED so heaviest CTAs launch first (causal LPT balance).
// smem: Q (128x136) + 2 stages of (K,V 64x136) = 104448 B
// ---------------------------------------------------------------------------
#define FROWB 272
#define FQT   (128 * FROWB)            // 34816
#define FKT   (64 * FROWB)             // 17408
#define FKVST (2 * FKT)                // 34816 per stage
#define FLASH_SMEM (FQT + 2 * FKVST)   // 104448
#define SC_LOG2E 0.12751631762078975f  // (1/sqrt(128)) * log2(e)

__global__ __launch_bounds__(256) void flash_tc(
    const __half* __restrict__ Q16,
    const __half* __restrict__ K16, const __half* __restrict__ V16,
    __half* __restrict__ O)
{
    extern __shared__ char sm[];
    const uint32_t sb  = smem_to_u32(sm);
    const uint32_t sQ  = sb;
    const uint32_t sKV = sb + FQT;

    const int q0  = (gridDim.x - 1 - blockIdx.x) * 128;   // heaviest first
    const int h   = blockIdx.y;
    const int b   = blockIdx.z;
    const int kvh = h >> 2;
    const int tid  = threadIdx.x;
    const int wid  = tid >> 5;
    const int lane = tid & 31;

    const __half* kvp[2] = {K16, V16};

#define KV_ISSUE(kt, buf) do { \
    uint32_t db = sKV + (uint32_t)(buf) * FKVST; \
    size_t gb = (size_t)(b * SS + (kt)) * KVDIM + kvh * HD; \
    _Pragma("unroll") \
    for (int p = 0; p < 2; p++) { \
        const __half* sp = kvp[p]; \
        _Pragma("unroll") \
        for (int j = 0; j < 4; j++) { \
            int i = tid + j * 256; \
            int r = i >> 4, c16 = (i & 15) * 16; \
            cp16(db + p * FKT + r * FROWB + c16, \
                 sp + gb + (size_t)r * KVDIM + (c16 >> 1)); \
        } \
    } \
} while (0)

    for (int i = tid; i < 128 * 16; i += 256) {
        int r = i >> 4, c = i & 15;
        size_t g = (size_t)(b * SS + q0 + r) * QDIM + h * HD + c * 8;
        *(uint4*)(sm + r * FROWB + c * 16) = *(const uint4*)(Q16 + g);
    }

    const int ntiles = q0 / 64 + 2;
    KV_ISSUE(0, 0); CP_COMMIT();
    KV_ISSUE(64, 1); CP_COMMIT();

    const uint32_t a_off  = (uint32_t)((16 * wid + (lane & 7) + 8 * ((lane >> 3) & 1)) * FROWB
                                       + (lane >> 4) * 16);
    const uint32_t vt_off = (uint32_t)(((lane & 7) + 8 * ((lane >> 3) & 1)) * FROWB
                                       + (lane >> 4) * 16);
    const uint32_t b_off  = (uint32_t)(((lane & 7) + 8 * (lane >> 4)) * FROWB
                                       + ((lane >> 3) & 1) * 16);

    float o[16][4];
#pragma unroll
    for (int nf = 0; nf < 16; nf++)
#pragma unroll
        for (int r = 0; r < 4; r++) o[nf][r] = 0.f;
    float mo[2] = {-1e30f, -1e30f};
    float ls[2] = {0.f, 0.f};

    for (int t = 0; t < ntiles; t++) {
        const int kt = t * 64;
        if (t + 1 < ntiles) CP_WAIT(1); else CP_WAIT(0);
        __syncthreads();

        const uint32_t kvb = sKV + (uint32_t)(t & 1) * FKVST;
        const uint32_t cK = kvb, cV = kvb + FKT;

        // ---- S = Q K^T (single pass)
        float s[8][4];
#pragma unroll
        for (int f = 0; f < 8; f++)
#pragma unroll
            for (int r = 0; r < 4; r++) s[f][r] = 0.f;

#pragma unroll
        for (int ks = 0; ks < 8; ks++) {
            uint32_t qq[4];
            LDMX4(qq, sQ + a_off + ks * 32);
#pragma unroll
            for (int nb = 0; nb < 4; nb++) {
                uint32_t kk[4];
                LDMX4(kk, cK + b_off + nb * 16 * FROWB + ks * 32);
                MMA_F16(s[2 * nb],     qq, kk[0], kk[1]);
                MMA_F16(s[2 * nb + 1], qq, kk[2], kk[3]);
            }
        }

#pragma unroll
        for (int f = 0; f < 8; f++)
#pragma unroll
            for (int r = 0; r < 4; r++) s[f][r] *= SC_LOG2E;

        if (t >= ntiles - 2) {
            const int row0 = q0 + 16 * wid + (lane >> 2);
            const int colb = kt + 2 * (lane & 3);
#pragma unroll
            for (int f = 0; f < 8; f++)
#pragma unroll
                for (int r = 0; r < 4; r++) {
                    int col = colb + 8 * f + (r & 1);
                    int row = row0 + 8 * (r >> 1);
                    if (col > row) s[f][r] = -1e30f;
                }
        }

        // ---- online softmax
#pragma unroll
        for (int hh = 0; hh < 2; hh++) {
            float mt = -1e30f;
#pragma unroll
            for (int f = 0; f < 8; f++)
                mt = fmaxf(mt, fmaxf(s[f][2 * hh], s[f][2 * hh + 1]));
            mt = fmaxf(mt, __shfl_xor_sync(0xffffffffu, mt, 1));
            mt = fmaxf(mt, __shfl_xor_sync(0xffffffffu, mt, 2));
            float mn = fmaxf(mo[hh], mt);
            float alpha = exp2f(mo[hh] - mn);
            float rs = 0.f;
#pragma unroll
            for (int f = 0; f < 8; f++) {
                float p0 = exp2f(s[f][2 * hh] - mn);
                float p1 = exp2f(s[f][2 * hh + 1] - mn);
                s[f][2 * hh] = p0;
                s[f][2 * hh + 1] = p1;
                rs += p0 + p1;
            }
            rs += __shfl_xor_sync(0xffffffffu, rs, 1);
            rs += __shfl_xor_sync(0xffffffffu, rs, 2);
            ls[hh] = ls[hh] * alpha + rs;
            mo[hh] = mn;
#pragma unroll
            for (int nf = 0; nf < 16; nf++) {
                o[nf][2 * hh]     *= alpha;
                o[nf][2 * hh + 1] *= alpha;
            }
        }

        // ---- O += P V (single pass)
#pragma unroll
        for (int ks = 0; ks < 4; ks++) {
            uint32_t ph[4];
            ph[0] = pack_h2(__float2half_rn(s[2 * ks][0]),     __float2half_rn(s[2 * ks][1]));
            ph[1] = pack_h2(__float2half_rn(s[2 * ks][2]),     __float2half_rn(s[2 * ks][3]));
            ph[2] = pack_h2(__float2half_rn(s[2 * ks + 1][0]), __float2half_rn(s[2 * ks + 1][1]));
            ph[3] = pack_h2(__float2half_rn(s[2 * ks + 1][2]), __float2half_rn(s[2 * ks + 1][3]));
#pragma unroll
            for (int nb = 0; nb < 8; nb++) {
                uint32_t vv[4];
                LDMX4T(vv, cV + vt_off + ks * 16 * FROWB + nb * 32);
                MMA_F16(o[2 * nb],     ph, vv[0], vv[1]);
                MMA_F16(o[2 * nb + 1], ph, vv[2], vv[3]);
            }
        }

        __syncthreads();
        if (t + 2 < ntiles) { KV_ISSUE(kt + 128, t & 1); CP_COMMIT(); }
    }

    // epilogue: normalize, store single fp16
    float inv0 = 1.f / ls[0];
    float inv1 = 1.f / ls[1];
#pragma unroll
    for (int nf = 0; nf < 16; nf++) {
#pragma unroll
        for (int rp = 0; rp < 2; rp++) {
            float invv = rp ? inv1 : inv0;
            float v0 = o[nf][2 * rp] * invv;
            float v1 = o[nf][2 * rp + 1] * invv;
            uint32_t hv = pack_h2(__float2half_rn(v0), __float2half_rn(v1));
            int row = q0 + 16 * wid + (lane >> 2) + 8 * rp;
            int col = h * HD + 8 * nf + 2 * (lane & 3);
            size_t g = (size_t)(b * SS + row) * QDIM + col;
            *(uint32_t*)(O + g) = hv;
        }
    }
#undef KV_ISSUE
}

// ---------------------------------------------------------------------------
// launcher
// ---------------------------------------------------------------------------
extern "C" void kernel_launch(void* const* d_in, const int* in_sizes, int n_in,
                              void* d_out, int out_size)
{
    const float* hidden = (const float*)d_in[0];
    const float* Wq     = (const float*)d_in[1];
    const float* Wk     = (const float*)d_in[2];
    const float* Wv     = (const float*)d_in[3];
    const float* Wo     = (const float*)d_in[4];
    const int*   pos    = (const int*)d_in[5];
    float* out = (float*)d_out;

    float* Cb;
    cudaGetSymbolAddress((void**)&Cb, g_C);
    __half *H16, *W16, *Wo16, *Q16, *K16, *V16, *O16;
    cudaGetSymbolAddress((void**)&H16, g_H16);
    cudaGetSymbolAddress((void**)&W16, g_W16);
    cudaGetSymbolAddress((void**)&Wo16, g_Wo16);
    cudaGetSymbolAddress((void**)&Q16, g_Q16);
    cudaGetSymbolAddress((void**)&K16, g_K16);
    cudaGetSymbolAddress((void**)&V16, g_V16);
    cudaGetSymbolAddress((void**)&O16, g_O16);

    cudaFuncSetAttribute(gemm_f16,
                         cudaFuncAttributeMaxDynamicSharedMemorySize, GEMM_SMEM);
    cudaFuncSetAttribute(flash_tc,
                         cudaFuncAttributeMaxDynamicSharedMemorySize, FLASH_SMEM);

    // 1. convert: hidden -> fp16; weights -> scaled single fp16 (packed QKV)
    split_single<<<(MTOK * HID / 4 + 255) / 256, 256>>>(hidden, H16, MTOK * HID / 4);
    conv_w<<<(QDIM * HID / 4 + 255) / 256, 256>>>(Wq, W16, QDIM * HID / 4);
    conv_w<<<(KVDIM * HID / 4 + 255) / 256, 256>>>(
        Wk, W16 + (size_t)QDIM * HID, KVDIM * HID / 4);
    conv_w<<<(KVDIM * HID / 4 + 255) / 256, 256>>>(
        Wv, W16 + (size_t)(QDIM + KVDIM) * HID, KVDIM * HID / 4);
    conv_w<<<(HID * QDIM / 4 + 255) / 256, 256>>>(Wo, Wo16, HID * QDIM / 4);

    // 2. fused QKV projection -> fp32 C [MTOK, 3072] (unscale by 1/64)
    gemm_f16<<<dim3(QKVD / 128, MTOK / 128), 256, GEMM_SMEM>>>(
        H16, W16, Cb, MTOK, QKVD, HID, INV_WSCALE);

    // 3. RoPE: Q -> single; K -> single; V -> single
    rope_single_kernel<<<(MTOK * 64) / 256, 256>>>(Cb, QKVD, pos, NH, Q16);
    rope_single_kernel<<<(MTOK * 64) / 256, 256>>>(Cb + QDIM, QKVD, pos, NKV, K16);
    single_strided<<<(MTOK * KVDIM / 4 + 255) / 256, 256>>>(
        Cb + QDIM + KVDIM, QKVD, KVDIM, V16, MTOK);

    // 4. flash attention -> single fp16 O
    flash_tc<<<dim3(SS / 128, NH, BB), 256, FLASH_SMEM>>>(Q16, K16, V16, O16);

    // 5. output projection (unscale by 1/64)
    gemm_f16<<<dim3(HID / 128, MTOK / 128), 256, GEMM_SMEM>>>(
        O16, Wo16, out, MTOK, HID, QDIM, INV_WSCALE);
}

// round 10
// speedup vs baseline: 2.4135x; 1.0255x over previous
#include <cuda_runtime.h>
#include <cuda_fp16.h>
#include <math.h>
#include <stdint.h>

// Problem constants
#define BB   2
#define SS   2048
#define HID  2048
#define NH   16
#define NKV  4
#define HD   128
#define MTOK (BB*SS)          // 4096
#define QDIM (NH*HD)          // 2048
#define KVDIM (NKV*HD)        // 512
#define QKVD (QDIM + 2*KVDIM) // 3072

#define WSCALE    64.0f
#define INV_WSCALE 0.015625f

// ---------------------------------------------------------------------------
// Scratch (device globals; no allocation allowed)
// ---------------------------------------------------------------------------
__device__ __half g_C16[(size_t)MTOK * QKVD];              // fused QKV fp16 (roped in place)
__device__ __half g_H16[(size_t)MTOK * HID];               // hidden fp16
__device__ __half g_W16[(size_t)QKVD * HID];               // packed QKV weights x64
__device__ __half g_Wo16[(size_t)HID * QDIM];              // Wo x64
__device__ __half g_O16[(size_t)MTOK * QDIM];              // attn out fp16

// ---------------------------------------------------------------------------
// helpers
// ---------------------------------------------------------------------------
__device__ __forceinline__ uint32_t smem_to_u32(const void* p) {
    uint32_t a;
    asm("{ .reg .u64 t; cvta.to.shared.u64 t, %1; cvt.u32.u64 %0, t; }"
        : "=r"(a) : "l"(p));
    return a;
}
__device__ __forceinline__ uint32_t pack_h2(__half a, __half b) {
    return (uint32_t)__half_as_ushort(a) | ((uint32_t)__half_as_ushort(b) << 16);
}

#define LDMX4(r, addr) \
    asm volatile("ldmatrix.sync.aligned.m8n8.x4.shared.b16 {%0,%1,%2,%3}, [%4];" \
        : "=r"((r)[0]), "=r"((r)[1]), "=r"((r)[2]), "=r"((r)[3]) : "r"(addr))
#define LDMX4T(r, addr) \
    asm volatile("ldmatrix.sync.aligned.m8n8.x4.trans.shared.b16 {%0,%1,%2,%3}, [%4];" \
        : "=r"((r)[0]), "=r"((r)[1]), "=r"((r)[2]), "=r"((r)[3]) : "r"(addr))
#define MMA_F16(c, a, b0, b1) \
    asm volatile("mma.sync.aligned.m16n8k16.row.col.f32.f16.f16.f32 " \
        "{%0,%1,%2,%3},{%4,%5,%6,%7},{%8,%9},{%0,%1,%2,%3};" \
        : "+f"((c)[0]), "+f"((c)[1]), "+f"((c)[2]), "+f"((c)[3]) \
        : "r"((a)[0]), "r"((a)[1]), "r"((a)[2]), "r"((a)[3]), "r"(b0), "r"(b1))

__device__ __forceinline__ void cp16(uint32_t dst, const void* src) {
    asm volatile("cp.async.cg.shared.global [%0], [%1], 16;" :: "r"(dst), "l"(src));
}
#define CP_COMMIT() asm volatile("cp.async.commit_group;" ::: "memory")
#define CP_WAIT(n)  asm volatile("cp.async.wait_group %0;" :: "n"(n) : "memory")

// ---------------------------------------------------------------------------
// one conversion kernel for all fp32 -> fp16 inputs (region switch)
// regions: hidden(x1) | Wq(x64) | Wk(x64) | Wv(x64) | Wo(x64)
// ---------------------------------------------------------------------------
#define CN0 (MTOK * HID / 4)     // hidden
#define CN1 (QDIM * HID / 4)     // Wq
#define CN2 (KVDIM * HID / 4)    // Wk
#define CN3 (KVDIM * HID / 4)    // Wv
#define CN4 (HID * QDIM / 4)     // Wo
#define CNT (CN0 + CN1 + CN2 + CN3 + CN4)

__global__ void conv_all(const float* __restrict__ hid, const float* __restrict__ wq,
                         const float* __restrict__ wk, const float* __restrict__ wv,
                         const float* __restrict__ wo,
                         __half* __restrict__ H16, __half* __restrict__ W16,
                         __half* __restrict__ Wo16)
{
    int i = blockIdx.x * blockDim.x + threadIdx.x;
    if (i >= CNT) return;
    const float* src;
    __half* dst;
    int j;
    float sc;
    if (i < CN0)                 { src = hid; dst = H16; j = i; sc = 1.f; }
    else if (i < CN0 + CN1)      { src = wq;  dst = W16; j = i - CN0; sc = WSCALE; }
    else if (i < CN0 + CN1 + CN2){ src = wk;  dst = W16 + (size_t)QDIM * HID;
                                   j = i - CN0 - CN1; sc = WSCALE; }
    else if (i < CN0 + CN1 + CN2 + CN3)
                                 { src = wv;  dst = W16 + (size_t)(QDIM + KVDIM) * HID;
                                   j = i - CN0 - CN1 - CN2; sc = WSCALE; }
    else                         { src = wo;  dst = Wo16;
                                   j = i - CN0 - CN1 - CN2 - CN3; sc = WSCALE; }
    float4 v = ((const float4*)src)[j];
    ((uint2*)dst)[j] = make_uint2(
        pack_h2(__float2half_rn(v.x * sc), __float2half_rn(v.y * sc)),
        pack_h2(__float2half_rn(v.z * sc), __float2half_rn(v.w * sc)));
}

// ---------------------------------------------------------------------------
// RoPE in-place on fp16 C16: Q region (16 heads) + K region (4 heads), one launch
// ---------------------------------------------------------------------------
__global__ void rope_all(__half* __restrict__ C, const int* __restrict__ pos_ids)
{
    int idx = blockIdx.x * blockDim.x + threadIdx.x;
    if (idx >= 2 * MTOK * 64) return;
    int nheads, colbase;
    if (idx < MTOK * 64) { nheads = NH;  colbase = 0; }
    else                 { nheads = NKV; colbase = QDIM; idx -= MTOK * 64; }
    int i = idx & 63;
    int m = idx >> 6;
    int p = pos_ids[m];

    double invf = exp(-(double)i * 0.14391156831212787);  // ln(10000)/64
    double ang = (double)p * invf;
    double k = rint(ang * 0.15915494309189535);
    float r = (float)(ang - k * 6.283185307179586477);
    float sv, cv;
    sincosf(r, &sv, &cv);

    size_t base = (size_t)m * QKVD + colbase + i;
#pragma unroll 4
    for (int h = 0; h < nheads; h++) {
        float x1 = __half2float(C[base]);
        float x2 = __half2float(C[base + 64]);
        C[base]      = __float2half_rn(x1 * cv - x2 * sv);
        C[base + 64] = __float2half_rn(x2 * cv + x1 * sv);
        base += 128;
    }
}

// ---------------------------------------------------------------------------
// GEMM core (shared by fp16-out and fp32-out variants)
// CTA 128x128, BK=32, 256 thr, 8 warps (warp 64x32). 3-stage cp.async.
// ---------------------------------------------------------------------------
#define SROW   40
#define TPART  (128 * SROW * 2)        // 10240 B
#define TSTAGE (2 * TPART)             // 20480 B
#define GEMM_SMEM (3 * TSTAGE)         // 61440 B

#define GEMM_BODY(EPILOGUE) \
    extern __shared__ char smem[]; \
    const uint32_t sbase = smem_to_u32(smem); \
    const int tid  = threadIdx.x; \
    const int wid  = tid >> 5; \
    const int lane = tid & 31; \
    const int wm   = wid >> 2; \
    const int wn   = wid & 3; \
    const int bm   = blockIdx.y * 128; \
    const int bn   = blockIdx.x * 128; \
    const int NKT  = K / 32; \
    const int cr0 = tid >> 2, cc0 = (tid & 3) * 16; \
    const int cr1 = (tid + 256) >> 2; \
    float acc[4][4][4]; \
    _Pragma("unroll") \
    for (int mf = 0; mf < 4; mf++) \
        _Pragma("unroll") \
        for (int nf = 0; nf < 4; nf++) \
            _Pragma("unroll") \
            for (int r = 0; r < 4; r++) acc[mf][nf][r] = 0.f; \
    G_ISSUE(0, 0); CP_COMMIT(); \
    G_ISSUE(1, 1); CP_COMMIT(); \
    G_ISSUE(2, 2); CP_COMMIT(); \
    const int lr16 = lane & 15; \
    const int lh   = lane >> 4; \
    const uint32_t a_lane = (uint32_t)((wm * 64 + lr16) * (SROW * 2) + lh * 16); \
    const uint32_t b_lane = (uint32_t)((wn * 32 + lr16) * (SROW * 2) + lh * 16); \
    for (int kt = 0; kt < NKT; kt++) { \
        if (kt + 3 <= NKT)       CP_WAIT(2); \
        else if (kt + 2 == NKT)  CP_WAIT(1); \
        else                     CP_WAIT(0); \
        __syncthreads(); \
        { \
            const uint32_t base = sbase + (uint32_t)(kt % 3) * TSTAGE; \
            _Pragma("unroll") \
            for (int ks = 0; ks < 2; ks++) { \
                const uint32_t kb = ks * 32; \
                uint32_t ah[4][4], bh[2][4]; \
                _Pragma("unroll") \
                for (int mf = 0; mf < 4; mf++) \
                    LDMX4(ah[mf], base + a_lane + mf * 16 * (SROW * 2) + kb); \
                _Pragma("unroll") \
                for (int nf2 = 0; nf2 < 2; nf2++) \
                    LDMX4(bh[nf2], base + TPART + b_lane + nf2 * 16 * (SROW * 2) + kb); \
                _Pragma("unroll") \
                for (int mf = 0; mf < 4; mf++) \
                    _Pragma("unroll") \
                    for (int nf = 0; nf < 4; nf++) \
                        MMA_F16(acc[mf][nf], ah[mf], \
                                bh[nf >> 1][nf & 1], bh[nf >> 1][(nf & 1) + 2]); \
            } \
        } \
        __syncthreads(); \
        if (kt + 3 < NKT) { G_ISSUE(kt + 3, kt % 3); CP_COMMIT(); } \
    } \
    const int erow = bm + wm * 64 + (lane >> 2); \
    const int ecol = bn + wn * 32 + (lane & 3) * 2; \
    EPILOGUE

#define G_ISSUE(kt, buf) do { \
    uint32_t db = sbase + (uint32_t)(buf) * TSTAGE; \
    cp16(db + cr0 * 80 + cc0, \
         A + (size_t)(bm + cr0) * K + (kt) * 32 + (cc0 >> 1)); \
    cp16(db + cr1 * 80 + cc0, \
         A + (size_t)(bm + cr1) * K + (kt) * 32 + (cc0 >> 1)); \
    cp16(db + TPART + cr0 * 80 + cc0, \
         B + (size_t)(bn + cr0) * K + (kt) * 32 + (cc0 >> 1)); \
    cp16(db + TPART + cr1 * 80 + cc0, \
         B + (size_t)(bn + cr1) * K + (kt) * 32 + (cc0 >> 1)); \
} while (0)

// fp16-output GEMM (QKV projection)
__global__ __launch_bounds__(256) void gemm_f16h(
    const __half* __restrict__ A, const __half* __restrict__ B,
    __half* __restrict__ C, int M, int N, int K, float outscale)
{
    GEMM_BODY(
#pragma unroll
        for (int mf = 0; mf < 4; mf++)
#pragma unroll
            for (int nf = 0; nf < 4; nf++) {
                float* c = acc[mf][nf];
                size_t ro0 = (size_t)(erow + mf * 16) * N + ecol + nf * 8;
                size_t ro1 = ro0 + 8 * (size_t)N;
                *(uint32_t*)(C + ro0) = pack_h2(
                    __float2half_rn(c[0] * outscale), __float2half_rn(c[1] * outscale));
                *(uint32_t*)(C + ro1) = pack_h2(
                    __float2half_rn(c[2] * outscale), __float2half_rn(c[3] * outscale));
            }
    )
}

// fp32-output GEMM (output projection)
__global__ __launch_bounds__(256) void gemm_f16(
    const __half* __restrict__ A, const __half* __restrict__ B,
    float* __restrict__ C, int M, int N, int K, float outscale)
{
    GEMM_BODY(
#pragma unroll
        for (int mf = 0; mf < 4; mf++)
#pragma unroll
            for (int nf = 0; nf < 4; nf++) {
                float* c = acc[mf][nf];
                size_t ro0 = (size_t)(erow + mf * 16) * N + ecol + nf * 8;
                size_t ro1 = ro0 + 8 * (size_t)N;
                *(float2*)(C + ro0) = make_float2(c[0] * outscale, c[1] * outscale);
                *(float2*)(C + ro1) = make_float2(c[2] * outscale, c[3] * outscale);
            }
    )
}
#undef G_ISSUE

// ---------------------------------------------------------------------------
// Tensor-core flash attention, causal, GQA; reads Q/K/V straight from C16
// (row stride QKVD). 2 MMA passes per tile (QK, PV), both single fp16.
// 128 q-rows x 64 kv tiles, 8 warps, K/V double-buffered cp.async.
// q-tile order reversed (heaviest CTAs first).
// ---------------------------------------------------------------------------
#define FROWB 272
#define FQT   (128 * FROWB)            // 34816
#define FKT   (64 * FROWB)             // 17408
#define FKVST (2 * FKT)                // 34816 per stage
#define FLASH_SMEM (FQT + 2 * FKVST)   // 104448
#define SC_LOG2E 0.12751631762078975f  // (1/sqrt(128)) * log2(e)

__global__ __launch_bounds__(256) void flash_tc(
    const __half* __restrict__ C16, __half* __restrict__ O)
{
    extern __shared__ char sm[];
    const uint32_t sb  = smem_to_u32(sm);
    const uint32_t sQ  = sb;
    const uint32_t sKV = sb + FQT;

    const int q0  = (gridDim.x - 1 - blockIdx.x) * 128;   // heaviest first
    const int h   = blockIdx.y;
    const int b   = blockIdx.z;
    const int kvh = h >> 2;
    const int tid  = threadIdx.x;
    const int wid  = tid >> 5;
    const int lane = tid & 31;

    // K at col QDIM + kvh*HD, V at col QDIM + KVDIM + kvh*HD, row stride QKVD
    const __half* Kp = C16 + QDIM + kvh * HD;
    const __half* Vp = C16 + QDIM + KVDIM + kvh * HD;

#define KV_ISSUE(kt, buf) do { \
    uint32_t db = sKV + (uint32_t)(buf) * FKVST; \
    size_t gb = (size_t)(b * SS + (kt)) * QKVD; \
    _Pragma("unroll") \
    for (int j = 0; j < 4; j++) { \
        int i = tid + j * 256; \
        int r = i >> 4, c16v = (i & 15) * 16; \
        size_t roff = gb + (size_t)r * QKVD + (c16v >> 1); \
        cp16(db + r * FROWB + c16v, Kp + roff); \
        cp16(db + FKT + r * FROWB + c16v, Vp + roff); \
    } \
} while (0)

    for (int i = tid; i < 128 * 16; i += 256) {
        int r = i >> 4, c = i & 15;
        size_t g = (size_t)(b * SS + q0 + r) * QKVD + h * HD + c * 8;
        *(uint4*)(sm + r * FROWB + c * 16) = *(const uint4*)(C16 + g);
    }

    const int ntiles = q0 / 64 + 2;
    KV_ISSUE(0, 0); CP_COMMIT();
    KV_ISSUE(64, 1); CP_COMMIT();

    const uint32_t a_off  = (uint32_t)((16 * wid + (lane & 7) + 8 * ((lane >> 3) & 1)) * FROWB
                                       + (lane >> 4) * 16);
    const uint32_t vt_off = (uint32_t)(((lane & 7) + 8 * ((lane >> 3) & 1)) * FROWB
                                       + (lane >> 4) * 16);
    const uint32_t b_off  = (uint32_t)(((lane & 7) + 8 * (lane >> 4)) * FROWB
                                       + ((lane >> 3) & 1) * 16);

    float o[16][4];
#pragma unroll
    for (int nf = 0; nf < 16; nf++)
#pragma unroll
        for (int r = 0; r < 4; r++) o[nf][r] = 0.f;
    float mo[2] = {-1e30f, -1e30f};
    float ls[2] = {0.f, 0.f};

    for (int t = 0; t < ntiles; t++) {
        const int kt = t * 64;
        if (t + 1 < ntiles) CP_WAIT(1); else CP_WAIT(0);
        __syncthreads();

        const uint32_t kvb = sKV + (uint32_t)(t & 1) * FKVST;
        const uint32_t cK = kvb, cV = kvb + FKT;

        // ---- S = Q K^T (single pass)
        float s[8][4];
#pragma unroll
        for (int f = 0; f < 8; f++)
#pragma unroll
            for (int r = 0; r < 4; r++) s[f][r] = 0.f;

#pragma unroll
        for (int ks = 0; ks < 8; ks++) {
            uint32_t qq[4];
            LDMX4(qq, sQ + a_off + ks * 32);
#pragma unroll
            for (int nb = 0; nb < 4; nb++) {
                uint32_t kk[4];
                LDMX4(kk, cK + b_off + nb * 16 * FROWB + ks * 32);
                MMA_F16(s[2 * nb],     qq, kk[0], kk[1]);
                MMA_F16(s[2 * nb + 1], qq, kk[2], kk[3]);
            }
        }

#pragma unroll
        for (int f = 0; f < 8; f++)
#pragma unroll
            for (int r = 0; r < 4; r++) s[f][r] *= SC_LOG2E;

        if (t >= ntiles - 2) {
            const int row0 = q0 + 16 * wid + (lane >> 2);
            const int colb = kt + 2 * (lane & 3);
#pragma unroll
            for (int f = 0; f < 8; f++)
#pragma unroll
                for (int r = 0; r < 4; r++) {
                    int col = colb + 8 * f + (r & 1);
                    int row = row0 + 8 * (r >> 1);
                    if (col > row) s[f][r] = -1e30f;
                }
        }

        // ---- online softmax
#pragma unroll
        for (int hh = 0; hh < 2; hh++) {
            float mt = -1e30f;
#pragma unroll
            for (int f = 0; f < 8; f++)
                mt = fmaxf(mt, fmaxf(s[f][2 * hh], s[f][2 * hh + 1]));
            mt = fmaxf(mt, __shfl_xor_sync(0xffffffffu, mt, 1));
            mt = fmaxf(mt, __shfl_xor_sync(0xffffffffu, mt, 2));
            float mn = fmaxf(mo[hh], mt);
            float alpha = exp2f(mo[hh] - mn);
            float rs = 0.f;
#pragma unroll
            for (int f = 0; f < 8; f++) {
                float p0 = exp2f(s[f][2 * hh] - mn);
                float p1 = exp2f(s[f][2 * hh + 1] - mn);
                s[f][2 * hh] = p0;
                s[f][2 * hh + 1] = p1;
                rs += p0 + p1;
            }
            rs += __shfl_xor_sync(0xffffffffu, rs, 1);
            rs += __shfl_xor_sync(0xffffffffu, rs, 2);
            ls[hh] = ls[hh] * alpha + rs;
            mo[hh] = mn;
#pragma unroll
            for (int nf = 0; nf < 16; nf++) {
                o[nf][2 * hh]     *= alpha;
                o[nf][2 * hh + 1] *= alpha;
            }
        }

        // ---- O += P V (single pass)
#pragma unroll
        for (int ks = 0; ks < 4; ks++) {
            uint32_t ph[4];
            ph[0] = pack_h2(__float2half_rn(s[2 * ks][0]),     __float2half_rn(s[2 * ks][1]));
            ph[1] = pack_h2(__float2half_rn(s[2 * ks][2]),     __float2half_rn(s[2 * ks][3]));
            ph[2] = pack_h2(__float2half_rn(s[2 * ks + 1][0]), __float2half_rn(s[2 * ks + 1][1]));
            ph[3] = pack_h2(__float2half_rn(s[2 * ks + 1][2]), __float2half_rn(s[2 * ks + 1][3]));
#pragma unroll
            for (int nb = 0; nb < 8; nb++) {
                uint32_t vv[4];
                LDMX4T(vv, cV + vt_off + ks * 16 * FROWB + nb * 32);
                MMA_F16(o[2 * nb],     ph, vv[0], vv[1]);
                MMA_F16(o[2 * nb + 1], ph, vv[2], vv[3]);
            }
        }

        __syncthreads();
        if (t + 2 < ntiles) { KV_ISSUE(kt + 128, t & 1); CP_COMMIT(); }
    }

    // epilogue: normalize, store single fp16
    float inv0 = 1.f / ls[0];
    float inv1 = 1.f / ls[1];
#pragma unroll
    for (int nf = 0; nf < 16; nf++) {
#pragma unroll
        for (int rp = 0; rp < 2; rp++) {
            float invv = rp ? inv1 : inv0;
            float v0 = o[nf][2 * rp] * invv;
            float v1 = o[nf][2 * rp + 1] * invv;
            uint32_t hv = pack_h2(__float2half_rn(v0), __float2half_rn(v1));
            int row = q0 + 16 * wid + (lane >> 2) + 8 * rp;
            int col = h * HD + 8 * nf + 2 * (lane & 3);
            size_t g = (size_t)(b * SS + row) * QDIM + col;
            *(uint32_t*)(O + g) = hv;
        }
    }
#undef KV_ISSUE
}

// ---------------------------------------------------------------------------
// launcher
// ---------------------------------------------------------------------------
extern "C" void kernel_launch(void* const* d_in, const int* in_sizes, int n_in,
                              void* d_out, int out_size)
{
    const float* hidden = (const float*)d_in[0];
    const float* Wq     = (const float*)d_in[1];
    const float* Wk     = (const float*)d_in[2];
    const float* Wv     = (const float*)d_in[3];
    const float* Wo     = (const float*)d_in[4];
    const int*   pos    = (const int*)d_in[5];
    float* out = (float*)d_out;

    __half *C16, *H16, *W16, *Wo16, *O16;
    cudaGetSymbolAddress((void**)&C16, g_C16);
    cudaGetSymbolAddress((void**)&H16, g_H16);
    cudaGetSymbolAddress((void**)&W16, g_W16);
    cudaGetSymbolAddress((void**)&Wo16, g_Wo16);
    cudaGetSymbolAddress((void**)&O16, g_O16);

    cudaFuncSetAttribute(gemm_f16h,
                         cudaFuncAttributeMaxDynamicSharedMemorySize, GEMM_SMEM);
    cudaFuncSetAttribute(gemm_f16,
                         cudaFuncAttributeMaxDynamicSharedMemorySize, GEMM_SMEM);
    cudaFuncSetAttribute(flash_tc,
                         cudaFuncAttributeMaxDynamicSharedMemorySize, FLASH_SMEM);

    // 1. one conversion kernel for everything
    conv_all<<<(CNT + 255) / 256, 256>>>(hidden, Wq, Wk, Wv, Wo, H16, W16, Wo16);

    // 2. fused QKV projection -> fp16 C16 [MTOK, 3072] (unscale by 1/64)
    gemm_f16h<<<dim3(QKVD / 128, MTOK / 128), 256, GEMM_SMEM>>>(
        H16, W16, C16, MTOK, QKVD, HID, INV_WSCALE);

    // 3. RoPE in place on C16 (Q and K regions, one launch)
    rope_all<<<(2 * MTOK * 64 + 255) / 256, 256>>>(C16, pos);

    // 4. flash attention (reads Q/K/V straight from C16) -> fp16 O
    flash_tc<<<dim3(SS / 128, NH, BB), 256, FLASH_SMEM>>>(C16, O16);

    // 5. output projection (unscale by 1/64)
    gemm_f16<<<dim3(HID / 128, MTOK / 128), 256, GEMM_SMEM>>>(
        O16, Wo16, out, MTOK, HID, QDIM, INV_WSCALE);
}

// round 11
// speedup vs baseline: 2.5826x; 1.0701x over previous
#include <cuda_runtime.h>
#include <cuda_fp16.h>
#include <math.h>
#include <stdint.h>

// Problem constants
#define BB   2
#define SS   2048
#define HID  2048
#define NH   16
#define NKV  4
#define HD   128
#define MTOK (BB*SS)          // 4096
#define QDIM (NH*HD)          // 2048
#define KVDIM (NKV*HD)        // 512
#define QKVD (QDIM + 2*KVDIM) // 3072

#define WSCALE    64.0f
#define INV_WSCALE 0.015625f

// ---------------------------------------------------------------------------
// Scratch (device globals; no allocation allowed)
// ---------------------------------------------------------------------------
__device__ __half g_C16[(size_t)MTOK * QKVD];              // fused QKV fp16 (roped in place)
__device__ __half g_H16[(size_t)MTOK * HID];               // hidden fp16
__device__ __half g_W16[(size_t)QKVD * HID];               // packed QKV weights x64
__device__ __half g_Wo16[(size_t)HID * QDIM];              // Wo x64
__device__ __half g_O16[(size_t)MTOK * QDIM];              // attn out fp16

// ---------------------------------------------------------------------------
// helpers
// ---------------------------------------------------------------------------
__device__ __forceinline__ uint32_t smem_to_u32(const void* p) {
    uint32_t a;
    asm("{ .reg .u64 t; cvta.to.shared.u64 t, %1; cvt.u32.u64 %0, t; }"
        : "=r"(a) : "l"(p));
    return a;
}
__device__ __forceinline__ uint32_t pack_h2(__half a, __half b) {
    return (uint32_t)__half_as_ushort(a) | ((uint32_t)__half_as_ushort(b) << 16);
}

#define LDMX4(r, addr) \
    asm volatile("ldmatrix.sync.aligned.m8n8.x4.shared.b16 {%0,%1,%2,%3}, [%4];" \
        : "=r"((r)[0]), "=r"((r)[1]), "=r"((r)[2]), "=r"((r)[3]) : "r"(addr))
#define LDMX4T(r, addr) \
    asm volatile("ldmatrix.sync.aligned.m8n8.x4.trans.shared.b16 {%0,%1,%2,%3}, [%4];" \
        : "=r"((r)[0]), "=r"((r)[1]), "=r"((r)[2]), "=r"((r)[3]) : "r"(addr))
#define MMA_F16(c, a, b0, b1) \
    asm volatile("mma.sync.aligned.m16n8k16.row.col.f32.f16.f16.f32 " \
        "{%0,%1,%2,%3},{%4,%5,%6,%7},{%8,%9},{%0,%1,%2,%3};" \
        : "+f"((c)[0]), "+f"((c)[1]), "+f"((c)[2]), "+f"((c)[3]) \
        : "r"((a)[0]), "r"((a)[1]), "r"((a)[2]), "r"((a)[3]), "r"(b0), "r"(b1))

__device__ __forceinline__ void cp16(uint32_t dst, const void* src) {
    asm volatile("cp.async.cg.shared.global [%0], [%1], 16;" :: "r"(dst), "l"(src));
}
#define CP_COMMIT() asm volatile("cp.async.commit_group;" ::: "memory")
#define CP_WAIT(n)  asm volatile("cp.async.wait_group %0;" :: "n"(n) : "memory")

// ---------------------------------------------------------------------------
// one conversion kernel for all fp32 -> fp16 inputs (region switch)
// ---------------------------------------------------------------------------
#define CN0 (MTOK * HID / 4)     // hidden
#define CN1 (QDIM * HID / 4)     // Wq
#define CN2 (KVDIM * HID / 4)    // Wk
#define CN3 (KVDIM * HID / 4)    // Wv
#define CN4 (HID * QDIM / 4)     // Wo
#define CNT (CN0 + CN1 + CN2 + CN3 + CN4)

__global__ void conv_all(const float* __restrict__ hid, const float* __restrict__ wq,
                         const float* __restrict__ wk, const float* __restrict__ wv,
                         const float* __restrict__ wo,
                         __half* __restrict__ H16, __half* __restrict__ W16,
                         __half* __restrict__ Wo16)
{
    int i = blockIdx.x * blockDim.x + threadIdx.x;
    if (i >= CNT) return;
    const float* src;
    __half* dst;
    int j;
    float sc;
    if (i < CN0)                 { src = hid; dst = H16; j = i; sc = 1.f; }
    else if (i < CN0 + CN1)      { src = wq;  dst = W16; j = i - CN0; sc = WSCALE; }
    else if (i < CN0 + CN1 + CN2){ src = wk;  dst = W16 + (size_t)QDIM * HID;
                                   j = i - CN0 - CN1; sc = WSCALE; }
    else if (i < CN0 + CN1 + CN2 + CN3)
                                 { src = wv;  dst = W16 + (size_t)(QDIM + KVDIM) * HID;
                                   j = i - CN0 - CN1 - CN2; sc = WSCALE; }
    else                         { src = wo;  dst = Wo16;
                                   j = i - CN0 - CN1 - CN2 - CN3; sc = WSCALE; }
    float4 v = ((const float4*)src)[j];
    ((uint2*)dst)[j] = make_uint2(
        pack_h2(__float2half_rn(v.x * sc), __float2half_rn(v.y * sc)),
        pack_h2(__float2half_rn(v.z * sc), __float2half_rn(v.w * sc)));
}

// ---------------------------------------------------------------------------
// RoPE in-place on fp16 C16: Q region (16 heads) + K region (4 heads)
// ---------------------------------------------------------------------------
__global__ void rope_all(__half* __restrict__ C, const int* __restrict__ pos_ids)
{
    int idx = blockIdx.x * blockDim.x + threadIdx.x;
    if (idx >= 2 * MTOK * 64) return;
    int nheads, colbase;
    if (idx < MTOK * 64) { nheads = NH;  colbase = 0; }
    else                 { nheads = NKV; colbase = QDIM; idx -= MTOK * 64; }
    int i = idx & 63;
    int m = idx >> 6;
    int p = pos_ids[m];

    double invf = exp(-(double)i * 0.14391156831212787);  // ln(10000)/64
    double ang = (double)p * invf;
    double k = rint(ang * 0.15915494309189535);
    float r = (float)(ang - k * 6.283185307179586477);
    float sv, cv;
    sincosf(r, &sv, &cv);

    size_t base = (size_t)m * QKVD + colbase + i;
#pragma unroll 4
    for (int h = 0; h < nheads; h++) {
        float x1 = __half2float(C[base]);
        float x2 = __half2float(C[base + 64]);
        C[base]      = __float2half_rn(x1 * cv - x2 * sv);
        C[base + 64] = __float2half_rn(x2 * cv + x1 * sv);
        base += 128;
    }
}

// ---------------------------------------------------------------------------
// GEMM core (shared by fp16-out and fp32-out variants)
// CTA 128x128, BK=32, 256 thr, 8 warps (warp 64x32). 3-stage cp.async.
// ---------------------------------------------------------------------------
#define SROW   40
#define TPART  (128 * SROW * 2)        // 10240 B
#define TSTAGE (2 * TPART)             // 20480 B
#define GEMM_SMEM (3 * TSTAGE)         // 61440 B

#define GEMM_BODY(EPILOGUE) \
    extern __shared__ char smem[]; \
    const uint32_t sbase = smem_to_u32(smem); \
    const int tid  = threadIdx.x; \
    const int wid  = tid >> 5; \
    const int lane = tid & 31; \
    const int wm   = wid >> 2; \
    const int wn   = wid & 3; \
    const int bm   = blockIdx.y * 128; \
    const int bn   = blockIdx.x * 128; \
    const int NKT  = K / 32; \
    const int cr0 = tid >> 2, cc0 = (tid & 3) * 16; \
    const int cr1 = (tid + 256) >> 2; \
    float acc[4][4][4]; \
    _Pragma("unroll") \
    for (int mf = 0; mf < 4; mf++) \
        _Pragma("unroll") \
        for (int nf = 0; nf < 4; nf++) \
            _Pragma("unroll") \
            for (int r = 0; r < 4; r++) acc[mf][nf][r] = 0.f; \
    G_ISSUE(0, 0); CP_COMMIT(); \
    G_ISSUE(1, 1); CP_COMMIT(); \
    G_ISSUE(2, 2); CP_COMMIT(); \
    const int lr16 = lane & 15; \
    const int lh   = lane >> 4; \
    const uint32_t a_lane = (uint32_t)((wm * 64 + lr16) * (SROW * 2) + lh * 16); \
    const uint32_t b_lane = (uint32_t)((wn * 32 + lr16) * (SROW * 2) + lh * 16); \
    for (int kt = 0; kt < NKT; kt++) { \
        if (kt + 3 <= NKT)       CP_WAIT(2); \
        else if (kt + 2 == NKT)  CP_WAIT(1); \
        else                     CP_WAIT(0); \
        __syncthreads(); \
        { \
            const uint32_t base = sbase + (uint32_t)(kt % 3) * TSTAGE; \
            _Pragma("unroll") \
            for (int ks = 0; ks < 2; ks++) { \
                const uint32_t kb = ks * 32; \
                uint32_t ah[4][4], bh[2][4]; \
                _Pragma("unroll") \
                for (int mf = 0; mf < 4; mf++) \
                    LDMX4(ah[mf], base + a_lane + mf * 16 * (SROW * 2) + kb); \
                _Pragma("unroll") \
                for (int nf2 = 0; nf2 < 2; nf2++) \
                    LDMX4(bh[nf2], base + TPART + b_lane + nf2 * 16 * (SROW * 2) + kb); \
                _Pragma("unroll") \
                for (int mf = 0; mf < 4; mf++) \
                    _Pragma("unroll") \
                    for (int nf = 0; nf < 4; nf++) \
                        MMA_F16(acc[mf][nf], ah[mf], \
                                bh[nf >> 1][nf & 1], bh[nf >> 1][(nf & 1) + 2]); \
            } \
        } \
        __syncthreads(); \
        if (kt + 3 < NKT) { G_ISSUE(kt + 3, kt % 3); CP_COMMIT(); } \
    } \
    const int erow = bm + wm * 64 + (lane >> 2); \
    const int ecol = bn + wn * 32 + (lane & 3) * 2; \
    EPILOGUE

#define G_ISSUE(kt, buf) do { \
    uint32_t db = sbase + (uint32_t)(buf) * TSTAGE; \
    cp16(db + cr0 * 80 + cc0, \
         A + (size_t)(bm + cr0) * K + (kt) * 32 + (cc0 >> 1)); \
    cp16(db + cr1 * 80 + cc0, \
         A + (size_t)(bm + cr1) * K + (kt) * 32 + (cc0 >> 1)); \
    cp16(db + TPART + cr0 * 80 + cc0, \
         B + (size_t)(bn + cr0) * K + (kt) * 32 + (cc0 >> 1)); \
    cp16(db + TPART + cr1 * 80 + cc0, \
         B + (size_t)(bn + cr1) * K + (kt) * 32 + (cc0 >> 1)); \
} while (0)

// fp16-output GEMM (QKV projection)
__global__ __launch_bounds__(256, 2) void gemm_f16h(
    const __half* __restrict__ A, const __half* __restrict__ B,
    __half* __restrict__ C, int M, int N, int K, float outscale)
{
    GEMM_BODY(
#pragma unroll
        for (int mf = 0; mf < 4; mf++)
#pragma unroll
            for (int nf = 0; nf < 4; nf++) {
                float* c = acc[mf][nf];
                size_t ro0 = (size_t)(erow + mf * 16) * N + ecol + nf * 8;
                size_t ro1 = ro0 + 8 * (size_t)N;
                *(uint32_t*)(C + ro0) = pack_h2(
                    __float2half_rn(c[0] * outscale), __float2half_rn(c[1] * outscale));
                *(uint32_t*)(C + ro1) = pack_h2(
                    __float2half_rn(c[2] * outscale), __float2half_rn(c[3] * outscale));
            }
    )
}

// fp32-output GEMM (output projection)
__global__ __launch_bounds__(256, 2) void gemm_f16(
    const __half* __restrict__ A, const __half* __restrict__ B,
    float* __restrict__ C, int M, int N, int K, float outscale)
{
    GEMM_BODY(
#pragma unroll
        for (int mf = 0; mf < 4; mf++)
#pragma unroll
            for (int nf = 0; nf < 4; nf++) {
                float* c = acc[mf][nf];
                size_t ro0 = (size_t)(erow + mf * 16) * N + ecol + nf * 8;
                size_t ro1 = ro0 + 8 * (size_t)N;
                *(float2*)(C + ro0) = make_float2(c[0] * outscale, c[1] * outscale);
                *(float2*)(C + ro1) = make_float2(c[2] * outscale, c[3] * outscale);
            }
    )
}
#undef G_ISSUE

// ---------------------------------------------------------------------------
// Tensor-core flash attention, causal, GQA; reads Q/K/V straight from C16
// (row stride QKVD). 2 MMA passes per tile (QK, PV), both single fp16.
// 128 q-rows x 64 kv tiles, 8 warps, K/V double-buffered cp.async.
// __launch_bounds__(256,2): cap regs at 128 so TWO CTAs fit per SM
// (129 regs previously left occupancy at 1 CTA -> tensor pipe 30%).
// ---------------------------------------------------------------------------
#define FROWB 272
#define FQT   (128 * FROWB)            // 34816
#define FKT   (64 * FROWB)             // 17408
#define FKVST (2 * FKT)                // 34816 per stage
#define FLASH_SMEM (FQT + 2 * FKVST)   // 104448
#define SC_LOG2E 0.12751631762078975f  // (1/sqrt(128)) * log2(e)

__global__ __launch_bounds__(256, 2) void flash_tc(
    const __half* __restrict__ C16, __half* __restrict__ O)
{
    extern __shared__ char sm[];
    const uint32_t sb  = smem_to_u32(sm);
    const uint32_t sQ  = sb;
    const uint32_t sKV = sb + FQT;

    const int q0  = (gridDim.x - 1 - blockIdx.x) * 128;   // heaviest first
    const int h   = blockIdx.y;
    const int b   = blockIdx.z;
    const int kvh = h >> 2;
    const int tid  = threadIdx.x;
    const int wid  = tid >> 5;
    const int lane = tid & 31;

    const __half* Kp = C16 + QDIM + kvh * HD;
    const __half* Vp = C16 + QDIM + KVDIM + kvh * HD;

#define KV_ISSUE(kt, buf) do { \
    uint32_t db = sKV + (uint32_t)(buf) * FKVST; \
    size_t gb = (size_t)(b * SS + (kt)) * QKVD; \
    _Pragma("unroll") \
    for (int j = 0; j < 4; j++) { \
        int i = tid + j * 256; \
        int r = i >> 4, c16v = (i & 15) * 16; \
        size_t roff = gb + (size_t)r * QKVD + (c16v >> 1); \
        cp16(db + r * FROWB + c16v, Kp + roff); \
        cp16(db + FKT + r * FROWB + c16v, Vp + roff); \
    } \
} while (0)

    for (int i = tid; i < 128 * 16; i += 256) {
        int r = i >> 4, c = i & 15;
        size_t g = (size_t)(b * SS + q0 + r) * QKVD + h * HD + c * 8;
        *(uint4*)(sm + r * FROWB + c * 16) = *(const uint4*)(C16 + g);
    }

    const int ntiles = q0 / 64 + 2;
    KV_ISSUE(0, 0); CP_COMMIT();
    KV_ISSUE(64, 1); CP_COMMIT();

    const uint32_t a_off  = (uint32_t)((16 * wid + (lane & 7) + 8 * ((lane >> 3) & 1)) * FROWB
                                       + (lane >> 4) * 16);
    const uint32_t vt_off = (uint32_t)(((lane & 7) + 8 * ((lane >> 3) & 1)) * FROWB
                                       + (lane >> 4) * 16);
    const uint32_t b_off  = (uint32_t)(((lane & 7) + 8 * (lane >> 4)) * FROWB
                                       + ((lane >> 3) & 1) * 16);

    float o[16][4];
#pragma unroll
    for (int nf = 0; nf < 16; nf++)
#pragma unroll
        for (int r = 0; r < 4; r++) o[nf][r] = 0.f;
    float mo[2] = {-1e30f, -1e30f};
    float ls[2] = {0.f, 0.f};

    for (int t = 0; t < ntiles; t++) {
        const int kt = t * 64;
        if (t + 1 < ntiles) CP_WAIT(1); else CP_WAIT(0);
        __syncthreads();

        const uint32_t kvb = sKV + (uint32_t)(t & 1) * FKVST;
        const uint32_t cK = kvb, cV = kvb + FKT;

        // ---- S = Q K^T (single pass)
        float s[8][4];
#pragma unroll
        for (int f = 0; f < 8; f++)
#pragma unroll
            for (int r = 0; r < 4; r++) s[f][r] = 0.f;

#pragma unroll
        for (int ks = 0; ks < 8; ks++) {
            uint32_t qq[4];
            LDMX4(qq, sQ + a_off + ks * 32);
#pragma unroll
            for (int nb = 0; nb < 4; nb++) {
                uint32_t kk[4];
                LDMX4(kk, cK + b_off + nb * 16 * FROWB + ks * 32);
                MMA_F16(s[2 * nb],     qq, kk[0], kk[1]);
                MMA_F16(s[2 * nb + 1], qq, kk[2], kk[3]);
            }
        }

#pragma unroll
        for (int f = 0; f < 8; f++)
#pragma unroll
            for (int r = 0; r < 4; r++) s[f][r] *= SC_LOG2E;

        if (t >= ntiles - 2) {
            const int row0 = q0 + 16 * wid + (lane >> 2);
            const int colb = kt + 2 * (lane & 3);
#pragma unroll
            for (int f = 0; f < 8; f++)
#pragma unroll
                for (int r = 0; r < 4; r++) {
                    int col = colb + 8 * f + (r & 1);
                    int row = row0 + 8 * (r >> 1);
                    if (col > row) s[f][r] = -1e30f;
                }
        }

        // ---- online softmax
#pragma unroll
        for (int hh = 0; hh < 2; hh++) {
            float mt = -1e30f;
#pragma unroll
            for (int f = 0; f < 8; f++)
                mt = fmaxf(mt, fmaxf(s[f][2 * hh], s[f][2 * hh + 1]));
            mt = fmaxf(mt, __shfl_xor_sync(0xffffffffu, mt, 1));
            mt = fmaxf(mt, __shfl_xor_sync(0xffffffffu, mt, 2));
            float mn = fmaxf(mo[hh], mt);
            float alpha = exp2f(mo[hh] - mn);
            float rs = 0.f;
#pragma unroll
            for (int f = 0; f < 8; f++) {
                float p0 = exp2f(s[f][2 * hh] - mn);
                float p1 = exp2f(s[f][2 * hh + 1] - mn);
                s[f][2 * hh] = p0;
                s[f][2 * hh + 1] = p1;
                rs += p0 + p1;
            }
            rs += __shfl_xor_sync(0xffffffffu, rs, 1);
            rs += __shfl_xor_sync(0xffffffffu, rs, 2);
            ls[hh] = ls[hh] * alpha + rs;
            mo[hh] = mn;
#pragma unroll
            for (int nf = 0; nf < 16; nf++) {
                o[nf][2 * hh]     *= alpha;
                o[nf][2 * hh + 1] *= alpha;
            }
        }

        // ---- O += P V (single pass)
#pragma unroll
        for (int ks = 0; ks < 4; ks++) {
            uint32_t ph[4];
            ph[0] = pack_h2(__float2half_rn(s[2 * ks][0]),     __float2half_rn(s[2 * ks][1]));
            ph[1] = pack_h2(__float2half_rn(s[2 * ks][2]),     __float2half_rn(s[2 * ks][3]));
            ph[2] = pack_h2(__float2half_rn(s[2 * ks + 1][0]), __float2half_rn(s[2 * ks + 1][1]));
            ph[3] = pack_h2(__float2half_rn(s[2 * ks + 1][2]), __float2half_rn(s[2 * ks + 1][3]));
#pragma unroll
            for (int nb = 0; nb < 8; nb++) {
                uint32_t vv[4];
                LDMX4T(vv, cV + vt_off + ks * 16 * FROWB + nb * 32);
                MMA_F16(o[2 * nb],     ph, vv[0], vv[1]);
                MMA_F16(o[2 * nb + 1], ph, vv[2], vv[3]);
            }
        }

        __syncthreads();
        if (t + 2 < ntiles) { KV_ISSUE(kt + 128, t & 1); CP_COMMIT(); }
    }

    // epilogue: normalize, store single fp16
    float inv0 = 1.f / ls[0];
    float inv1 = 1.f / ls[1];
#pragma unroll
    for (int nf = 0; nf < 16; nf++) {
#pragma unroll
        for (int rp = 0; rp < 2; rp++) {
            float invv = rp ? inv1 : inv0;
            float v0 = o[nf][2 * rp] * invv;
            float v1 = o[nf][2 * rp + 1] * invv;
            uint32_t hv = pack_h2(__float2half_rn(v0), __float2half_rn(v1));
            int row = q0 + 16 * wid + (lane >> 2) + 8 * rp;
            int col = h * HD + 8 * nf + 2 * (lane & 3);
            size_t g = (size_t)(b * SS + row) * QDIM + col;
            *(uint32_t*)(O + g) = hv;
        }
    }
#undef KV_ISSUE
}

// ---------------------------------------------------------------------------
// launcher
// ---------------------------------------------------------------------------
extern "C" void kernel_launch(void* const* d_in, const int* in_sizes, int n_in,
                              void* d_out, int out_size)
{
    const float* hidden = (const float*)d_in[0];
    const float* Wq     = (const float*)d_in[1];
    const float* Wk     = (const float*)d_in[2];
    const float* Wv     = (const float*)d_in[3];
    const float* Wo     = (const float*)d_in[4];
    const int*   pos    = (const int*)d_in[5];
    float* out = (float*)d_out;

    __half *C16, *H16, *W16, *Wo16, *O16;
    cudaGetSymbolAddress((void**)&C16, g_C16);
    cudaGetSymbolAddress((void**)&H16, g_H16);
    cudaGetSymbolAddress((void**)&W16, g_W16);
    cudaGetSymbolAddress((void**)&Wo16, g_Wo16);
    cudaGetSymbolAddress((void**)&O16, g_O16);

    cudaFuncSetAttribute(gemm_f16h,
                         cudaFuncAttributeMaxDynamicSharedMemorySize, GEMM_SMEM);
    cudaFuncSetAttribute(gemm_f16,
                         cudaFuncAttributeMaxDynamicSharedMemorySize, GEMM_SMEM);
    cudaFuncSetAttribute(flash_tc,
                         cudaFuncAttributeMaxDynamicSharedMemorySize, FLASH_SMEM);

    // 1. one conversion kernel for everything
    conv_all<<<(CNT + 255) / 256, 256>>>(hidden, Wq, Wk, Wv, Wo, H16, W16, Wo16);

    // 2. fused QKV projection -> fp16 C16 [MTOK, 3072] (unscale by 1/64)
    gemm_f16h<<<dim3(QKVD / 128, MTOK / 128), 256, GEMM_SMEM>>>(
        H16, W16, C16, MTOK, QKVD, HID, INV_WSCALE);

    // 3. RoPE in place on C16 (Q and K regions, one launch)
    rope_all<<<(2 * MTOK * 64 + 255) / 256, 256>>>(C16, pos);

    // 4. flash attention (reads Q/K/V straight from C16) -> fp16 O
    flash_tc<<<dim3(SS / 128, NH, BB), 256, FLASH_SMEM>>>(C16, O16);

    // 5. output projection (unscale by 1/64)
    gemm_f16<<<dim3(HID / 128, MTOK / 128), 256, GEMM_SMEM>>>(
        O16, Wo16, out, MTOK, HID, QDIM, INV_WSCALE);
}

// round 12
// speedup vs baseline: 2.6679x; 1.0330x over previous
#include <cuda_runtime.h>
#include <cuda_fp16.h>
#include <math.h>
#include <stdint.h>

// Problem constants
#define BB   2
#define SS   2048
#define HID  2048
#define NH   16
#define NKV  4
#define HD   128
#define MTOK (BB*SS)          // 4096
#define QDIM (NH*HD)          // 2048
#define KVDIM (NKV*HD)        // 512
#define QKVD (QDIM + 2*KVDIM) // 3072
#define NQ   (SS/128)         // 16 q-tiles per (b)

#define WSCALE    64.0f
#define INV_WSCALE 0.015625f

// ---------------------------------------------------------------------------
// Scratch (device globals; no allocation allowed)
// ---------------------------------------------------------------------------
__device__ __half g_C16[(size_t)MTOK * QKVD];              // fused QKV fp16 (roped in place)
__device__ __half g_H16[(size_t)MTOK * HID];               // hidden fp16
__device__ __half g_W16[(size_t)QKVD * HID];               // packed QKV weights x64
__device__ __half g_Wo16[(size_t)HID * QDIM];              // Wo x64
__device__ __half g_O16[(size_t)MTOK * QDIM];              // combined attn out fp16
__device__ __half g_Op[2 * (size_t)MTOK * QDIM];           // split-KV partial O (normalized)
__device__ float2 g_ml[2 * (size_t)MTOK * NH];             // split-KV partial (m, l)

// ---------------------------------------------------------------------------
// helpers
// ---------------------------------------------------------------------------
__device__ __forceinline__ uint32_t smem_to_u32(const void* p) {
    uint32_t a;
    asm("{ .reg .u64 t; cvta.to.shared.u64 t, %1; cvt.u32.u64 %0, t; }"
        : "=r"(a) : "l"(p));
    return a;
}
__device__ __forceinline__ uint32_t pack_h2(__half a, __half b) {
    return (uint32_t)__half_as_ushort(a) | ((uint32_t)__half_as_ushort(b) << 16);
}

#define LDMX4(r, addr) \
    asm volatile("ldmatrix.sync.aligned.m8n8.x4.shared.b16 {%0,%1,%2,%3}, [%4];" \
        : "=r"((r)[0]), "=r"((r)[1]), "=r"((r)[2]), "=r"((r)[3]) : "r"(addr))
#define LDMX4T(r, addr) \
    asm volatile("ldmatrix.sync.aligned.m8n8.x4.trans.shared.b16 {%0,%1,%2,%3}, [%4];" \
        : "=r"((r)[0]), "=r"((r)[1]), "=r"((r)[2]), "=r"((r)[3]) : "r"(addr))
#define MMA_F16(c, a, b0, b1) \
    asm volatile("mma.sync.aligned.m16n8k16.row.col.f32.f16.f16.f32 " \
        "{%0,%1,%2,%3},{%4,%5,%6,%7},{%8,%9},{%0,%1,%2,%3};" \
        : "+f"((c)[0]), "+f"((c)[1]), "+f"((c)[2]), "+f"((c)[3]) \
        : "r"((a)[0]), "r"((a)[1]), "r"((a)[2]), "r"((a)[3]), "r"(b0), "r"(b1))

__device__ __forceinline__ void cp16(uint32_t dst, const void* src) {
    asm volatile("cp.async.cg.shared.global [%0], [%1], 16;" :: "r"(dst), "l"(src));
}
#define CP_COMMIT() asm volatile("cp.async.commit_group;" ::: "memory")
#define CP_WAIT(n)  asm volatile("cp.async.wait_group %0;" :: "n"(n) : "memory")

// ---------------------------------------------------------------------------
// one conversion kernel for all fp32 -> fp16 inputs (region switch)
// ---------------------------------------------------------------------------
#define CN0 (MTOK * HID / 4)     // hidden
#define CN1 (QDIM * HID / 4)     // Wq
#define CN2 (KVDIM * HID / 4)    // Wk
#define CN3 (KVDIM * HID / 4)    // Wv
#define CN4 (HID * QDIM / 4)     // Wo
#define CNT (CN0 + CN1 + CN2 + CN3 + CN4)

__global__ void conv_all(const float* __restrict__ hid, const float* __restrict__ wq,
                         const float* __restrict__ wk, const float* __restrict__ wv,
                         const float* __restrict__ wo,
                         __half* __restrict__ H16, __half* __restrict__ W16,
                         __half* __restrict__ Wo16)
{
    int i = blockIdx.x * blockDim.x + threadIdx.x;
    if (i >= CNT) return;
    const float* src;
    __half* dst;
    int j;
    float sc;
    if (i < CN0)                 { src = hid; dst = H16; j = i; sc = 1.f; }
    else if (i < CN0 + CN1)      { src = wq;  dst = W16; j = i - CN0; sc = WSCALE; }
    else if (i < CN0 + CN1 + CN2){ src = wk;  dst = W16 + (size_t)QDIM * HID;
                                   j = i - CN0 - CN1; sc = WSCALE; }
    else if (i < CN0 + CN1 + CN2 + CN3)
                                 { src = wv;  dst = W16 + (size_t)(QDIM + KVDIM) * HID;
                                   j = i - CN0 - CN1 - CN2; sc = WSCALE; }
    else                         { src = wo;  dst = Wo16;
                                   j = i - CN0 - CN1 - CN2 - CN3; sc = WSCALE; }
    float4 v = ((const float4*)src)[j];
    ((uint2*)dst)[j] = make_uint2(
        pack_h2(__float2half_rn(v.x * sc), __float2half_rn(v.y * sc)),
        pack_h2(__float2half_rn(v.z * sc), __float2half_rn(v.w * sc)));
}

// ---------------------------------------------------------------------------
// RoPE in-place on fp16 C16: Q region (16 heads) + K region (4 heads)
// ---------------------------------------------------------------------------
__global__ void rope_all(__half* __restrict__ C, const int* __restrict__ pos_ids)
{
    int idx = blockIdx.x * blockDim.x + threadIdx.x;
    if (idx >= 2 * MTOK * 64) return;
    int nheads, colbase;
    if (idx < MTOK * 64) { nheads = NH;  colbase = 0; }
    else                 { nheads = NKV; colbase = QDIM; idx -= MTOK * 64; }
    int i = idx & 63;
    int m = idx >> 6;
    int p = pos_ids[m];

    double invf = exp(-(double)i * 0.14391156831212787);  // ln(10000)/64
    double ang = (double)p * invf;
    double k = rint(ang * 0.15915494309189535);
    float r = (float)(ang - k * 6.283185307179586477);
    float sv, cv;
    sincosf(r, &sv, &cv);

    size_t base = (size_t)m * QKVD + colbase + i;
#pragma unroll 4
    for (int h = 0; h < nheads; h++) {
        float x1 = __half2float(C[base]);
        float x2 = __half2float(C[base + 64]);
        C[base]      = __float2half_rn(x1 * cv - x2 * sv);
        C[base + 64] = __float2half_rn(x2 * cv + x1 * sv);
        base += 128;
    }
}

// ---------------------------------------------------------------------------
// GEMM core (fp16-out and fp32-out variants)
// CTA 128x128, BK=32, 256 thr, 8 warps (warp 64x32). 3-stage cp.async.
// ---------------------------------------------------------------------------
#define SROW   40
#define TPART  (128 * SROW * 2)        // 10240 B
#define TSTAGE (2 * TPART)             // 20480 B
#define GEMM_SMEM (3 * TSTAGE)         // 61440 B

#define GEMM_BODY(EPILOGUE) \
    extern __shared__ char smem[]; \
    const uint32_t sbase = smem_to_u32(smem); \
    const int tid  = threadIdx.x; \
    const int wid  = tid >> 5; \
    const int lane = tid & 31; \
    const int wm   = wid >> 2; \
    const int wn   = wid & 3; \
    const int bm   = blockIdx.y * 128; \
    const int bn   = blockIdx.x * 128; \
    const int NKT  = K / 32; \
    const int cr0 = tid >> 2, cc0 = (tid & 3) * 16; \
    const int cr1 = (tid + 256) >> 2; \
    float acc[4][4][4]; \
    _Pragma("unroll") \
    for (int mf = 0; mf < 4; mf++) \
        _Pragma("unroll") \
        for (int nf = 0; nf < 4; nf++) \
            _Pragma("unroll") \
            for (int r = 0; r < 4; r++) acc[mf][nf][r] = 0.f; \
    G_ISSUE(0, 0); CP_COMMIT(); \
    G_ISSUE(1, 1); CP_COMMIT(); \
    G_ISSUE(2, 2); CP_COMMIT(); \
    const int lr16 = lane & 15; \
    const int lh   = lane >> 4; \
    const uint32_t a_lane = (uint32_t)((wm * 64 + lr16) * (SROW * 2) + lh * 16); \
    const uint32_t b_lane = (uint32_t)((wn * 32 + lr16) * (SROW * 2) + lh * 16); \
    for (int kt = 0; kt < NKT; kt++) { \
        if (kt + 3 <= NKT)       CP_WAIT(2); \
        else if (kt + 2 == NKT)  CP_WAIT(1); \
        else                     CP_WAIT(0); \
        __syncthreads(); \
        { \
            const uint32_t base = sbase + (uint32_t)(kt % 3) * TSTAGE; \
            _Pragma("unroll") \
            for (int ks = 0; ks < 2; ks++) { \
                const uint32_t kb = ks * 32; \
                uint32_t ah[4][4], bh[2][4]; \
                _Pragma("unroll") \
                for (int mf = 0; mf < 4; mf++) \
                    LDMX4(ah[mf], base + a_lane + mf * 16 * (SROW * 2) + kb); \
                _Pragma("unroll") \
                for (int nf2 = 0; nf2 < 2; nf2++) \
                    LDMX4(bh[nf2], base + TPART + b_lane + nf2 * 16 * (SROW * 2) + kb); \
                _Pragma("unroll") \
                for (int mf = 0; mf < 4; mf++) \
                    _Pragma("unroll") \
                    for (int nf = 0; nf < 4; nf++) \
                        MMA_F16(acc[mf][nf], ah[mf], \
                                bh[nf >> 1][nf & 1], bh[nf >> 1][(nf & 1) + 2]); \
            } \
        } \
        __syncthreads(); \
        if (kt + 3 < NKT) { G_ISSUE(kt + 3, kt % 3); CP_COMMIT(); } \
    } \
    const int erow = bm + wm * 64 + (lane >> 2); \
    const int ecol = bn + wn * 32 + (lane & 3) * 2; \
    EPILOGUE

#define G_ISSUE(kt, buf) do { \
    uint32_t db = sbase + (uint32_t)(buf) * TSTAGE; \
    cp16(db + cr0 * 80 + cc0, \
         A + (size_t)(bm + cr0) * K + (kt) * 32 + (cc0 >> 1)); \
    cp16(db + cr1 * 80 + cc0, \
         A + (size_t)(bm + cr1) * K + (kt) * 32 + (cc0 >> 1)); \
    cp16(db + TPART + cr0 * 80 + cc0, \
         B + (size_t)(bn + cr0) * K + (kt) * 32 + (cc0 >> 1)); \
    cp16(db + TPART + cr1 * 80 + cc0, \
         B + (size_t)(bn + cr1) * K + (kt) * 32 + (cc0 >> 1)); \
} while (0)

// fp16-output GEMM (QKV projection)
__global__ __launch_bounds__(256, 2) void gemm_f16h(
    const __half* __restrict__ A, const __half* __restrict__ B,
    __half* __restrict__ C, int M, int N, int K, float outscale)
{
    GEMM_BODY(
#pragma unroll
        for (int mf = 0; mf < 4; mf++)
#pragma unroll
            for (int nf = 0; nf < 4; nf++) {
                float* c = acc[mf][nf];
                size_t ro0 = (size_t)(erow + mf * 16) * N + ecol + nf * 8;
                size_t ro1 = ro0 + 8 * (size_t)N;
                *(uint32_t*)(C + ro0) = pack_h2(
                    __float2half_rn(c[0] * outscale), __float2half_rn(c[1] * outscale));
                *(uint32_t*)(C + ro1) = pack_h2(
                    __float2half_rn(c[2] * outscale), __float2half_rn(c[3] * outscale));
            }
    )
}

// fp32-output GEMM (output projection)
__global__ __launch_bounds__(256, 2) void gemm_f16(
    const __half* __restrict__ A, const __half* __restrict__ B,
    float* __restrict__ C, int M, int N, int K, float outscale)
{
    GEMM_BODY(
#pragma unroll
        for (int mf = 0; mf < 4; mf++)
#pragma unroll
            for (int nf = 0; nf < 4; nf++) {
                float* c = acc[mf][nf];
                size_t ro0 = (size_t)(erow + mf * 16) * N + ecol + nf * 8;
                size_t ro1 = ro0 + 8 * (size_t)N;
                *(float2*)(C + ro0) = make_float2(c[0] * outscale, c[1] * outscale);
                *(float2*)(C + ro1) = make_float2(c[2] * outscale, c[3] * outscale);
            }
    )
}
#undef G_ISSUE

// ---------------------------------------------------------------------------
// Split-KV tensor-core flash attention (partial pass).
// grid.x = NQ*2: blockIdx.x = qi*2 + half; qt reversed for LPT.
// Each partial covers half the KV tile range of its q-tile and writes
// normalized O partial (fp16) + per-row (m, l) for the combine pass.
// ---------------------------------------------------------------------------
#define FROWB 272
#define FQT   (128 * FROWB)            // 34816
#define FKT   (64 * FROWB)             // 17408
#define FKVST (2 * FKT)                // 34816 per stage
#define FLASH_SMEM (FQT + 2 * FKVST)   // 104448
#define SC_LOG2E 0.12751631762078975f  // (1/sqrt(128)) * log2(e)

__global__ __launch_bounds__(256, 2) void flash_part(
    const __half* __restrict__ C16, __half* __restrict__ Op,
    float2* __restrict__ ml)
{
    extern __shared__ char sm[];
    const uint32_t sb  = smem_to_u32(sm);
    const uint32_t sQ  = sb;
    const uint32_t sKV = sb + FQT;

    const int qi   = blockIdx.x >> 1;
    const int half = blockIdx.x & 1;
    const int qt   = NQ - 1 - qi;        // heaviest first
    const int q0   = qt * 128;
    const int h    = blockIdx.y;
    const int b    = blockIdx.z;
    const int kvh  = h >> 2;
    const int tid  = threadIdx.x;
    const int wid  = tid >> 5;
    const int lane = tid & 31;

    const int ntF = 2 * qt + 2;          // full tile count (even)
    const int t0  = half ? ntF / 2 : 0;
    const int t1  = half ? ntF : ntF / 2;

    const __half* Kp = C16 + QDIM + kvh * HD;
    const __half* Vp = C16 + QDIM + KVDIM + kvh * HD;
    __half* Oph = Op + (size_t)half * MTOK * QDIM;
    float2* mlh = ml + (size_t)half * MTOK * NH;

#define KV_ISSUE(kt, buf) do { \
    uint32_t db = sKV + (uint32_t)(buf) * FKVST; \
    size_t gb = (size_t)(b * SS + (kt)) * QKVD; \
    _Pragma("unroll") \
    for (int j = 0; j < 4; j++) { \
        int i = tid + j * 256; \
        int r = i >> 4, c16v = (i & 15) * 16; \
        size_t roff = gb + (size_t)r * QKVD + (c16v >> 1); \
        cp16(db + r * FROWB + c16v, Kp + roff); \
        cp16(db + FKT + r * FROWB + c16v, Vp + roff); \
    } \
} while (0)

    for (int i = tid; i < 128 * 16; i += 256) {
        int r = i >> 4, c = i & 15;
        size_t g = (size_t)(b * SS + q0 + r) * QKVD + h * HD + c * 8;
        *(uint4*)(sm + r * FROWB + c * 16) = *(const uint4*)(C16 + g);
    }

    KV_ISSUE(t0 * 64, t0 & 1); CP_COMMIT();
    if (t0 + 1 < t1) { KV_ISSUE((t0 + 1) * 64, (t0 + 1) & 1); CP_COMMIT(); }

    const uint32_t a_off  = (uint32_t)((16 * wid + (lane & 7) + 8 * ((lane >> 3) & 1)) * FROWB
                                       + (lane >> 4) * 16);
    const uint32_t vt_off = (uint32_t)(((lane & 7) + 8 * ((lane >> 3) & 1)) * FROWB
                                       + (lane >> 4) * 16);
    const uint32_t b_off  = (uint32_t)(((lane & 7) + 8 * (lane >> 4)) * FROWB
                                       + ((lane >> 3) & 1) * 16);

    float o[16][4];
#pragma unroll
    for (int nf = 0; nf < 16; nf++)
#pragma unroll
        for (int r = 0; r < 4; r++) o[nf][r] = 0.f;
    float mo[2] = {-1e30f, -1e30f};
    float ls[2] = {0.f, 0.f};

    for (int t = t0; t < t1; t++) {
        const int kt = t * 64;
        if (t + 1 < t1) CP_WAIT(1); else CP_WAIT(0);
        __syncthreads();

        const uint32_t kvb = sKV + (uint32_t)(t & 1) * FKVST;
        const uint32_t cK = kvb, cV = kvb + FKT;

        // ---- S = Q K^T
        float s[8][4];
#pragma unroll
        for (int f = 0; f < 8; f++)
#pragma unroll
            for (int r = 0; r < 4; r++) s[f][r] = 0.f;

#pragma unroll
        for (int ks = 0; ks < 8; ks++) {
            uint32_t qq[4];
            LDMX4(qq, sQ + a_off + ks * 32);
#pragma unroll
            for (int nb = 0; nb < 4; nb++) {
                uint32_t kk[4];
                LDMX4(kk, cK + b_off + nb * 16 * FROWB + ks * 32);
                MMA_F16(s[2 * nb],     qq, kk[0], kk[1]);
                MMA_F16(s[2 * nb + 1], qq, kk[2], kk[3]);
            }
        }

#pragma unroll
        for (int f = 0; f < 8; f++)
#pragma unroll
            for (int r = 0; r < 4; r++) s[f][r] *= SC_LOG2E;

        // causal mask on the last two tiles of the FULL range
        if (t >= ntF - 2) {
            const int row0 = q0 + 16 * wid + (lane >> 2);
            const int colb = kt + 2 * (lane & 3);
#pragma unroll
            for (int f = 0; f < 8; f++)
#pragma unroll
                for (int r = 0; r < 4; r++) {
                    int col = colb + 8 * f + (r & 1);
                    int row = row0 + 8 * (r >> 1);
                    if (col > row) s[f][r] = -1e30f;
                }
        }

        // ---- online softmax (alpha-skip when row max unchanged)
#pragma unroll
        for (int hh = 0; hh < 2; hh++) {
            float mt = -1e30f;
#pragma unroll
            for (int f = 0; f < 8; f++)
                mt = fmaxf(mt, fmaxf(s[f][2 * hh], s[f][2 * hh + 1]));
            mt = fmaxf(mt, __shfl_xor_sync(0xffffffffu, mt, 1));
            mt = fmaxf(mt, __shfl_xor_sync(0xffffffffu, mt, 2));
            float mn = fmaxf(mo[hh], mt);
            float rs = 0.f;
#pragma unroll
            for (int f = 0; f < 8; f++) {
                float p0 = exp2f(s[f][2 * hh] - mn);
                float p1 = exp2f(s[f][2 * hh + 1] - mn);
                s[f][2 * hh] = p0;
                s[f][2 * hh + 1] = p1;
                rs += p0 + p1;
            }
            rs += __shfl_xor_sync(0xffffffffu, rs, 1);
            rs += __shfl_xor_sync(0xffffffffu, rs, 2);
            if (mt > mo[hh]) {
                float alpha = exp2f(mo[hh] - mn);
                ls[hh] = ls[hh] * alpha + rs;
                mo[hh] = mn;
#pragma unroll
                for (int nf = 0; nf < 16; nf++) {
                    o[nf][2 * hh]     *= alpha;
                    o[nf][2 * hh + 1] *= alpha;
                }
            } else {
                ls[hh] += rs;
            }
        }

        // ---- O += P V
#pragma unroll
        for (int ks = 0; ks < 4; ks++) {
            uint32_t ph[4];
            ph[0] = pack_h2(__float2half_rn(s[2 * ks][0]),     __float2half_rn(s[2 * ks][1]));
            ph[1] = pack_h2(__float2half_rn(s[2 * ks][2]),     __float2half_rn(s[2 * ks][3]));
            ph[2] = pack_h2(__float2half_rn(s[2 * ks + 1][0]), __float2half_rn(s[2 * ks + 1][1]));
            ph[3] = pack_h2(__float2half_rn(s[2 * ks + 1][2]), __float2half_rn(s[2 * ks + 1][3]));
#pragma unroll
            for (int nb = 0; nb < 8; nb++) {
                uint32_t vv[4];
                LDMX4T(vv, cV + vt_off + ks * 16 * FROWB + nb * 32);
                MMA_F16(o[2 * nb],     ph, vv[0], vv[1]);
                MMA_F16(o[2 * nb + 1], ph, vv[2], vv[3]);
            }
        }

        __syncthreads();
        if (t + 2 < t1) { KV_ISSUE((t + 2) * 64, t & 1); CP_COMMIT(); }
    }

    // epilogue: normalize by this partial's l, write Op + (m, l)
    float inv0 = ls[0] > 0.f ? 1.f / ls[0] : 0.f;
    float inv1 = ls[1] > 0.f ? 1.f / ls[1] : 0.f;
#pragma unroll
    for (int nf = 0; nf < 16; nf++) {
#pragma unroll
        for (int rp = 0; rp < 2; rp++) {
            float invv = rp ? inv1 : inv0;
            float v0 = o[nf][2 * rp] * invv;
            float v1 = o[nf][2 * rp + 1] * invv;
            uint32_t hv = pack_h2(__float2half_rn(v0), __float2half_rn(v1));
            int row = q0 + 16 * wid + (lane >> 2) + 8 * rp;
            int col = h * HD + 8 * nf + 2 * (lane & 3);
            size_t g = (size_t)(b * SS + row) * QDIM + col;
            *(uint32_t*)(Oph + g) = hv;
        }
    }
    if ((lane & 3) == 0) {
#pragma unroll
        for (int rp = 0; rp < 2; rp++) {
            int row = q0 + 16 * wid + (lane >> 2) + 8 * rp;
            mlh[(size_t)(b * SS + row) * NH + h] = make_float2(mo[rp], ls[rp]);
        }
    }
#undef KV_ISSUE
}

// ---------------------------------------------------------------------------
// Split-KV combine: O = (w0*O0 + w1*O1)/(w0+w1), w_i = l_i * 2^(m_i - M)
// ---------------------------------------------------------------------------
__global__ void flash_combine(const __half* __restrict__ Op,
                              const float2* __restrict__ ml,
                              __half* __restrict__ O)
{
    int idx = blockIdx.x * blockDim.x + threadIdx.x;
    if (idx >= MTOK * NH * 16) return;
    int cg = idx & 15;          // 16 groups of 8 cols
    int rh = idx >> 4;
    int h  = rh & (NH - 1);
    int m  = rh >> 4;           // token (NH=16)

    float2 ml0 = ml[rh];
    float2 ml1 = ml[(size_t)MTOK * NH + rh];
    float M = fmaxf(ml0.x, ml1.x);
    float w0 = ml0.y * exp2f(ml0.x - M);
    float w1 = ml1.y * exp2f(ml1.x - M);
    float inv = 1.f / (w0 + w1);
    w0 *= inv; w1 *= inv;

    size_t off = ((size_t)m * QDIM + h * HD + cg * 8) >> 3;   // uint4 index
    uint4 a = ((const uint4*)Op)[off];
    uint4 bq = ((const uint4*)(Op + (size_t)MTOK * QDIM))[off];

    uint4 r;
    uint32_t* ap = (uint32_t*)&a;
    uint32_t* bp = (uint32_t*)&bq;
    uint32_t* rp = (uint32_t*)&r;
#pragma unroll
    for (int j = 0; j < 4; j++) {
        __half2 ha = *(__half2*)&ap[j];
        __half2 hb = *(__half2*)&bp[j];
        float2 fa = __half22float2(ha);
        float2 fb = __half22float2(hb);
        rp[j] = pack_h2(__float2half_rn(fa.x * w0 + fb.x * w1),
                        __float2half_rn(fa.y * w0 + fb.y * w1));
    }
    ((uint4*)O)[off] = r;
}

// ---------------------------------------------------------------------------
// launcher
// ---------------------------------------------------------------------------
extern "C" void kernel_launch(void* const* d_in, const int* in_sizes, int n_in,
                              void* d_out, int out_size)
{
    const float* hidden = (const float*)d_in[0];
    const float* Wq     = (const float*)d_in[1];
    const float* Wk     = (const float*)d_in[2];
    const float* Wv     = (const float*)d_in[3];
    const float* Wo     = (const float*)d_in[4];
    const int*   pos    = (const int*)d_in[5];
    float* out = (float*)d_out;

    __half *C16, *H16, *W16, *Wo16, *O16, *Op;
    float2* ml;
    cudaGetSymbolAddress((void**)&C16, g_C16);
    cudaGetSymbolAddress((void**)&H16, g_H16);
    cudaGetSymbolAddress((void**)&W16, g_W16);
    cudaGetSymbolAddress((void**)&Wo16, g_Wo16);
    cudaGetSymbolAddress((void**)&O16, g_O16);
    cudaGetSymbolAddress((void**)&Op, g_Op);
    cudaGetSymbolAddress((void**)&ml, g_ml);

    cudaFuncSetAttribute(gemm_f16h,
                         cudaFuncAttributeMaxDynamicSharedMemorySize, GEMM_SMEM);
    cudaFuncSetAttribute(gemm_f16,
                         cudaFuncAttributeMaxDynamicSharedMemorySize, GEMM_SMEM);
    cudaFuncSetAttribute(flash_part,
                         cudaFuncAttributeMaxDynamicSharedMemorySize, FLASH_SMEM);

    // 1. one conversion kernel for everything
    conv_all<<<(CNT + 255) / 256, 256>>>(hidden, Wq, Wk, Wv, Wo, H16, W16, Wo16);

    // 2. fused QKV projection -> fp16 C16 [MTOK, 3072] (unscale by 1/64)
    gemm_f16h<<<dim3(QKVD / 128, MTOK / 128), 256, GEMM_SMEM>>>(
        H16, W16, C16, MTOK, QKVD, HID, INV_WSCALE);

    // 3. RoPE in place on C16 (Q and K regions, one launch)
    rope_all<<<(2 * MTOK * 64 + 255) / 256, 256>>>(C16, pos);

    // 4. split-KV flash attention partials + combine
    flash_part<<<dim3(NQ * 2, NH, BB), 256, FLASH_SMEM>>>(C16, Op, ml);
    flash_combine<<<(MTOK * NH * 16 + 255) / 256, 256>>>(Op, ml, O16);

    // 5. output projection (unscale by 1/64)
    gemm_f16<<<dim3(HID / 128, MTOK / 128), 256, GEMM_SMEM>>>(
        O16, Wo16, out, MTOK, HID, QDIM, INV_WSCALE);
}